// round 1
// baseline (speedup 1.0000x reference)
#include <cuda_runtime.h>
#include <cuda_bf16.h>
#include <math_constants.h>

// Problem constants
#define BATCH 2
#define SEQ   2048
#define DMODEL 1024
#define NHEAD 16
#define DHEAD 64
#define MTOT  (BATCH*SEQ)          // 4096 rows for projection GEMMs

// ---------------------------------------------------------------------------
// Scratch (device globals; no allocation allowed)
// ---------------------------------------------------------------------------
__device__ float g_Q[BATCH*NHEAD*SEQ*DHEAD];   // [BH][S][64]
__device__ float g_K[BATCH*NHEAD*SEQ*DHEAD];
__device__ float g_V[BATCH*NHEAD*SEQ*DHEAD];
__device__ float g_AO[MTOT*DMODEL];            // [B,S,DMODEL] attention output

// ---------------------------------------------------------------------------
// SGEMM: C[M,N] = A[M,K] @ B[K,N] + bias[N]
// BM=128, BN=128, BK=8, 256 threads, 8x8 per thread, double buffered.
// MODE 0: row-major C.  MODE 1: scatter to [B,H,S,64] layout (QKV proj).
// ---------------------------------------------------------------------------
template<int MODE>
__global__ void __launch_bounds__(256)
sgemm_kernel(const float* __restrict__ A, const float* __restrict__ B,
             const float* __restrict__ bias, float* __restrict__ C,
             int M, int N, int K)
{
    __shared__ float As[2][8][128];
    __shared__ float Bs[2][8][128];

    const int bm = blockIdx.y * 128;
    const int bn = blockIdx.x * 128;
    const int tid = threadIdx.x;

    // gmem->smem mapping
    const int a_r = tid >> 1;           // 0..127
    const int a_c = (tid & 1) * 4;      // 0 or 4
    const int b_r = tid >> 5;           // 0..7
    const int b_c = (tid & 31) * 4;     // 0..124

    const float* Ap = A + (size_t)(bm + a_r) * K + a_c;
    const float* Bp = B + (size_t)b_r * N + bn + b_c;

    const int tm = (tid >> 4) * 8;
    const int tn = (tid & 15) * 8;

    float acc[8][8];
#pragma unroll
    for (int i = 0; i < 8; i++)
#pragma unroll
        for (int j = 0; j < 8; j++) acc[i][j] = 0.f;

    // prologue: tile 0
    {
        float4 av = *(const float4*)Ap;
        float4 bv = *(const float4*)Bp;
        As[0][a_c+0][a_r] = av.x;
        As[0][a_c+1][a_r] = av.y;
        As[0][a_c+2][a_r] = av.z;
        As[0][a_c+3][a_r] = av.w;
        *(float4*)&Bs[0][b_r][b_c] = bv;
    }
    __syncthreads();

    const int nt = K / 8;
    for (int t = 0; t < nt; t++) {
        const int cur = t & 1;
        const int nxt = cur ^ 1;
        float4 av2, bv2;
        const bool more = (t + 1 < nt);
        if (more) {
            av2 = *(const float4*)(Ap + (t + 1) * 8);
            bv2 = *(const float4*)(Bp + (size_t)(t + 1) * 8 * N);
        }
#pragma unroll
        for (int k = 0; k < 8; k++) {
            float4 a0 = *(const float4*)&As[cur][k][tm];
            float4 a1 = *(const float4*)&As[cur][k][tm + 4];
            float4 b0 = *(const float4*)&Bs[cur][k][tn];
            float4 b1 = *(const float4*)&Bs[cur][k][tn + 4];
            float ar[8] = {a0.x,a0.y,a0.z,a0.w,a1.x,a1.y,a1.z,a1.w};
            float br[8] = {b0.x,b0.y,b0.z,b0.w,b1.x,b1.y,b1.z,b1.w};
#pragma unroll
            for (int i = 0; i < 8; i++)
#pragma unroll
                for (int j = 0; j < 8; j++)
                    acc[i][j] = fmaf(ar[i], br[j], acc[i][j]);
        }
        if (more) {
            As[nxt][a_c+0][a_r] = av2.x;
            As[nxt][a_c+1][a_r] = av2.y;
            As[nxt][a_c+2][a_r] = av2.z;
            As[nxt][a_c+3][a_r] = av2.w;
            *(float4*)&Bs[nxt][b_r][b_c] = bv2;
            __syncthreads();
        }
    }

    // epilogue
#pragma unroll
    for (int i = 0; i < 8; i++) {
        const int m = bm + tm + i;
#pragma unroll
        for (int j4 = 0; j4 < 8; j4 += 4) {
            const int n = bn + tn + j4;
            float4 v = make_float4(acc[i][j4+0] + bias[n+0],
                                   acc[i][j4+1] + bias[n+1],
                                   acc[i][j4+2] + bias[n+2],
                                   acc[i][j4+3] + bias[n+3]);
            if (MODE == 0) {
                *(float4*)&C[(size_t)m * N + n] = v;
            } else {
                // m = b*SEQ + s ; n = h*64 + d  -> [(b*16+h)*SEQ + s]*64 + d
                const int b = m >> 11;          // SEQ = 2048
                const int s = m & 2047;
                const int h = n >> 6;
                const int d = n & 63;
                *(float4*)&C[(((size_t)b * NHEAD + h) * SEQ + s) * DHEAD + d] = v;
            }
        }
    }
}

// ---------------------------------------------------------------------------
// Flash attention, fp32. BM=BN=64, DH=64, 256 threads (16x16 grid of 4x4 tiles)
// Q/K/V in [BH][S][64]. Output written to AO[B,S,DMODEL].
// ---------------------------------------------------------------------------
#define LQ 68   // Qs row stride (float4-aligned, broadcast reads)
#define LK 65   // Ks row stride (conflict-reduced scalar reads)
#define LV 64   // Vs row stride (natural, vectorized reads)
#define LP 68   // Ps row stride

__global__ void __launch_bounds__(256)
attn_kernel(const float* __restrict__ Qg, const float* __restrict__ Kg,
            const float* __restrict__ Vg, float* __restrict__ AO)
{
    extern __shared__ float sm[];
    float* Qs = sm;                    // [64][LQ]
    float* Ks = Qs + 64 * LQ;          // [64][LK]
    float* Vs = Ks + 64 * LK;          // [64][LV]
    float* Ps = Vs + 64 * LV;          // [64][LP]

    const int bh = blockIdx.y;
    const int q0 = blockIdx.x * 64;
    const int tid = threadIdx.x;
    const int tr = tid >> 4;   // 0..15 (row group)
    const int tc = tid & 15;   // 0..15 (col group)

    const float* Qb = Qg + (size_t)bh * SEQ * DHEAD;
    const float* Kb = Kg + (size_t)bh * SEQ * DHEAD;
    const float* Vb = Vg + (size_t)bh * SEQ * DHEAD;

    const float scale = 0.125f;   // 1/sqrt(64)

    // load Q tile (scaled)
    {
        const int c4 = (tid & 15) * 4;
#pragma unroll
        for (int it = 0; it < 4; it++) {
            const int r = (tid >> 4) + it * 16;
            float4 q = *(const float4*)&Qb[(size_t)(q0 + r) * DHEAD + c4];
            Qs[r * LQ + c4 + 0] = q.x * scale;
            Qs[r * LQ + c4 + 1] = q.y * scale;
            Qs[r * LQ + c4 + 2] = q.z * scale;
            Qs[r * LQ + c4 + 3] = q.w * scale;
        }
    }

    float m_run[4], l_run[4], o_acc[4][4];
#pragma unroll
    for (int i = 0; i < 4; i++) {
        m_run[i] = -1e30f;
        l_run[i] = 0.f;
#pragma unroll
        for (int j = 0; j < 4; j++) o_acc[i][j] = 0.f;
    }

    for (int kt = 0; kt < SEQ / 64; kt++) {
        __syncthreads();   // protect Ks/Vs/Ps from previous iteration readers
        const int k0 = kt * 64;
        {
            const int c4 = (tid & 15) * 4;
#pragma unroll
            for (int it = 0; it < 4; it++) {
                const int r = (tid >> 4) + it * 16;
                float4 kv = *(const float4*)&Kb[(size_t)(k0 + r) * DHEAD + c4];
                Ks[r * LK + c4 + 0] = kv.x;
                Ks[r * LK + c4 + 1] = kv.y;
                Ks[r * LK + c4 + 2] = kv.z;
                Ks[r * LK + c4 + 3] = kv.w;
                float4 vv = *(const float4*)&Vb[(size_t)(k0 + r) * DHEAD + c4];
                *(float4*)&Vs[r * LV + c4] = vv;
            }
        }
        __syncthreads();

        // ---- scores: s = Q @ K^T (reduction over d) ----
        float s[4][4];
#pragma unroll
        for (int i = 0; i < 4; i++)
#pragma unroll
            for (int j = 0; j < 4; j++) s[i][j] = 0.f;

#pragma unroll
        for (int k4 = 0; k4 < DHEAD; k4 += 4) {
            float4 a[4];
#pragma unroll
            for (int ii = 0; ii < 4; ii++)
                a[ii] = *(const float4*)&Qs[(tr * 4 + ii) * LQ + k4];
#pragma unroll
            for (int jj = 0; jj < 4; jj++) {
                const int col = tc * 4 + jj;
                const float b0 = Ks[col * LK + k4 + 0];
                const float b1 = Ks[col * LK + k4 + 1];
                const float b2 = Ks[col * LK + k4 + 2];
                const float b3 = Ks[col * LK + k4 + 3];
#pragma unroll
                for (int ii = 0; ii < 4; ii++) {
                    s[ii][jj] = fmaf(a[ii].x, b0, s[ii][jj]);
                    s[ii][jj] = fmaf(a[ii].y, b1, s[ii][jj]);
                    s[ii][jj] = fmaf(a[ii].z, b2, s[ii][jj]);
                    s[ii][jj] = fmaf(a[ii].w, b3, s[ii][jj]);
                }
            }
        }

        // ---- online softmax (16 threads per row group share stats) ----
#pragma unroll
        for (int ii = 0; ii < 4; ii++) {
            float mx = s[ii][0];
            mx = fmaxf(mx, s[ii][1]);
            mx = fmaxf(mx, s[ii][2]);
            mx = fmaxf(mx, s[ii][3]);
#pragma unroll
            for (int off = 1; off < 16; off <<= 1)
                mx = fmaxf(mx, __shfl_xor_sync(0xffffffffu, mx, off));
            const float mnew = fmaxf(m_run[ii], mx);
            const float corr = __expf(m_run[ii] - mnew);
            float ssum = 0.f;
#pragma unroll
            for (int jj = 0; jj < 4; jj++) {
                const float p = __expf(s[ii][jj] - mnew);
                s[ii][jj] = p;
                ssum += p;
            }
#pragma unroll
            for (int off = 1; off < 16; off <<= 1)
                ssum += __shfl_xor_sync(0xffffffffu, ssum, off);
            l_run[ii] = l_run[ii] * corr + ssum;
            m_run[ii] = mnew;
#pragma unroll
            for (int jj = 0; jj < 4; jj++) o_acc[ii][jj] *= corr;
        }

        // ---- write P to smem ----
#pragma unroll
        for (int ii = 0; ii < 4; ii++)
            *(float4*)&Ps[(tr * 4 + ii) * LP + tc * 4] =
                make_float4(s[ii][0], s[ii][1], s[ii][2], s[ii][3]);
        __syncthreads();

        // ---- O += P @ V (reduction over j) ----
#pragma unroll
        for (int j4 = 0; j4 < 64; j4 += 4) {
            float4 p[4];
#pragma unroll
            for (int ii = 0; ii < 4; ii++)
                p[ii] = *(const float4*)&Ps[(tr * 4 + ii) * LP + j4];
#pragma unroll
            for (int r = 0; r < 4; r++) {
                float4 v = *(const float4*)&Vs[(j4 + r) * LV + tc * 4];
#pragma unroll
                for (int ii = 0; ii < 4; ii++) {
                    const float pv = (r == 0) ? p[ii].x : (r == 1) ? p[ii].y
                                  : (r == 2) ? p[ii].z : p[ii].w;
                    o_acc[ii][0] = fmaf(pv, v.x, o_acc[ii][0]);
                    o_acc[ii][1] = fmaf(pv, v.y, o_acc[ii][1]);
                    o_acc[ii][2] = fmaf(pv, v.z, o_acc[ii][2]);
                    o_acc[ii][3] = fmaf(pv, v.w, o_acc[ii][3]);
                }
            }
        }
    }

    // epilogue: AO[b, s, h*64 + d]
    const int b = bh >> 4;
    const int h = bh & 15;
#pragma unroll
    for (int ii = 0; ii < 4; ii++) {
        const float inv = 1.f / l_run[ii];
        const int sg = q0 + tr * 4 + ii;
        float4 o = make_float4(o_acc[ii][0] * inv, o_acc[ii][1] * inv,
                               o_acc[ii][2] * inv, o_acc[ii][3] * inv);
        *(float4*)&AO[((size_t)b * SEQ + sg) * DMODEL + h * DHEAD + tc * 4] = o;
    }
}

// ---------------------------------------------------------------------------
// Launch
// ---------------------------------------------------------------------------
extern "C" void kernel_launch(void* const* d_in, const int* in_sizes, int n_in,
                              void* d_out, int out_size)
{
    const float* query = (const float*)d_in[0];
    const float* key   = (const float*)d_in[1];
    const float* value = (const float*)d_in[2];
    const float* Wq    = (const float*)d_in[3];
    const float* bq    = (const float*)d_in[4];
    const float* Wk    = (const float*)d_in[5];
    const float* bk    = (const float*)d_in[6];
    const float* Wv    = (const float*)d_in[7];
    const float* bv    = (const float*)d_in[8];
    const float* Wo    = (const float*)d_in[9];
    const float* bo    = (const float*)d_in[10];
    float* out = (float*)d_out;

    float *gQ, *gK, *gV, *gAO;
    cudaGetSymbolAddress((void**)&gQ,  g_Q);
    cudaGetSymbolAddress((void**)&gK,  g_K);
    cudaGetSymbolAddress((void**)&gV,  g_V);
    cudaGetSymbolAddress((void**)&gAO, g_AO);

    dim3 gg(DMODEL / 128, MTOT / 128);   // (8, 32)

    sgemm_kernel<1><<<gg, 256>>>(query, Wq, bq, gQ, MTOT, DMODEL, DMODEL);
    sgemm_kernel<1><<<gg, 256>>>(key,   Wk, bk, gK, MTOT, DMODEL, DMODEL);
    sgemm_kernel<1><<<gg, 256>>>(value, Wv, bv, gV, MTOT, DMODEL, DMODEL);

    const int smem = (64 * LQ + 64 * LK + 64 * LV + 64 * LP) * (int)sizeof(float);
    static bool attr_set = false;
    // setting an attribute is idempotent and capture-safe; do it every call
    cudaFuncSetAttribute(attn_kernel, cudaFuncAttributeMaxDynamicSharedMemorySize, smem);
    (void)attr_set;
    attn_kernel<<<dim3(SEQ / 64, BATCH * NHEAD), 256, smem>>>(gQ, gK, gV, gAO);

    sgemm_kernel<0><<<gg, 256>>>(gAO, Wo, bo, out, MTOT, DMODEL, DMODEL);
}

// round 3
// speedup vs baseline: 1.4474x; 1.4474x over previous
#include <cuda_runtime.h>
#include <cuda.h>
#include <cuda_bf16.h>
#include <cstdint>

#define BATCH 2
#define SEQ   2048
#define DMODEL 1024
#define NHEAD 16
#define DHEAD 64
#define MTOT  (BATCH*SEQ)          // 4096

// ---------------------------------------------------------------------------
// Device scratch. Split buffers are [rows][2048]: hi in cols 0-1023, lo in
// 1024-2047, so one tensor map serves the 3-term compensated GEMM.
// ---------------------------------------------------------------------------
__device__ float g_Q[BATCH*NHEAD*SEQ*DHEAD];
__device__ float g_K[BATCH*NHEAD*SEQ*DHEAD];
__device__ float g_V[BATCH*NHEAD*SEQ*DHEAD];
__device__ __nv_bfloat16 g_act[3u*MTOT*2*DMODEL];    // q,k,v activations split
__device__ __nv_bfloat16 g_wt[4u*DMODEL*2*DMODEL];   // W^T split (q,k,v,o)
__device__ __nv_bfloat16 g_ao[(size_t)MTOT*2*DMODEL];// attention out split

// ---------------------------------------------------------------------------
// PTX helpers (all legal at virtual arch compute_103: no tcgen05)
// ---------------------------------------------------------------------------
__device__ __forceinline__ uint32_t smem_u32(const void* p) {
    uint32_t a;
    asm("{ .reg .u64 t; cvta.to.shared.u64 t, %1; cvt.u32.u64 %0, t; }" : "=r"(a) : "l"(p));
    return a;
}

#define MBARRIER_INIT(addr, cnt) \
    asm volatile("mbarrier.init.shared.b64 [%0], %1;" :: "r"((uint32_t)(addr)), "r"((uint32_t)(cnt)) : "memory")
#define MBARRIER_EXPECT_TX(addr, bytes) \
    asm volatile("mbarrier.arrive.expect_tx.shared.b64 _, [%0], %1;" :: "r"((uint32_t)(addr)), "r"((uint32_t)(bytes)) : "memory")

#define MBARRIER_WAIT_PARITY(mbar_smem_addr, phase_parity) do { \
    uint32_t _mbar = (uint32_t)(mbar_smem_addr); \
    uint32_t _parity = (uint32_t)(phase_parity); \
    uint32_t _done; \
    asm volatile( \
        "{\n\t.reg .pred p;\n\t" \
        "mbarrier.try_wait.parity.acquire.cta.shared::cta.b64 p, [%1], %2;\n\t" \
        "selp.b32 %0, 1, 0, p;\n\t}" \
        : "=r"(_done) : "r"(_mbar), "r"(_parity) : "memory"); \
    if (!_done) { \
        asm volatile( \
            "{\n\t.reg .pred P1;\n\t" \
            "WAIT_LOOP_%=:\n\t" \
            "mbarrier.try_wait.parity.acquire.cta.shared::cta.b64 P1, [%0], %1, 0x989680;\n\t" \
            "@P1 bra.uni WAIT_DONE_%=;\n\t" \
            "bra.uni WAIT_LOOP_%=;\n\t" \
            "WAIT_DONE_%=:\n\t}" \
            :: "r"(_mbar), "r"(_parity) : "memory"); \
    } \
} while(0)

__device__ __forceinline__ void tma2d(uint32_t dst, const CUtensorMap* m, int x, int y, uint32_t bar) {
    asm volatile(
        "cp.async.bulk.tensor.2d.shared::cta.global.tile.mbarrier::complete_tx::bytes "
        "[%0], [%1, {%2, %3}], [%4];"
        :: "r"(dst), "l"(m), "r"(x), "r"(y), "r"(bar) : "memory");
}

__device__ __forceinline__ void ldsm_x4(uint32_t& r0, uint32_t& r1, uint32_t& r2, uint32_t& r3,
                                        uint32_t addr) {
    asm volatile("ldmatrix.sync.aligned.m8n8.x4.shared.b16 {%0,%1,%2,%3}, [%4];"
                 : "=r"(r0), "=r"(r1), "=r"(r2), "=r"(r3) : "r"(addr));
}

__device__ __forceinline__ void mma16816(float* c, const uint32_t* a, uint32_t b0, uint32_t b1) {
    asm volatile(
        "mma.sync.aligned.m16n8k16.row.col.f32.bf16.bf16.f32 "
        "{%0,%1,%2,%3}, {%4,%5,%6,%7}, {%8,%9}, {%0,%1,%2,%3};"
        : "+f"(c[0]), "+f"(c[1]), "+f"(c[2]), "+f"(c[3])
        : "r"(a[0]), "r"(a[1]), "r"(a[2]), "r"(a[3]), "r"(b0), "r"(b1));
}

__device__ __forceinline__ void split_bf16(float x, __nv_bfloat16& h, __nv_bfloat16& l) {
    h = __float2bfloat16(x);
    l = __float2bfloat16(x - __bfloat162float(h));
}

// ---------------------------------------------------------------------------
// fp32 [rows][1024] -> split bf16 [rows][2048] (hi | lo)
// ---------------------------------------------------------------------------
__global__ void __launch_bounds__(256)
split_rows_kernel(const float* __restrict__ x, __nv_bfloat16* __restrict__ dst)
{
    const int idx = blockIdx.x * 256 + threadIdx.x;
    const int m = idx >> 8;
    const int k4 = (idx & 255) * 4;
    float4 v = *(const float4*)&x[(size_t)m * DMODEL + k4];
    __nv_bfloat16 h0,h1,h2,h3,l0,l1,l2,l3;
    split_bf16(v.x,h0,l0); split_bf16(v.y,h1,l1);
    split_bf16(v.z,h2,l2); split_bf16(v.w,h3,l3);
    __nv_bfloat16* hi = dst + (size_t)m * 2 * DMODEL + k4;
    __nv_bfloat16* lo = hi + DMODEL;
    *(__nv_bfloat162*)(hi)     = __halves2bfloat162(h0,h1);
    *(__nv_bfloat162*)(hi + 2) = __halves2bfloat162(h2,h3);
    *(__nv_bfloat162*)(lo)     = __halves2bfloat162(l0,l1);
    *(__nv_bfloat162*)(lo + 2) = __halves2bfloat162(l2,l3);
}

// ---------------------------------------------------------------------------
// W[K=1024][N=1024] -> T[N][2048] = (W^T hi | W^T lo)
// ---------------------------------------------------------------------------
__global__ void __launch_bounds__(256)
wt_split_kernel(const float* __restrict__ W, __nv_bfloat16* __restrict__ T)
{
    __shared__ float t[32][33];
    const int n0 = blockIdx.x * 32, k0 = blockIdx.y * 32;
    const int tx = threadIdx.x, ty = threadIdx.y;   // (32, 8)
#pragma unroll
    for (int i = 0; i < 4; i++)
        t[ty + 8*i][tx] = W[(size_t)(k0 + ty + 8*i) * DMODEL + n0 + tx];
    __syncthreads();
#pragma unroll
    for (int i = 0; i < 4; i++) {
        const int n = n0 + ty + 8*i;
        const int k = k0 + tx;
        float v = t[tx][ty + 8*i];
        __nv_bfloat16 h, l; split_bf16(v, h, l);
        T[(size_t)n * 2 * DMODEL + k] = h;
        T[(size_t)n * 2 * DMODEL + DMODEL + k] = l;
    }
}

// ---------------------------------------------------------------------------
// HMMA GEMM with 3-term compensated bf16 split folded into one K'=3072 loop.
// C[M=4096, N=1024] = A'[M, 3072] @ B'[N, 3072]^T + bias
// BM=128, BN=128, BK=64, 3-stage TMA pipeline, 256 threads (8 warps, 32x64).
// MODE 0: row-major fp32 C.  MODE 1: scatter to [B,H,S,64] fp32.
// ---------------------------------------------------------------------------
#define BK       64
#define NCHUNK   48                 // 3 segments x (1024/64)
#define STAGES   3
#define TILEA_SZ 16384              // 128 rows x 128 B
#define TILEB_SZ 16384
#define STAGE_SZ (TILEA_SZ + TILEB_SZ)
#define GSMEM    (1024 + STAGES * STAGE_SZ)

template<int MODE>
__global__ void __launch_bounds__(256, 2)
gemm_mma(const __grid_constant__ CUtensorMap tmA,
         const __grid_constant__ CUtensorMap tmB,
         const float* __restrict__ bias, float* __restrict__ C)
{
    extern __shared__ char sm_raw[];
    const uint32_t sb = smem_u32(sm_raw);
    const uint32_t tiles = (sb + 1024) & ~1023u;        // 1024-aligned (SW128)
    const int tid = threadIdx.x;
    const int lane = tid & 31, wid = tid >> 5;
    const int wm = wid & 3, wn = wid >> 2;              // 4 x 2 warp grid

    const uint32_t FULL = sb;                           // 3 mbarriers, 8B each

    if (tid == 0) {
#pragma unroll
        for (int s = 0; s < STAGES; s++) MBARRIER_INIT(FULL + 8*s, 1);
    }
    __syncthreads();

    const int bm = blockIdx.y * 128;
    const int bn = blockIdx.x * 128;

    // chunk -> TMA x-coords (element units). seg0: Ah*Bh, seg1: Ah*Bl, seg2: Al*Bh
    auto coords = [](int c, int& ax, int& bx) {
        const int seg = c >> 4;
        const int kk = (c & 15) * BK;
        ax = (seg == 2) ? DMODEL + kk : kk;
        bx = (seg == 1) ? DMODEL + kk : kk;
    };

    if (tid == 0) {
#pragma unroll
        for (int s = 0; s < STAGES; s++) {
            int ax, bx; coords(s, ax, bx);
            MBARRIER_EXPECT_TX(FULL + 8*s, STAGE_SZ);
            tma2d(tiles + s*STAGE_SZ,            &tmA, ax, bm, FULL + 8*s);
            tma2d(tiles + s*STAGE_SZ + TILEA_SZ, &tmB, bx, bn, FULL + 8*s);
        }
    }

    float acc[2][8][4];
#pragma unroll
    for (int i = 0; i < 2; i++)
#pragma unroll
        for (int j = 0; j < 8; j++)
#pragma unroll
            for (int q = 0; q < 4; q++) acc[i][j][q] = 0.f;

    // per-thread ldmatrix row components (swizzle uses lane&7 since all row
    // offsets are multiples of 8)
    const int lrow = lane & 15;
    const int lcolhalf = lane >> 4;          // 0/1: which 16B col within pair
    const int sw = lane & 7;

    for (int c = 0; c < NCHUNK; c++) {
        const int s = c % STAGES;
        const int ph = (c / STAGES) & 1;
        MBARRIER_WAIT_PARITY(FULL + 8*s, ph);

        const uint32_t As = tiles + s*STAGE_SZ;
        const uint32_t Bs = As + TILEA_SZ;

#pragma unroll
        for (int kk = 0; kk < 4; kk++) {
            const int cidx = 2*kk + lcolhalf;
            const uint32_t coff = (uint32_t)((cidx ^ sw) << 4);

            uint32_t a[2][4];
#pragma unroll
            for (int mi = 0; mi < 2; mi++) {
                const int r = wm*32 + mi*16 + lrow;
                ldsm_x4(a[mi][0], a[mi][1], a[mi][2], a[mi][3],
                        As + (uint32_t)r*128 + coff);
            }
            uint32_t b[4][4];
#pragma unroll
            for (int ni = 0; ni < 4; ni++) {
                const int r = wn*64 + ni*16 + lrow;
                ldsm_x4(b[ni][0], b[ni][1], b[ni][2], b[ni][3],
                        Bs + (uint32_t)r*128 + coff);
            }
#pragma unroll
            for (int mi = 0; mi < 2; mi++)
#pragma unroll
                for (int ni = 0; ni < 4; ni++) {
                    mma16816(acc[mi][2*ni+0], a[mi], b[ni][0], b[ni][2]);
                    mma16816(acc[mi][2*ni+1], a[mi], b[ni][1], b[ni][3]);
                }
        }
        __syncthreads();
        if (tid == 0 && c + STAGES < NCHUNK) {
            int ax, bx; coords(c + STAGES, ax, bx);
            MBARRIER_EXPECT_TX(FULL + 8*s, STAGE_SZ);
            tma2d(As, &tmA, ax, bm, FULL + 8*s);
            tma2d(Bs, &tmB, bx, bn, FULL + 8*s);
        }
    }

    // epilogue: c-frag (m16n8): rows t/4, t/4+8; cols (t%4)*2, +1
    const int grp = lane >> 2;
    const int qd  = lane & 3;
#pragma unroll
    for (int mi = 0; mi < 2; mi++) {
#pragma unroll
        for (int nj = 0; nj < 8; nj++) {
            const int col = bn + wn*64 + nj*8 + qd*2;
            const float b0 = __ldg(&bias[col]);
            const float b1 = __ldg(&bias[col + 1]);
#pragma unroll
            for (int half = 0; half < 2; half++) {
                const int m = bm + wm*32 + mi*16 + grp + half*8;
                float2 v = make_float2(acc[mi][nj][2*half+0] + b0,
                                       acc[mi][nj][2*half+1] + b1);
                if (MODE == 0) {
                    *(float2*)&C[(size_t)m * DMODEL + col] = v;
                } else {
                    const int b = m >> 11, srow = m & 2047;
                    const int h = col >> 6, d = col & 63;
                    *(float2*)&C[(((size_t)b * NHEAD + h) * SEQ + srow) * DHEAD + d] = v;
                }
            }
        }
    }
}

// ---------------------------------------------------------------------------
// Flash attention fp32 (same core as R1); epilogue writes split AO [m][2048].
// ---------------------------------------------------------------------------
#define LQ 68
#define LK 65
#define LV 64
#define LP 68

__global__ void __launch_bounds__(256)
attn_kernel(const float* __restrict__ Qg, const float* __restrict__ Kg,
            const float* __restrict__ Vg, __nv_bfloat16* __restrict__ AO)
{
    extern __shared__ float smf[];
    float* Qs = smf;
    float* Ks = Qs + 64 * LQ;
    float* Vs = Ks + 64 * LK;
    float* Ps = Vs + 64 * LV;

    const int bh = blockIdx.y;
    const int q0 = blockIdx.x * 64;
    const int tid = threadIdx.x;
    const int tr = tid >> 4;
    const int tc = tid & 15;

    const float* Qb = Qg + (size_t)bh * SEQ * DHEAD;
    const float* Kb = Kg + (size_t)bh * SEQ * DHEAD;
    const float* Vb = Vg + (size_t)bh * SEQ * DHEAD;

    const float scale = 0.125f;
    {
        const int c4 = (tid & 15) * 4;
#pragma unroll
        for (int it = 0; it < 4; it++) {
            const int r = (tid >> 4) + it * 16;
            float4 q = *(const float4*)&Qb[(size_t)(q0 + r) * DHEAD + c4];
            Qs[r * LQ + c4 + 0] = q.x * scale;
            Qs[r * LQ + c4 + 1] = q.y * scale;
            Qs[r * LQ + c4 + 2] = q.z * scale;
            Qs[r * LQ + c4 + 3] = q.w * scale;
        }
    }

    float m_run[4], l_run[4], o_acc[4][4];
#pragma unroll
    for (int i = 0; i < 4; i++) {
        m_run[i] = -1e30f; l_run[i] = 0.f;
#pragma unroll
        for (int j = 0; j < 4; j++) o_acc[i][j] = 0.f;
    }

    for (int kt = 0; kt < SEQ / 64; kt++) {
        __syncthreads();
        const int k0 = kt * 64;
        {
            const int c4 = (tid & 15) * 4;
#pragma unroll
            for (int it = 0; it < 4; it++) {
                const int r = (tid >> 4) + it * 16;
                float4 kv = *(const float4*)&Kb[(size_t)(k0 + r) * DHEAD + c4];
                Ks[r * LK + c4 + 0] = kv.x;
                Ks[r * LK + c4 + 1] = kv.y;
                Ks[r * LK + c4 + 2] = kv.z;
                Ks[r * LK + c4 + 3] = kv.w;
                float4 vv = *(const float4*)&Vb[(size_t)(k0 + r) * DHEAD + c4];
                *(float4*)&Vs[r * LV + c4] = vv;
            }
        }
        __syncthreads();

        float s[4][4];
#pragma unroll
        for (int i = 0; i < 4; i++)
#pragma unroll
            for (int j = 0; j < 4; j++) s[i][j] = 0.f;

#pragma unroll
        for (int k4 = 0; k4 < DHEAD; k4 += 4) {
            float4 a[4];
#pragma unroll
            for (int ii = 0; ii < 4; ii++)
                a[ii] = *(const float4*)&Qs[(tr * 4 + ii) * LQ + k4];
#pragma unroll
            for (int jj = 0; jj < 4; jj++) {
                const int col = tc * 4 + jj;
                const float b0 = Ks[col * LK + k4 + 0];
                const float b1 = Ks[col * LK + k4 + 1];
                const float b2 = Ks[col * LK + k4 + 2];
                const float b3 = Ks[col * LK + k4 + 3];
#pragma unroll
                for (int ii = 0; ii < 4; ii++) {
                    s[ii][jj] = fmaf(a[ii].x, b0, s[ii][jj]);
                    s[ii][jj] = fmaf(a[ii].y, b1, s[ii][jj]);
                    s[ii][jj] = fmaf(a[ii].z, b2, s[ii][jj]);
                    s[ii][jj] = fmaf(a[ii].w, b3, s[ii][jj]);
                }
            }
        }

#pragma unroll
        for (int ii = 0; ii < 4; ii++) {
            float mx = fmaxf(fmaxf(s[ii][0], s[ii][1]), fmaxf(s[ii][2], s[ii][3]));
#pragma unroll
            for (int off = 1; off < 16; off <<= 1)
                mx = fmaxf(mx, __shfl_xor_sync(0xffffffffu, mx, off));
            const float mnew = fmaxf(m_run[ii], mx);
            const float corr = __expf(m_run[ii] - mnew);
            float ssum = 0.f;
#pragma unroll
            for (int jj = 0; jj < 4; jj++) {
                const float p = __expf(s[ii][jj] - mnew);
                s[ii][jj] = p; ssum += p;
            }
#pragma unroll
            for (int off = 1; off < 16; off <<= 1)
                ssum += __shfl_xor_sync(0xffffffffu, ssum, off);
            l_run[ii] = l_run[ii] * corr + ssum;
            m_run[ii] = mnew;
#pragma unroll
            for (int jj = 0; jj < 4; jj++) o_acc[ii][jj] *= corr;
        }

#pragma unroll
        for (int ii = 0; ii < 4; ii++)
            *(float4*)&Ps[(tr * 4 + ii) * LP + tc * 4] =
                make_float4(s[ii][0], s[ii][1], s[ii][2], s[ii][3]);
        __syncthreads();

#pragma unroll
        for (int j4 = 0; j4 < 64; j4 += 4) {
            float4 p[4];
#pragma unroll
            for (int ii = 0; ii < 4; ii++)
                p[ii] = *(const float4*)&Ps[(tr * 4 + ii) * LP + j4];
#pragma unroll
            for (int r = 0; r < 4; r++) {
                float4 v = *(const float4*)&Vs[(j4 + r) * LV + tc * 4];
#pragma unroll
                for (int ii = 0; ii < 4; ii++) {
                    const float pv = (r == 0) ? p[ii].x : (r == 1) ? p[ii].y
                                  : (r == 2) ? p[ii].z : p[ii].w;
                    o_acc[ii][0] = fmaf(pv, v.x, o_acc[ii][0]);
                    o_acc[ii][1] = fmaf(pv, v.y, o_acc[ii][1]);
                    o_acc[ii][2] = fmaf(pv, v.z, o_acc[ii][2]);
                    o_acc[ii][3] = fmaf(pv, v.w, o_acc[ii][3]);
                }
            }
        }
    }

    const int b = bh >> 4;
    const int h = bh & 15;
#pragma unroll
    for (int ii = 0; ii < 4; ii++) {
        const float inv = 1.f / l_run[ii];
        const int sg = q0 + tr * 4 + ii;
        float4 o = make_float4(o_acc[ii][0] * inv, o_acc[ii][1] * inv,
                               o_acc[ii][2] * inv, o_acc[ii][3] * inv);
        __nv_bfloat16 h0,h1,h2,h3,l0,l1,l2,l3;
        split_bf16(o.x,h0,l0); split_bf16(o.y,h1,l1);
        split_bf16(o.z,h2,l2); split_bf16(o.w,h3,l3);
        __nv_bfloat16* hi = AO + ((size_t)b * SEQ + sg) * 2 * DMODEL + h * DHEAD + tc * 4;
        __nv_bfloat16* lo = hi + DMODEL;
        *(__nv_bfloat162*)(hi)     = __halves2bfloat162(h0,h1);
        *(__nv_bfloat162*)(hi + 2) = __halves2bfloat162(h2,h3);
        *(__nv_bfloat162*)(lo)     = __halves2bfloat162(l0,l1);
        *(__nv_bfloat162*)(lo + 2) = __halves2bfloat162(l2,l3);
    }
}

// ---------------------------------------------------------------------------
// Host
// ---------------------------------------------------------------------------
typedef CUresult (*PFN_tmEncode)(CUtensorMap*, CUtensorMapDataType, cuuint32_t, void*,
                                 const cuuint64_t*, const cuuint64_t*, const cuuint32_t*,
                                 const cuuint32_t*, CUtensorMapInterleave, CUtensorMapSwizzle,
                                 CUtensorMapL2promotion, CUtensorMapFloatOOBfill);

static void make_map(PFN_tmEncode enc, CUtensorMap* m, void* p, uint64_t rows)
{
    cuuint64_t dims[2]    = { 2 * DMODEL, rows };
    cuuint64_t strides[1] = { 2 * DMODEL * 2 };   // row bytes (bf16)
    cuuint32_t box[2]     = { BK, 128 };
    cuuint32_t es[2]      = { 1, 1 };
    enc(m, CU_TENSOR_MAP_DATA_TYPE_BFLOAT16, 2, p, dims, strides, box, es,
        CU_TENSOR_MAP_INTERLEAVE_NONE, CU_TENSOR_MAP_SWIZZLE_128B,
        CU_TENSOR_MAP_L2_PROMOTION_L2_128B, CU_TENSOR_MAP_FLOAT_OOB_FILL_NONE);
}

extern "C" void kernel_launch(void* const* d_in, const int* in_sizes, int n_in,
                              void* d_out, int out_size)
{
    const float* act[3] = { (const float*)d_in[0], (const float*)d_in[1], (const float*)d_in[2] };
    const float* W[4]   = { (const float*)d_in[3], (const float*)d_in[5], (const float*)d_in[7], (const float*)d_in[9] };
    const float* bia[4] = { (const float*)d_in[4], (const float*)d_in[6], (const float*)d_in[8], (const float*)d_in[10] };
    float* out = (float*)d_out;

    float *gQ, *gK, *gV;
    __nv_bfloat16 *pact, *pwt, *pao;
    cudaGetSymbolAddress((void**)&gQ,  g_Q);
    cudaGetSymbolAddress((void**)&gK,  g_K);
    cudaGetSymbolAddress((void**)&gV,  g_V);
    cudaGetSymbolAddress((void**)&pact, g_act);
    cudaGetSymbolAddress((void**)&pwt,  g_wt);
    cudaGetSymbolAddress((void**)&pao,  g_ao);

    PFN_tmEncode enc = nullptr;
    cudaDriverEntryPointQueryResult qr;
    cudaGetDriverEntryPointByVersion("cuTensorMapEncodeTiled", (void**)&enc, 12000,
                                     cudaEnableDefault, &qr);

    const size_t AM2 = (size_t)MTOT * 2 * DMODEL;
    const size_t WM2 = (size_t)DMODEL * 2 * DMODEL;

    static CUtensorMap mA[4], mB[4];
    for (int i = 0; i < 3; i++) make_map(enc, &mA[i], pact + i * AM2, MTOT);
    make_map(enc, &mA[3], pao, MTOT);
    for (int i = 0; i < 4; i++) make_map(enc, &mB[i], pwt + i * WM2, DMODEL);

    cudaFuncSetAttribute(gemm_mma<0>, cudaFuncAttributeMaxDynamicSharedMemorySize, GSMEM);
    cudaFuncSetAttribute(gemm_mma<1>, cudaFuncAttributeMaxDynamicSharedMemorySize, GSMEM);
    const int attn_smem = (64 * LQ + 64 * LK + 64 * LV + 64 * LP) * (int)sizeof(float);
    cudaFuncSetAttribute(attn_kernel, cudaFuncAttributeMaxDynamicSharedMemorySize, attn_smem);

    // 1. split activations into [m][2048] (hi|lo)
    for (int i = 0; i < 3; i++)
        split_rows_kernel<<<MTOT, 256>>>(act[i], pact + i * AM2);

    // 2. transpose + split weights into [n][2048]
    for (int i = 0; i < 4; i++)
        wt_split_kernel<<<dim3(32, 32), dim3(32, 8)>>>(W[i], pwt + i * WM2);

    // 3. QKV projections (scatter to [B,H,S,64])
    dim3 gg(DMODEL / 128, MTOT / 128);   // (8, 32) = 256 CTAs (one wave @ occ 2)
    float* qkv[3] = { gQ, gK, gV };
    for (int i = 0; i < 3; i++)
        gemm_mma<1><<<gg, 256, GSMEM>>>(mA[i], mB[i], bia[i], qkv[i]);

    // 4. attention (fp32 core), writes split AO
    attn_kernel<<<dim3(SEQ / 64, BATCH * NHEAD), 256, attn_smem>>>(gQ, gK, gV, pao);

    // 5. output projection
    gemm_mma<0><<<gg, 256, GSMEM>>>(mA[3], mB[3], bia[3], out);
}

// round 5
// speedup vs baseline: 2.8672x; 1.9809x over previous
#include <cuda_runtime.h>
#include <cuda.h>
#include <cuda_bf16.h>
#include <cstdint>

#define BATCH 2
#define SEQ   2048
#define DMODEL 1024
#define NHEAD 16
#define DHEAD 64
#define MTOT  (BATCH*SEQ)          // 4096
#define BHTOT (BATCH*NHEAD)        // 32
#define QKVPART ((size_t)BHTOT*SEQ*DHEAD)   // 4.19M elems per split buffer

// ---------------------------------------------------------------------------
// Device scratch
// ---------------------------------------------------------------------------
__device__ __nv_bfloat16 g_act[3u*MTOT*2*DMODEL];    // q,k,v activations split (hi|lo)
__device__ __nv_bfloat16 g_wt[4u*DMODEL*2*DMODEL];   // W^T split (q,k,v,o)
__device__ __nv_bfloat16 g_ao[(size_t)MTOT*2*DMODEL];// attention out split (hi|lo)
__device__ __nv_bfloat16 g_qkvs[6*QKVPART];          // Qh,Ql,Kh,Kl,Vh,Vl [BH][S][64]

// ---------------------------------------------------------------------------
// PTX helpers (legal at virtual arch compute_103: no tcgen05)
// ---------------------------------------------------------------------------
__device__ __forceinline__ uint32_t smem_u32(const void* p) {
    uint32_t a;
    asm("{ .reg .u64 t; cvta.to.shared.u64 t, %1; cvt.u32.u64 %0, t; }" : "=r"(a) : "l"(p));
    return a;
}

#define MBARRIER_INIT(addr, cnt) \
    asm volatile("mbarrier.init.shared.b64 [%0], %1;" :: "r"((uint32_t)(addr)), "r"((uint32_t)(cnt)) : "memory")
#define MBARRIER_EXPECT_TX(addr, bytes) \
    asm volatile("mbarrier.arrive.expect_tx.shared.b64 _, [%0], %1;" :: "r"((uint32_t)(addr)), "r"((uint32_t)(bytes)) : "memory")

#define MBARRIER_WAIT_PARITY(mbar_smem_addr, phase_parity) do { \
    uint32_t _mbar = (uint32_t)(mbar_smem_addr); \
    uint32_t _parity = (uint32_t)(phase_parity); \
    uint32_t _done; \
    asm volatile( \
        "{\n\t.reg .pred p;\n\t" \
        "mbarrier.try_wait.parity.acquire.cta.shared::cta.b64 p, [%1], %2;\n\t" \
        "selp.b32 %0, 1, 0, p;\n\t}" \
        : "=r"(_done) : "r"(_mbar), "r"(_parity) : "memory"); \
    if (!_done) { \
        asm volatile( \
            "{\n\t.reg .pred P1;\n\t" \
            "WAIT_LOOP_%=:\n\t" \
            "mbarrier.try_wait.parity.acquire.cta.shared::cta.b64 P1, [%0], %1, 0x989680;\n\t" \
            "@P1 bra.uni WAIT_DONE_%=;\n\t" \
            "bra.uni WAIT_LOOP_%=;\n\t" \
            "WAIT_DONE_%=:\n\t}" \
            :: "r"(_mbar), "r"(_parity) : "memory"); \
    } \
} while(0)

__device__ __forceinline__ void tma2d(uint32_t dst, const CUtensorMap* m, int x, int y, uint32_t bar) {
    asm volatile(
        "cp.async.bulk.tensor.2d.shared::cta.global.tile.mbarrier::complete_tx::bytes "
        "[%0], [%1, {%2, %3}], [%4];"
        :: "r"(dst), "l"(m), "r"(x), "r"(y), "r"(bar) : "memory");
}

__device__ __forceinline__ void ldsm_x4(uint32_t& r0, uint32_t& r1, uint32_t& r2, uint32_t& r3,
                                        uint32_t addr) {
    asm volatile("ldmatrix.sync.aligned.m8n8.x4.shared.b16 {%0,%1,%2,%3}, [%4];"
                 : "=r"(r0), "=r"(r1), "=r"(r2), "=r"(r3) : "r"(addr));
}
__device__ __forceinline__ void ldsm_x4_t(uint32_t& r0, uint32_t& r1, uint32_t& r2, uint32_t& r3,
                                          uint32_t addr) {
    asm volatile("ldmatrix.sync.aligned.m8n8.x4.trans.shared.b16 {%0,%1,%2,%3}, [%4];"
                 : "=r"(r0), "=r"(r1), "=r"(r2), "=r"(r3) : "r"(addr));
}

__device__ __forceinline__ void mma16816(float* c, const uint32_t* a, uint32_t b0, uint32_t b1) {
    asm volatile(
        "mma.sync.aligned.m16n8k16.row.col.f32.bf16.bf16.f32 "
        "{%0,%1,%2,%3}, {%4,%5,%6,%7}, {%8,%9}, {%0,%1,%2,%3};"
        : "+f"(c[0]), "+f"(c[1]), "+f"(c[2]), "+f"(c[3])
        : "r"(a[0]), "r"(a[1]), "r"(a[2]), "r"(a[3]), "r"(b0), "r"(b1));
}

__device__ __forceinline__ void split_bf16(float x, __nv_bfloat16& h, __nv_bfloat16& l) {
    h = __float2bfloat16(x);
    l = __float2bfloat16(x - __bfloat162float(h));
}

// pack two floats into a bf16x2 register pair (hi/lo split), as uint32
__device__ __forceinline__ void split_pack2(float x0, float x1, uint32_t& hp, uint32_t& lp) {
    __nv_bfloat16 h0,l0,h1,l1;
    split_bf16(x0,h0,l0); split_bf16(x1,h1,l1);
    hp = (uint32_t)__bfloat16_as_ushort(h0) | ((uint32_t)__bfloat16_as_ushort(h1) << 16);
    lp = (uint32_t)__bfloat16_as_ushort(l0) | ((uint32_t)__bfloat16_as_ushort(l1) << 16);
}

// smem address for 16B unit `u` of row `r` in a SW128 tile (128B rows)
__device__ __forceinline__ uint32_t ldsm_addr(uint32_t base, int r, int u) {
    return base + (uint32_t)r * 128u + (uint32_t)((u ^ (r & 7)) << 4);
}

// ---------------------------------------------------------------------------
// fp32 [rows][1024] -> split bf16 [rows][2048] (hi | lo)
// ---------------------------------------------------------------------------
__global__ void __launch_bounds__(256)
split_rows_kernel(const float* __restrict__ x, __nv_bfloat16* __restrict__ dst)
{
    const int idx = blockIdx.x * 256 + threadIdx.x;
    const int m = idx >> 8;
    const int k4 = (idx & 255) * 4;
    float4 v = *(const float4*)&x[(size_t)m * DMODEL + k4];
    __nv_bfloat16 h0,h1,h2,h3,l0,l1,l2,l3;
    split_bf16(v.x,h0,l0); split_bf16(v.y,h1,l1);
    split_bf16(v.z,h2,l2); split_bf16(v.w,h3,l3);
    __nv_bfloat16* hi = dst + (size_t)m * 2 * DMODEL + k4;
    __nv_bfloat16* lo = hi + DMODEL;
    *(__nv_bfloat162*)(hi)     = __halves2bfloat162(h0,h1);
    *(__nv_bfloat162*)(hi + 2) = __halves2bfloat162(h2,h3);
    *(__nv_bfloat162*)(lo)     = __halves2bfloat162(l0,l1);
    *(__nv_bfloat162*)(lo + 2) = __halves2bfloat162(l2,l3);
}

// ---------------------------------------------------------------------------
// W[K=1024][N=1024] -> T[N][2048] = (W^T hi | W^T lo)
// ---------------------------------------------------------------------------
__global__ void __launch_bounds__(256)
wt_split_kernel(const float* __restrict__ W, __nv_bfloat16* __restrict__ T)
{
    __shared__ float t[32][33];
    const int n0 = blockIdx.x * 32, k0 = blockIdx.y * 32;
    const int tx = threadIdx.x, ty = threadIdx.y;   // (32, 8)
#pragma unroll
    for (int i = 0; i < 4; i++)
        t[ty + 8*i][tx] = W[(size_t)(k0 + ty + 8*i) * DMODEL + n0 + tx];
    __syncthreads();
#pragma unroll
    for (int i = 0; i < 4; i++) {
        const int n = n0 + ty + 8*i;
        const int k = k0 + tx;
        float v = t[tx][ty + 8*i];
        __nv_bfloat16 h, l; split_bf16(v, h, l);
        T[(size_t)n * 2 * DMODEL + k] = h;
        T[(size_t)n * 2 * DMODEL + DMODEL + k] = l;
    }
}

// ---------------------------------------------------------------------------
// HMMA GEMM, 3-term compensated split folded into one K'=3072 loop.
// MODE 0: row-major fp32 C.  MODE 1: split bf16 scatter to [BH][S][64] hi/lo.
// ---------------------------------------------------------------------------
#define BK       64
#define NCHUNK   48
#define STAGES   3
#define TILEA_SZ 16384
#define TILEB_SZ 16384
#define STAGE_SZ (TILEA_SZ + TILEB_SZ)
#define GSMEM    (1024 + STAGES * STAGE_SZ)

template<int MODE>
__global__ void __launch_bounds__(256, 2)
gemm_mma(const __grid_constant__ CUtensorMap tmA,
         const __grid_constant__ CUtensorMap tmB,
         const float* __restrict__ bias, float* __restrict__ C,
         __nv_bfloat16* __restrict__ Oh, __nv_bfloat16* __restrict__ Ol,
         float scale)
{
    extern __shared__ char sm_raw[];
    const uint32_t sb = smem_u32(sm_raw);
    const uint32_t tiles = (sb + 1024) & ~1023u;
    const int tid = threadIdx.x;
    const int lane = tid & 31, wid = tid >> 5;
    const int wm = wid & 3, wn = wid >> 2;

    const uint32_t FULL = sb;

    if (tid == 0) {
#pragma unroll
        for (int s = 0; s < STAGES; s++) MBARRIER_INIT(FULL + 8*s, 1);
    }
    __syncthreads();

    const int bm = blockIdx.y * 128;
    const int bn = blockIdx.x * 128;

    auto coords = [](int c, int& ax, int& bx) {
        const int seg = c >> 4;
        const int kk = (c & 15) * BK;
        ax = (seg == 2) ? DMODEL + kk : kk;
        bx = (seg == 1) ? DMODEL + kk : kk;
    };

    if (tid == 0) {
#pragma unroll
        for (int s = 0; s < STAGES; s++) {
            int ax, bx; coords(s, ax, bx);
            MBARRIER_EXPECT_TX(FULL + 8*s, STAGE_SZ);
            tma2d(tiles + s*STAGE_SZ,            &tmA, ax, bm, FULL + 8*s);
            tma2d(tiles + s*STAGE_SZ + TILEA_SZ, &tmB, bx, bn, FULL + 8*s);
        }
    }

    float acc[2][8][4];
#pragma unroll
    for (int i = 0; i < 2; i++)
#pragma unroll
        for (int j = 0; j < 8; j++)
#pragma unroll
            for (int q = 0; q < 4; q++) acc[i][j][q] = 0.f;

    const int lrow = lane & 15;
    const int lcolhalf = lane >> 4;
    const int sw = lane & 7;

    for (int c = 0; c < NCHUNK; c++) {
        const int s = c % STAGES;
        const int ph = (c / STAGES) & 1;
        MBARRIER_WAIT_PARITY(FULL + 8*s, ph);

        const uint32_t As = tiles + s*STAGE_SZ;
        const uint32_t Bs = As + TILEA_SZ;

#pragma unroll
        for (int kk = 0; kk < 4; kk++) {
            const int cidx = 2*kk + lcolhalf;
            const uint32_t coff = (uint32_t)((cidx ^ sw) << 4);

            uint32_t a[2][4];
#pragma unroll
            for (int mi = 0; mi < 2; mi++) {
                const int r = wm*32 + mi*16 + lrow;
                ldsm_x4(a[mi][0], a[mi][1], a[mi][2], a[mi][3],
                        As + (uint32_t)r*128 + coff);
            }
            uint32_t b[4][4];
#pragma unroll
            for (int ni = 0; ni < 4; ni++) {
                const int r = wn*64 + ni*16 + lrow;
                ldsm_x4(b[ni][0], b[ni][1], b[ni][2], b[ni][3],
                        Bs + (uint32_t)r*128 + coff);
            }
#pragma unroll
            for (int mi = 0; mi < 2; mi++)
#pragma unroll
                for (int ni = 0; ni < 4; ni++) {
                    mma16816(acc[mi][2*ni+0], a[mi], b[ni][0], b[ni][2]);
                    mma16816(acc[mi][2*ni+1], a[mi], b[ni][1], b[ni][3]);
                }
        }
        __syncthreads();
        if (tid == 0 && c + STAGES < NCHUNK) {
            int ax, bx; coords(c + STAGES, ax, bx);
            MBARRIER_EXPECT_TX(FULL + 8*s, STAGE_SZ);
            tma2d(As, &tmA, ax, bm, FULL + 8*s);
            tma2d(Bs, &tmB, bx, bn, FULL + 8*s);
        }
    }

    const int grp = lane >> 2;
    const int qd  = lane & 3;
#pragma unroll
    for (int mi = 0; mi < 2; mi++) {
#pragma unroll
        for (int nj = 0; nj < 8; nj++) {
            const int col = bn + wn*64 + nj*8 + qd*2;
            const float b0 = __ldg(&bias[col]);
            const float b1 = __ldg(&bias[col + 1]);
#pragma unroll
            for (int half = 0; half < 2; half++) {
                const int m = bm + wm*32 + mi*16 + grp + half*8;
                float v0 = acc[mi][nj][2*half+0] + b0;
                float v1 = acc[mi][nj][2*half+1] + b1;
                if (MODE == 0) {
                    *(float2*)&C[(size_t)m * DMODEL + col] = make_float2(v0, v1);
                } else {
                    v0 *= scale; v1 *= scale;
                    const int b = m >> 11, srow = m & 2047;
                    const int h = col >> 6, d = col & 63;
                    const size_t off = (((size_t)b * NHEAD + h) * SEQ + srow) * DHEAD + d;
                    uint32_t hp, lp;
                    split_pack2(v0, v1, hp, lp);
                    *(uint32_t*)&Oh[off] = hp;
                    *(uint32_t*)&Ol[off] = lp;
                }
            }
        }
    }
}

// ---------------------------------------------------------------------------
// Flash attention on HMMA with compensated bf16 splits.
// CTA: 128 Q rows, 8 warps x m16 tiles, 64 keys/iter, 2-stage TMA for K/V.
// ---------------------------------------------------------------------------
#define QT 128
#define KT 64
#define AT_TILEQ  16384              // 128 x 128B
#define AT_TILEKV 8192               // 64 x 128B
#define AT_STAGE  (4*AT_TILEKV)      // Kh,Kl,Vh,Vl
#define ASMEM (1024 + 2*AT_TILEQ + 2*AT_STAGE)

__global__ void __launch_bounds__(256)
attn_mma(const __grid_constant__ CUtensorMap tmQh, const __grid_constant__ CUtensorMap tmQl,
         const __grid_constant__ CUtensorMap tmKh, const __grid_constant__ CUtensorMap tmKl,
         const __grid_constant__ CUtensorMap tmVh, const __grid_constant__ CUtensorMap tmVl,
         __nv_bfloat16* __restrict__ AO)
{
    extern __shared__ char smraw[];
    const uint32_t sb = smem_u32(smraw);
    const uint32_t tiles = (sb + 1024) & ~1023u;
    const uint32_t QHs = tiles, QLs = tiles + AT_TILEQ;
    const uint32_t STG = tiles + 2*AT_TILEQ;
    const int tid = threadIdx.x, lane = tid & 31, wid = tid >> 5;
    const int bh = blockIdx.y;
    const int q0 = blockIdx.x * QT;
    const int gy = bh * SEQ;

    const uint32_t BQ = sb, BF = sb + 8;   // BF[2] @ sb+8, sb+16
    if (tid == 0) {
        MBARRIER_INIT(BQ, 1);
        MBARRIER_INIT(BF + 0, 1);
        MBARRIER_INIT(BF + 8, 1);
    }
    __syncthreads();
    if (tid == 0) {
        MBARRIER_EXPECT_TX(BQ, 2*AT_TILEQ);
        tma2d(QHs, &tmQh, 0, gy + q0, BQ);
        tma2d(QLs, &tmQl, 0, gy + q0, BQ);
#pragma unroll
        for (int s = 0; s < 2; s++) {
            const uint32_t st = STG + s*AT_STAGE;
            MBARRIER_EXPECT_TX(BF + 8*s, AT_STAGE);
            tma2d(st,                &tmKh, 0, gy + s*KT, BF + 8*s);
            tma2d(st +   AT_TILEKV,  &tmKl, 0, gy + s*KT, BF + 8*s);
            tma2d(st + 2*AT_TILEKV,  &tmVh, 0, gy + s*KT, BF + 8*s);
            tma2d(st + 3*AT_TILEKV,  &tmVl, 0, gy + s*KT, BF + 8*s);
        }
    }

    float m_run[2] = { -1e30f, -1e30f };
    float l_run[2] = { 0.f, 0.f };
    float o_acc[8][4];
#pragma unroll
    for (int i = 0; i < 8; i++)
#pragma unroll
        for (int j = 0; j < 4; j++) o_acc[i][j] = 0.f;

    MBARRIER_WAIT_PARITY(BQ, 0);

    const int r0q = wid * 16;
    // ldmatrix lane-address components
    const int la7 = lane & 7;
    const int g01 = (lane >> 3) & 1;
    const int g23 = lane >> 4;

    for (int kt = 0; kt < SEQ / KT; kt++) {
        const int s = kt & 1, ph = (kt >> 1) & 1;
        MBARRIER_WAIT_PARITY(BF + 8*s, ph);
        const uint32_t Kh = STG + s*AT_STAGE;
        const uint32_t Kl = Kh + AT_TILEKV;
        const uint32_t Vh = Kh + 2*AT_TILEKV;
        const uint32_t Vl = Kh + 3*AT_TILEKV;

        float sf[8][4];
#pragma unroll
        for (int i = 0; i < 8; i++)
#pragma unroll
            for (int j = 0; j < 4; j++) sf[i][j] = 0.f;

        // ---- S = Q K^T (3-term split) ----
#pragma unroll
        for (int j = 0; j < 4; j++) {
            uint32_t qh[4], ql[4];
            {
                const int rr = r0q + la7 + g01*8;
                const int uu = 2*j + g23;
                ldsm_x4(qh[0],qh[1],qh[2],qh[3], ldsm_addr(QHs, rr, uu));
                ldsm_x4(ql[0],ql[1],ql[2],ql[3], ldsm_addr(QLs, rr, uu));
            }
#pragma unroll
            for (int np = 0; np < 4; np++) {
                const int rr = np*16 + la7 + g23*8;
                const int uu = 2*j + g01;
                uint32_t k0,k1,k2,k3, m0,m1,m2,m3;
                ldsm_x4(k0,k1,k2,k3, ldsm_addr(Kh, rr, uu));
                ldsm_x4(m0,m1,m2,m3, ldsm_addr(Kl, rr, uu));
                mma16816(sf[2*np+0], qh, k0, k1);
                mma16816(sf[2*np+1], qh, k2, k3);
                mma16816(sf[2*np+0], qh, m0, m1);
                mma16816(sf[2*np+1], qh, m2, m3);
                mma16816(sf[2*np+0], ql, k0, k1);
                mma16816(sf[2*np+1], ql, k2, k3);
            }
        }

        // ---- online softmax (rows lane>>2 and +8) ----
#pragma unroll
        for (int hf = 0; hf < 2; hf++) {
            float mx = -1e30f;
#pragma unroll
            for (int nt = 0; nt < 8; nt++)
                mx = fmaxf(mx, fmaxf(sf[nt][2*hf], sf[nt][2*hf+1]));
            mx = fmaxf(mx, __shfl_xor_sync(0xffffffffu, mx, 1));
            mx = fmaxf(mx, __shfl_xor_sync(0xffffffffu, mx, 2));
            const float mnew = fmaxf(m_run[hf], mx);
            const float corr = __expf(m_run[hf] - mnew);
            float sum = 0.f;
#pragma unroll
            for (int nt = 0; nt < 8; nt++) {
                const float p0 = __expf(sf[nt][2*hf]   - mnew);
                const float p1 = __expf(sf[nt][2*hf+1] - mnew);
                sf[nt][2*hf] = p0; sf[nt][2*hf+1] = p1;
                sum += p0 + p1;
            }
            sum += __shfl_xor_sync(0xffffffffu, sum, 1);
            sum += __shfl_xor_sync(0xffffffffu, sum, 2);
            l_run[hf] = l_run[hf] * corr + sum;
            m_run[hf] = mnew;
#pragma unroll
            for (int nt = 0; nt < 8; nt++) {
                o_acc[nt][2*hf]   *= corr;
                o_acc[nt][2*hf+1] *= corr;
            }
        }

        // ---- O += P V (3-term split; P c-frags re-packed as A-frags) ----
#pragma unroll
        for (int j = 0; j < 4; j++) {
            uint32_t ah[4], al[4];
#pragma unroll
            for (int t = 0; t < 4; t++) {
                // t0: tile2j vals0,1 | t1: tile2j vals2,3 | t2: tile2j+1 v0,1 | t3: v2,3
                const int nt = 2*j + (t >> 1);
                const int vv = (t & 1) * 2;
                split_pack2(sf[nt][vv+0], sf[nt][vv+1], ah[t], al[t]);
            }
#pragma unroll
            for (int np = 0; np < 4; np++) {
                const int rr = 16*j + la7 + g01*8;
                const int uu = 2*np + g23;
                uint32_t v0,v1,v2,v3, w0,w1,w2,w3;
                ldsm_x4_t(v0,v1,v2,v3, ldsm_addr(Vh, rr, uu));
                ldsm_x4_t(w0,w1,w2,w3, ldsm_addr(Vl, rr, uu));
                mma16816(o_acc[2*np+0], ah, v0, v1);
                mma16816(o_acc[2*np+1], ah, v2, v3);
                mma16816(o_acc[2*np+0], ah, w0, w1);
                mma16816(o_acc[2*np+1], ah, w2, w3);
                mma16816(o_acc[2*np+0], al, v0, v1);
                mma16816(o_acc[2*np+1], al, v2, v3);
            }
        }

        __syncthreads();
        if (tid == 0 && kt + 2 < SEQ / KT) {
            const uint32_t st = STG + s*AT_STAGE;
            MBARRIER_EXPECT_TX(BF + 8*s, AT_STAGE);
            tma2d(st,               &tmKh, 0, gy + (kt+2)*KT, BF + 8*s);
            tma2d(st +   AT_TILEKV, &tmKl, 0, gy + (kt+2)*KT, BF + 8*s);
            tma2d(st + 2*AT_TILEKV, &tmVh, 0, gy + (kt+2)*KT, BF + 8*s);
            tma2d(st + 3*AT_TILEKV, &tmVl, 0, gy + (kt+2)*KT, BF + 8*s);
        }
    }

    // ---- epilogue: AO split [m][2048] ----
    const int b = bh >> 4, h = bh & 15;
#pragma unroll
    for (int hf = 0; hf < 2; hf++) {
        const float inv = 1.f / l_run[hf];
        const int srow = q0 + r0q + (lane >> 2) + hf*8;
#pragma unroll
        for (int nt = 0; nt < 8; nt++) {
            const int d = nt*8 + (lane & 3)*2;
            const float f0 = o_acc[nt][2*hf]   * inv;
            const float f1 = o_acc[nt][2*hf+1] * inv;
            uint32_t hp, lp;
            split_pack2(f0, f1, hp, lp);
            const size_t base = ((size_t)b * SEQ + srow) * 2 * DMODEL + h * DHEAD + d;
            *(uint32_t*)&AO[base]          = hp;
            *(uint32_t*)&AO[base + DMODEL] = lp;
        }
    }
}

// ---------------------------------------------------------------------------
// Host
// ---------------------------------------------------------------------------
typedef CUresult (*PFN_tmEncode)(CUtensorMap*, CUtensorMapDataType, cuuint32_t, void*,
                                 const cuuint64_t*, const cuuint64_t*, const cuuint32_t*,
                                 const cuuint32_t*, CUtensorMapInterleave, CUtensorMapSwizzle,
                                 CUtensorMapL2promotion, CUtensorMapFloatOOBfill);

static void make_map(PFN_tmEncode enc, CUtensorMap* m, void* p, uint64_t rows,
                     uint64_t width, uint32_t b0, uint32_t b1)
{
    cuuint64_t dims[2]    = { width, rows };
    cuuint64_t strides[1] = { width * 2 };
    cuuint32_t box[2]     = { b0, b1 };
    cuuint32_t es[2]      = { 1, 1 };
    enc(m, CU_TENSOR_MAP_DATA_TYPE_BFLOAT16, 2, p, dims, strides, box, es,
        CU_TENSOR_MAP_INTERLEAVE_NONE, CU_TENSOR_MAP_SWIZZLE_128B,
        CU_TENSOR_MAP_L2_PROMOTION_L2_128B, CU_TENSOR_MAP_FLOAT_OOB_FILL_NONE);
}

extern "C" void kernel_launch(void* const* d_in, const int* in_sizes, int n_in,
                              void* d_out, int out_size)
{
    const float* act[3] = { (const float*)d_in[0], (const float*)d_in[1], (const float*)d_in[2] };
    const float* W[4]   = { (const float*)d_in[3], (const float*)d_in[5], (const float*)d_in[7], (const float*)d_in[9] };
    const float* bia[4] = { (const float*)d_in[4], (const float*)d_in[6], (const float*)d_in[8], (const float*)d_in[10] };
    float* out = (float*)d_out;

    __nv_bfloat16 *pact, *pwt, *pao, *pqkv;
    cudaGetSymbolAddress((void**)&pact, g_act);
    cudaGetSymbolAddress((void**)&pwt,  g_wt);
    cudaGetSymbolAddress((void**)&pao,  g_ao);
    cudaGetSymbolAddress((void**)&pqkv, g_qkvs);

    PFN_tmEncode enc = nullptr;
    cudaDriverEntryPointQueryResult qr;
    cudaGetDriverEntryPointByVersion("cuTensorMapEncodeTiled", (void**)&enc, 12000,
                                     cudaEnableDefault, &qr);

    const size_t AM2 = (size_t)MTOT * 2 * DMODEL;
    const size_t WM2 = (size_t)DMODEL * 2 * DMODEL;

    static CUtensorMap mA[4], mB[4], mQKV[6];
    for (int i = 0; i < 3; i++) make_map(enc, &mA[i], pact + i * AM2, MTOT, 2*DMODEL, BK, 128);
    make_map(enc, &mA[3], pao, MTOT, 2*DMODEL, BK, 128);
    for (int i = 0; i < 4; i++) make_map(enc, &mB[i], pwt + i * WM2, DMODEL, 2*DMODEL, BK, 128);
    for (int i = 0; i < 6; i++)
        make_map(enc, &mQKV[i], pqkv + i * QKVPART, (uint64_t)BHTOT * SEQ, DHEAD,
                 DHEAD, (i < 2) ? QT : KT);

    cudaFuncSetAttribute(gemm_mma<0>, cudaFuncAttributeMaxDynamicSharedMemorySize, GSMEM);
    cudaFuncSetAttribute(gemm_mma<1>, cudaFuncAttributeMaxDynamicSharedMemorySize, GSMEM);
    cudaFuncSetAttribute(attn_mma, cudaFuncAttributeMaxDynamicSharedMemorySize, ASMEM);

    // 1. split activations into [m][2048] (hi|lo)
    for (int i = 0; i < 3; i++)
        split_rows_kernel<<<MTOT, 256>>>(act[i], pact + i * AM2);

    // 2. transpose + split weights into [n][2048]
    for (int i = 0; i < 4; i++)
        wt_split_kernel<<<dim3(32, 32), dim3(32, 8)>>>(W[i], pwt + i * WM2);

    // 3. QKV projections -> split bf16 [BH][S][64]; fold 1/8 scale into Q
    dim3 gg(DMODEL / 128, MTOT / 128);
    for (int i = 0; i < 3; i++)
        gemm_mma<1><<<gg, 256, GSMEM>>>(mA[i], mB[i], bia[i], nullptr,
                                        pqkv + (2*i+0) * QKVPART,
                                        pqkv + (2*i+1) * QKVPART,
                                        (i == 0) ? 0.125f : 1.0f);

    // 4. attention (HMMA), writes split AO
    attn_mma<<<dim3(SEQ / QT, BHTOT), 256, ASMEM>>>(
        mQKV[0], mQKV[1], mQKV[2], mQKV[3], mQKV[4], mQKV[5], pao);

    // 5. output projection
    gemm_mma<0><<<gg, 256, GSMEM>>>(mA[3], mB[3], bia[3], out, nullptr, nullptr, 1.0f);
}

// round 7
// speedup vs baseline: 3.1588x; 1.1017x over previous
#include <cuda_runtime.h>
#include <cuda.h>
#include <cuda_bf16.h>
#include <cuda_fp16.h>
#include <cstdint>

#define BATCH 2
#define SEQ   2048
#define DMODEL 1024
#define NHEAD 16
#define DHEAD 64
#define MTOT  (BATCH*SEQ)          // 4096
#define BHTOT (BATCH*NHEAD)        // 32
#define QKVPART ((size_t)BHTOT*SEQ*DHEAD)

// Q scale folded with log2(e) for exp2-domain softmax; applied to Wq/bq at
// preprocessing time (NOT in the GEMM epilogue).
#define QSCALE 0.1803368801111832f   // 0.125 * log2(e)

// ---------------------------------------------------------------------------
// Device scratch
// ---------------------------------------------------------------------------
__device__ __nv_bfloat16 g_act[3u*MTOT*2*DMODEL];    // activations split (hi|lo)
__device__ __nv_bfloat16 g_wt[4u*DMODEL*2*DMODEL];   // W^T split; segs q,k,v,o
__device__ __nv_bfloat16 g_ao[(size_t)MTOT*2*DMODEL];// attention out split
__device__ __half g_qkvs[6*QKVPART];                 // Qh,Ql,Kh,Kl,Vh,Vl (fp16)
__device__ float g_biasc[3*DMODEL];                  // concat bq*QSCALE|bk|bv

// ---------------------------------------------------------------------------
// PTX helpers (legal at virtual arch compute_103)
// ---------------------------------------------------------------------------
__device__ __forceinline__ uint32_t smem_u32(const void* p) {
    uint32_t a;
    asm("{ .reg .u64 t; cvta.to.shared.u64 t, %1; cvt.u32.u64 %0, t; }" : "=r"(a) : "l"(p));
    return a;
}

#define MBARRIER_INIT(addr, cnt) \
    asm volatile("mbarrier.init.shared.b64 [%0], %1;" :: "r"((uint32_t)(addr)), "r"((uint32_t)(cnt)) : "memory")
#define MBARRIER_EXPECT_TX(addr, bytes) \
    asm volatile("mbarrier.arrive.expect_tx.shared.b64 _, [%0], %1;" :: "r"((uint32_t)(addr)), "r"((uint32_t)(bytes)) : "memory")

#define MBARRIER_WAIT_PARITY(mbar_smem_addr, phase_parity) do { \
    uint32_t _mbar = (uint32_t)(mbar_smem_addr); \
    uint32_t _parity = (uint32_t)(phase_parity); \
    uint32_t _done; \
    asm volatile( \
        "{\n\t.reg .pred p;\n\t" \
        "mbarrier.try_wait.parity.acquire.cta.shared::cta.b64 p, [%1], %2;\n\t" \
        "selp.b32 %0, 1, 0, p;\n\t}" \
        : "=r"(_done) : "r"(_mbar), "r"(_parity) : "memory"); \
    if (!_done) { \
        asm volatile( \
            "{\n\t.reg .pred P1;\n\t" \
            "WAIT_LOOP_%=:\n\t" \
            "mbarrier.try_wait.parity.acquire.cta.shared::cta.b64 P1, [%0], %1, 0x989680;\n\t" \
            "@P1 bra.uni WAIT_DONE_%=;\n\t" \
            "bra.uni WAIT_LOOP_%=;\n\t" \
            "WAIT_DONE_%=:\n\t}" \
            :: "r"(_mbar), "r"(_parity) : "memory"); \
    } \
} while(0)

__device__ __forceinline__ void tma2d(uint32_t dst, const CUtensorMap* m, int x, int y, uint32_t bar) {
    asm volatile(
        "cp.async.bulk.tensor.2d.shared::cta.global.tile.mbarrier::complete_tx::bytes "
        "[%0], [%1, {%2, %3}], [%4];"
        :: "r"(dst), "l"(m), "r"(x), "r"(y), "r"(bar) : "memory");
}

__device__ __forceinline__ void ldsm_x4(uint32_t& r0, uint32_t& r1, uint32_t& r2, uint32_t& r3,
                                        uint32_t addr) {
    asm volatile("ldmatrix.sync.aligned.m8n8.x4.shared.b16 {%0,%1,%2,%3}, [%4];"
                 : "=r"(r0), "=r"(r1), "=r"(r2), "=r"(r3) : "r"(addr));
}
__device__ __forceinline__ void ldsm_x4_t(uint32_t& r0, uint32_t& r1, uint32_t& r2, uint32_t& r3,
                                          uint32_t addr) {
    asm volatile("ldmatrix.sync.aligned.m8n8.x4.trans.shared.b16 {%0,%1,%2,%3}, [%4];"
                 : "=r"(r0), "=r"(r1), "=r"(r2), "=r"(r3) : "r"(addr));
}

// bf16 mma (GEMMs)
__device__ __forceinline__ void mma16816(float* c, const uint32_t* a, uint32_t b0, uint32_t b1) {
    asm volatile(
        "mma.sync.aligned.m16n8k16.row.col.f32.bf16.bf16.f32 "
        "{%0,%1,%2,%3}, {%4,%5,%6,%7}, {%8,%9}, {%0,%1,%2,%3};"
        : "+f"(c[0]), "+f"(c[1]), "+f"(c[2]), "+f"(c[3])
        : "r"(a[0]), "r"(a[1]), "r"(a[2]), "r"(a[3]), "r"(b0), "r"(b1));
}
// fp16 mma (attention)
__device__ __forceinline__ void mma16816h(float* c, const uint32_t* a, uint32_t b0, uint32_t b1) {
    asm volatile(
        "mma.sync.aligned.m16n8k16.row.col.f32.f16.f16.f32 "
        "{%0,%1,%2,%3}, {%4,%5,%6,%7}, {%8,%9}, {%0,%1,%2,%3};"
        : "+f"(c[0]), "+f"(c[1]), "+f"(c[2]), "+f"(c[3])
        : "r"(a[0]), "r"(a[1]), "r"(a[2]), "r"(a[3]), "r"(b0), "r"(b1));
}

__device__ __forceinline__ void split_bf16(float x, __nv_bfloat16& h, __nv_bfloat16& l) {
    h = __float2bfloat16(x);
    l = __float2bfloat16(x - __bfloat162float(h));
}
__device__ __forceinline__ void split_pack2_bf16(float x0, float x1, uint32_t& hp, uint32_t& lp) {
    __nv_bfloat16 h0,l0,h1,l1;
    split_bf16(x0,h0,l0); split_bf16(x1,h1,l1);
    hp = (uint32_t)__bfloat16_as_ushort(h0) | ((uint32_t)__bfloat16_as_ushort(h1) << 16);
    lp = (uint32_t)__bfloat16_as_ushort(l0) | ((uint32_t)__bfloat16_as_ushort(l1) << 16);
}
// pack two fp32 -> fp16x2 (x0 in low half)
__device__ __forceinline__ uint32_t pack2_f16(float x0, float x1) {
    uint32_t u;
    asm("cvt.rn.f16x2.f32 %0, %1, %2;" : "=r"(u) : "f"(x1), "f"(x0));
    return u;
}
__device__ __forceinline__ void split_pack2_f16(float x0, float x1, uint32_t& hp, uint32_t& lp) {
    hp = pack2_f16(x0, x1);
    __half2 hh = *reinterpret_cast<__half2*>(&hp);
    lp = pack2_f16(x0 - __low2float(hh), x1 - __high2float(hh));
}
__device__ __forceinline__ float ex2(float x) {
    float y; asm("ex2.approx.f32 %0, %1;" : "=f"(y) : "f"(x)); return y;
}

// smem address for 16B unit `u` of row `r` in a SW128 tile (128B rows)
__device__ __forceinline__ uint32_t ldsm_addr(uint32_t base, int r, int u) {
    return base + (uint32_t)r * 128u + (uint32_t)((u ^ (r & 7)) << 4);
}

// ---------------------------------------------------------------------------
// Fused preprocessing
// ---------------------------------------------------------------------------
__global__ void __launch_bounds__(256)
split_rows_kernel(const float* __restrict__ q, const float* __restrict__ k,
                  const float* __restrict__ v, __nv_bfloat16* __restrict__ dstbase)
{
    const float* x = (blockIdx.y == 0) ? q : (blockIdx.y == 1) ? k : v;
    __nv_bfloat16* dst = dstbase + (size_t)blockIdx.y * MTOT * 2 * DMODEL;
    const int m = blockIdx.x;
    const int k4 = threadIdx.x * 4;
    float4 val = *(const float4*)&x[(size_t)m * DMODEL + k4];
    uint32_t hp0, lp0, hp1, lp1;
    split_pack2_bf16(val.x, val.y, hp0, lp0);
    split_pack2_bf16(val.z, val.w, hp1, lp1);
    __nv_bfloat16* hi = dst + (size_t)m * 2 * DMODEL + k4;
    *(uint32_t*)(hi)          = hp0;
    *(uint32_t*)(hi + 2)      = hp1;
    *(uint32_t*)(hi + DMODEL)     = lp0;
    *(uint32_t*)(hi + DMODEL + 2) = lp1;
}

// QSCALE folded into Wq (z==0) here, pre-split, so split precision is exact.
__global__ void __launch_bounds__(256)
wt_split_kernel(const float* __restrict__ Wq, const float* __restrict__ Wk,
                const float* __restrict__ Wv, const float* __restrict__ Wo,
                __nv_bfloat16* __restrict__ Tbase)
{
    const float* W = (blockIdx.z == 0) ? Wq : (blockIdx.z == 1) ? Wk
                   : (blockIdx.z == 2) ? Wv : Wo;
    const float sc = (blockIdx.z == 0) ? QSCALE : 1.0f;
    __nv_bfloat16* T = Tbase + (size_t)blockIdx.z * DMODEL * 2 * DMODEL;
    __shared__ float t[32][33];
    const int n0 = blockIdx.x * 32, k0 = blockIdx.y * 32;
    const int tx = threadIdx.x, ty = threadIdx.y;   // (32, 8)
#pragma unroll
    for (int i = 0; i < 4; i++)
        t[ty + 8*i][tx] = W[(size_t)(k0 + ty + 8*i) * DMODEL + n0 + tx];
    __syncthreads();
#pragma unroll
    for (int i = 0; i < 4; i++) {
        const int n = n0 + ty + 8*i;
        const int k = k0 + tx;
        float v = t[tx][ty + 8*i] * sc;
        __nv_bfloat16 h, l; split_bf16(v, h, l);
        T[(size_t)n * 2 * DMODEL + k] = h;
        T[(size_t)n * 2 * DMODEL + DMODEL + k] = l;
    }
}

__global__ void __launch_bounds__(256)
bias_concat_kernel(const float* __restrict__ bq, const float* __restrict__ bk,
                   const float* __restrict__ bv, float* __restrict__ dst)
{
    const int i = blockIdx.x * 256 + threadIdx.x;       // 0..3071
    const float* s = (i < 1024) ? bq : (i < 2048) ? bk : bv;
    const float sc = (i < 1024) ? QSCALE : 1.0f;
    dst[i] = s[i & 1023] * sc;
}

// ---------------------------------------------------------------------------
// HMMA GEMM, 3-term compensated bf16 split, one K'=3072 loop.
// MODE 0: row-major fp32 C (N=1024).
// MODE 1: fp16 split scatter to [BH][S][64] hi/lo (no scaling here).
// ---------------------------------------------------------------------------
#define BK       64
#define NCHUNK   48
#define STAGES   3
#define TILEA_SZ 16384
#define TILEB_SZ 16384
#define STAGE_SZ (TILEA_SZ + TILEB_SZ)
#define GSMEM    (1024 + STAGES * STAGE_SZ)

template<int MODE>
__global__ void __launch_bounds__(256, 2)
gemm_mma(const __grid_constant__ CUtensorMap tmA,
         const __grid_constant__ CUtensorMap tmB,
         const float* __restrict__ bias, float* __restrict__ C,
         __half* __restrict__ qkv)
{
    extern __shared__ char sm_raw[];
    const uint32_t sb = smem_u32(sm_raw);
    const uint32_t tiles = (sb + 1024) & ~1023u;
    const int tid = threadIdx.x;
    const int lane = tid & 31, wid = tid >> 5;
    const int wm = wid & 3, wn = wid >> 2;

    const uint32_t FULL = sb;

    if (tid == 0) {
#pragma unroll
        for (int s = 0; s < STAGES; s++) MBARRIER_INIT(FULL + 8*s, 1);
    }
    __syncthreads();

    const int bm = blockIdx.y * 128;
    const int bn = blockIdx.x * 128;

    auto coords = [](int c, int& ax, int& bx) {
        const int seg = c >> 4;
        const int kk = (c & 15) * BK;
        ax = (seg == 2) ? DMODEL + kk : kk;
        bx = (seg == 1) ? DMODEL + kk : kk;
    };

    if (tid == 0) {
#pragma unroll
        for (int s = 0; s < STAGES; s++) {
            int ax, bx; coords(s, ax, bx);
            MBARRIER_EXPECT_TX(FULL + 8*s, STAGE_SZ);
            tma2d(tiles + s*STAGE_SZ,            &tmA, ax, bm, FULL + 8*s);
            tma2d(tiles + s*STAGE_SZ + TILEA_SZ, &tmB, bx, bn, FULL + 8*s);
        }
    }

    float acc[2][8][4];
#pragma unroll
    for (int i = 0; i < 2; i++)
#pragma unroll
        for (int j = 0; j < 8; j++)
#pragma unroll
            for (int q = 0; q < 4; q++) acc[i][j][q] = 0.f;

    const int lrow = lane & 15;
    const int lcolhalf = lane >> 4;
    const int sw = lane & 7;

    for (int c = 0; c < NCHUNK; c++) {
        const int s = c % STAGES;
        const int ph = (c / STAGES) & 1;
        MBARRIER_WAIT_PARITY(FULL + 8*s, ph);

        const uint32_t As = tiles + s*STAGE_SZ;
        const uint32_t Bs = As + TILEA_SZ;

#pragma unroll
        for (int kk = 0; kk < 4; kk++) {
            const int cidx = 2*kk + lcolhalf;
            const uint32_t coff = (uint32_t)((cidx ^ sw) << 4);

            uint32_t a[2][4];
#pragma unroll
            for (int mi = 0; mi < 2; mi++) {
                const int r = wm*32 + mi*16 + lrow;
                ldsm_x4(a[mi][0], a[mi][1], a[mi][2], a[mi][3],
                        As + (uint32_t)r*128 + coff);
            }
            uint32_t b[4][4];
#pragma unroll
            for (int ni = 0; ni < 4; ni++) {
                const int r = wn*64 + ni*16 + lrow;
                ldsm_x4(b[ni][0], b[ni][1], b[ni][2], b[ni][3],
                        Bs + (uint32_t)r*128 + coff);
            }
#pragma unroll
            for (int mi = 0; mi < 2; mi++)
#pragma unroll
                for (int ni = 0; ni < 4; ni++) {
                    mma16816(acc[mi][2*ni+0], a[mi], b[ni][0], b[ni][2]);
                    mma16816(acc[mi][2*ni+1], a[mi], b[ni][1], b[ni][3]);
                }
        }
        __syncthreads();
        if (tid == 0 && c + STAGES < NCHUNK) {
            int ax, bx; coords(c + STAGES, ax, bx);
            MBARRIER_EXPECT_TX(FULL + 8*s, STAGE_SZ);
            tma2d(As, &tmA, ax, bm, FULL + 8*s);
            tma2d(Bs, &tmB, bx, bn, FULL + 8*s);
        }
    }

    const int grp = lane >> 2;
    const int qd  = lane & 3;
#pragma unroll
    for (int mi = 0; mi < 2; mi++) {
#pragma unroll
        for (int nj = 0; nj < 8; nj++) {
            const int col = bn + wn*64 + nj*8 + qd*2;
            const float b0 = __ldg(&bias[col]);
            const float b1 = __ldg(&bias[col + 1]);
#pragma unroll
            for (int half = 0; half < 2; half++) {
                const int m = bm + wm*32 + mi*16 + grp + half*8;
                const float v0 = acc[mi][nj][2*half+0] + b0;
                const float v1 = acc[mi][nj][2*half+1] + b1;
                if (MODE == 0) {
                    *(float2*)&C[(size_t)m * DMODEL + col] = make_float2(v0, v1);
                } else {
                    const int b = m >> 11, srow = m & 2047;
                    const int h = col >> 6, d = col & 63;
                    const size_t off = (((size_t)b * NHEAD + h) * SEQ + srow) * DHEAD + d;
                    uint32_t hp, lp;
                    split_pack2_f16(v0, v1, hp, lp);
                    *(uint32_t*)&qkv[off]            = hp;
                    *(uint32_t*)&qkv[off + QKVPART]  = lp;
                }
            }
        }
    }
}

// ---------------------------------------------------------------------------
// Flash attention on fp16 HMMA. QK: 3-product split; PV: 2-product (P≈Ph).
// exp2-domain softmax (log2e pre-folded into Wq/bq).
// ---------------------------------------------------------------------------
#define QT 128
#define KT 64
#define AT_TILEQ  16384
#define AT_TILEKV 8192
#define AT_STAGE  (4*AT_TILEKV)
#define ASMEM (1024 + 2*AT_TILEQ + 2*AT_STAGE)

__global__ void __launch_bounds__(256)
attn_mma(const __grid_constant__ CUtensorMap tmQh, const __grid_constant__ CUtensorMap tmQl,
         const __grid_constant__ CUtensorMap tmKh, const __grid_constant__ CUtensorMap tmKl,
         const __grid_constant__ CUtensorMap tmVh, const __grid_constant__ CUtensorMap tmVl,
         __nv_bfloat16* __restrict__ AO)
{
    extern __shared__ char smraw[];
    const uint32_t sb = smem_u32(smraw);
    const uint32_t tiles = (sb + 1024) & ~1023u;
    const uint32_t QHs = tiles, QLs = tiles + AT_TILEQ;
    const uint32_t STG = tiles + 2*AT_TILEQ;
    const int tid = threadIdx.x, lane = tid & 31, wid = tid >> 5;
    const int bh = blockIdx.y;
    const int q0 = blockIdx.x * QT;
    const int gy = bh * SEQ;

    const uint32_t BQ = sb, BF = sb + 8;
    if (tid == 0) {
        MBARRIER_INIT(BQ, 1);
        MBARRIER_INIT(BF + 0, 1);
        MBARRIER_INIT(BF + 8, 1);
    }
    __syncthreads();
    if (tid == 0) {
        MBARRIER_EXPECT_TX(BQ, 2*AT_TILEQ);
        tma2d(QHs, &tmQh, 0, gy + q0, BQ);
        tma2d(QLs, &tmQl, 0, gy + q0, BQ);
#pragma unroll
        for (int s = 0; s < 2; s++) {
            const uint32_t st = STG + s*AT_STAGE;
            MBARRIER_EXPECT_TX(BF + 8*s, AT_STAGE);
            tma2d(st,                &tmKh, 0, gy + s*KT, BF + 8*s);
            tma2d(st +   AT_TILEKV,  &tmKl, 0, gy + s*KT, BF + 8*s);
            tma2d(st + 2*AT_TILEKV,  &tmVh, 0, gy + s*KT, BF + 8*s);
            tma2d(st + 3*AT_TILEKV,  &tmVl, 0, gy + s*KT, BF + 8*s);
        }
    }

    float m_run[2] = { -1e30f, -1e30f };
    float l_run[2] = { 0.f, 0.f };
    float o_acc[8][4];
#pragma unroll
    for (int i = 0; i < 8; i++)
#pragma unroll
        for (int j = 0; j < 4; j++) o_acc[i][j] = 0.f;

    MBARRIER_WAIT_PARITY(BQ, 0);

    const int r0q = wid * 16;
    const int la7 = lane & 7;
    const int g01 = (lane >> 3) & 1;
    const int g23 = lane >> 4;

    for (int kt = 0; kt < SEQ / KT; kt++) {
        const int s = kt & 1, ph = (kt >> 1) & 1;
        MBARRIER_WAIT_PARITY(BF + 8*s, ph);
        const uint32_t Kh = STG + s*AT_STAGE;
        const uint32_t Kl = Kh + AT_TILEKV;
        const uint32_t Vh = Kh + 2*AT_TILEKV;
        const uint32_t Vl = Kh + 3*AT_TILEKV;

        float sf[8][4];
#pragma unroll
        for (int i = 0; i < 8; i++)
#pragma unroll
            for (int j = 0; j < 4; j++) sf[i][j] = 0.f;

        // ---- S = Q K^T, fp16 3-product ----
#pragma unroll
        for (int j = 0; j < 4; j++) {
            uint32_t qh[4], ql[4];
            {
                const int rr = r0q + la7 + g01*8;
                const int uu = 2*j + g23;
                ldsm_x4(qh[0],qh[1],qh[2],qh[3], ldsm_addr(QHs, rr, uu));
                ldsm_x4(ql[0],ql[1],ql[2],ql[3], ldsm_addr(QLs, rr, uu));
            }
#pragma unroll
            for (int np = 0; np < 4; np++) {
                const int rr = np*16 + la7 + g23*8;
                const int uu = 2*j + g01;
                uint32_t k0,k1,k2,k3, m0,m1,m2,m3;
                ldsm_x4(k0,k1,k2,k3, ldsm_addr(Kh, rr, uu));
                ldsm_x4(m0,m1,m2,m3, ldsm_addr(Kl, rr, uu));
                mma16816h(sf[2*np+0], qh, k0, k1);
                mma16816h(sf[2*np+1], qh, k2, k3);
                mma16816h(sf[2*np+0], qh, m0, m1);
                mma16816h(sf[2*np+1], qh, m2, m3);
                mma16816h(sf[2*np+0], ql, k0, k1);
                mma16816h(sf[2*np+1], ql, k2, k3);
            }
        }

        // ---- online softmax in exp2 domain ----
#pragma unroll
        for (int hf = 0; hf < 2; hf++) {
            float mx = -1e30f;
#pragma unroll
            for (int nt = 0; nt < 8; nt++)
                mx = fmaxf(mx, fmaxf(sf[nt][2*hf], sf[nt][2*hf+1]));
            mx = fmaxf(mx, __shfl_xor_sync(0xffffffffu, mx, 1));
            mx = fmaxf(mx, __shfl_xor_sync(0xffffffffu, mx, 2));
            const float mnew = fmaxf(m_run[hf], mx);
            const float corr = ex2(m_run[hf] - mnew);
            float sum = 0.f;
#pragma unroll
            for (int nt = 0; nt < 8; nt++) {
                const float p0 = ex2(sf[nt][2*hf]   - mnew);
                const float p1 = ex2(sf[nt][2*hf+1] - mnew);
                sf[nt][2*hf] = p0; sf[nt][2*hf+1] = p1;
                sum += p0 + p1;
            }
            sum += __shfl_xor_sync(0xffffffffu, sum, 1);
            sum += __shfl_xor_sync(0xffffffffu, sum, 2);
            l_run[hf] = l_run[hf] * corr + sum;
            m_run[hf] = mnew;
#pragma unroll
            for (int nt = 0; nt < 8; nt++) {
                o_acc[nt][2*hf]   *= corr;
                o_acc[nt][2*hf+1] *= corr;
            }
        }

        // ---- O += P V, fp16 2-product (P = Ph only; V split) ----
#pragma unroll
        for (int j = 0; j < 4; j++) {
            uint32_t ph16[4];
#pragma unroll
            for (int t = 0; t < 4; t++) {
                const int nt = 2*j + (t >> 1);
                const int vv = (t & 1) * 2;
                ph16[t] = pack2_f16(sf[nt][vv+0], sf[nt][vv+1]);
            }
#pragma unroll
            for (int np = 0; np < 4; np++) {
                const int rr = 16*j + la7 + g01*8;
                const int uu = 2*np + g23;
                uint32_t v0,v1,v2,v3, w0,w1,w2,w3;
                ldsm_x4_t(v0,v1,v2,v3, ldsm_addr(Vh, rr, uu));
                ldsm_x4_t(w0,w1,w2,w3, ldsm_addr(Vl, rr, uu));
                mma16816h(o_acc[2*np+0], ph16, v0, v1);
                mma16816h(o_acc[2*np+1], ph16, v2, v3);
                mma16816h(o_acc[2*np+0], ph16, w0, w1);
                mma16816h(o_acc[2*np+1], ph16, w2, w3);
            }
        }

        __syncthreads();
        if (tid == 0 && kt + 2 < SEQ / KT) {
            const uint32_t st = STG + s*AT_STAGE;
            MBARRIER_EXPECT_TX(BF + 8*s, AT_STAGE);
            tma2d(st,               &tmKh, 0, gy + (kt+2)*KT, BF + 8*s);
            tma2d(st +   AT_TILEKV, &tmKl, 0, gy + (kt+2)*KT, BF + 8*s);
            tma2d(st + 2*AT_TILEKV, &tmVh, 0, gy + (kt+2)*KT, BF + 8*s);
            tma2d(st + 3*AT_TILEKV, &tmVl, 0, gy + (kt+2)*KT, BF + 8*s);
        }
    }

    // ---- epilogue: AO split bf16 [m][2048] ----
    const int b = bh >> 4, h = bh & 15;
#pragma unroll
    for (int hf = 0; hf < 2; hf++) {
        const float inv = 1.f / l_run[hf];
        const int srow = q0 + r0q + (lane >> 2) + hf*8;
#pragma unroll
        for (int nt = 0; nt < 8; nt++) {
            const int d = nt*8 + (lane & 3)*2;
            const float f0 = o_acc[nt][2*hf]   * inv;
            const float f1 = o_acc[nt][2*hf+1] * inv;
            uint32_t hp, lp;
            split_pack2_bf16(f0, f1, hp, lp);
            const size_t base = ((size_t)b * SEQ + srow) * 2 * DMODEL + h * DHEAD + d;
            *(uint32_t*)&AO[base]          = hp;
            *(uint32_t*)&AO[base + DMODEL] = lp;
        }
    }
}

// ---------------------------------------------------------------------------
// Host
// ---------------------------------------------------------------------------
typedef CUresult (*PFN_tmEncode)(CUtensorMap*, CUtensorMapDataType, cuuint32_t, void*,
                                 const cuuint64_t*, const cuuint64_t*, const cuuint32_t*,
                                 const cuuint32_t*, CUtensorMapInterleave, CUtensorMapSwizzle,
                                 CUtensorMapL2promotion, CUtensorMapFloatOOBfill);

static void make_map(PFN_tmEncode enc, CUtensorMap* m, void* p, uint64_t rows,
                     uint64_t width, uint32_t b0, uint32_t b1, CUtensorMapDataType dt)
{
    cuuint64_t dims[2]    = { width, rows };
    cuuint64_t strides[1] = { width * 2 };
    cuuint32_t box[2]     = { b0, b1 };
    cuuint32_t es[2]      = { 1, 1 };
    enc(m, dt, 2, p, dims, strides, box, es,
        CU_TENSOR_MAP_INTERLEAVE_NONE, CU_TENSOR_MAP_SWIZZLE_128B,
        CU_TENSOR_MAP_L2_PROMOTION_L2_128B, CU_TENSOR_MAP_FLOAT_OOB_FILL_NONE);
}

extern "C" void kernel_launch(void* const* d_in, const int* in_sizes, int n_in,
                              void* d_out, int out_size)
{
    const float* act[3] = { (const float*)d_in[0], (const float*)d_in[1], (const float*)d_in[2] };
    const float* W[4]   = { (const float*)d_in[3], (const float*)d_in[5], (const float*)d_in[7], (const float*)d_in[9] };
    const float* bia[4] = { (const float*)d_in[4], (const float*)d_in[6], (const float*)d_in[8], (const float*)d_in[10] };
    float* out = (float*)d_out;

    __nv_bfloat16 *pact, *pwt, *pao;
    __half* pqkv;
    float* pbc;
    cudaGetSymbolAddress((void**)&pact, g_act);
    cudaGetSymbolAddress((void**)&pwt,  g_wt);
    cudaGetSymbolAddress((void**)&pao,  g_ao);
    cudaGetSymbolAddress((void**)&pqkv, g_qkvs);
    cudaGetSymbolAddress((void**)&pbc,  g_biasc);

    PFN_tmEncode enc = nullptr;
    cudaDriverEntryPointQueryResult qr;
    cudaGetDriverEntryPointByVersion("cuTensorMapEncodeTiled", (void**)&enc, 12000,
                                     cudaEnableDefault, &qr);

    const size_t WM2 = (size_t)DMODEL * 2 * DMODEL;

    static CUtensorMap mA[3], mAao, mBseg[3], mBo, mQKV[6];
    const CUtensorMapDataType BF = CU_TENSOR_MAP_DATA_TYPE_BFLOAT16;
    const CUtensorMapDataType F16 = CU_TENSOR_MAP_DATA_TYPE_FLOAT16;
    for (int i = 0; i < 3; i++)
        make_map(enc, &mA[i], pact + (size_t)i * MTOT * 2 * DMODEL, MTOT, 2*DMODEL, BK, 128, BF);
    make_map(enc, &mAao, pao, MTOT, 2*DMODEL, BK, 128, BF);
    for (int i = 0; i < 3; i++)
        make_map(enc, &mBseg[i], pwt + (size_t)i * WM2, DMODEL, 2*DMODEL, BK, 128, BF);
    make_map(enc, &mBo, pwt + 3*WM2, DMODEL, 2*DMODEL, BK, 128, BF);
    for (int i = 0; i < 6; i++)
        make_map(enc, &mQKV[i], pqkv + i * QKVPART, (uint64_t)BHTOT * SEQ, DHEAD,
                 DHEAD, (i < 2) ? QT : KT, F16);

    cudaFuncSetAttribute(gemm_mma<0>, cudaFuncAttributeMaxDynamicSharedMemorySize, GSMEM);
    cudaFuncSetAttribute(gemm_mma<1>, cudaFuncAttributeMaxDynamicSharedMemorySize, GSMEM);
    cudaFuncSetAttribute(attn_mma, cudaFuncAttributeMaxDynamicSharedMemorySize, ASMEM);

    // 1. fused preprocessing
    split_rows_kernel<<<dim3(MTOT, 3), 256>>>(act[0], act[1], act[2], pact);
    wt_split_kernel<<<dim3(32, 32, 4), dim3(32, 8)>>>(W[0], W[1], W[2], W[3], pwt);
    bias_concat_kernel<<<12, 256>>>(bia[0], bia[1], bia[2], pbc);

    // 2. QKV projections -> fp16 split QKV (scale pre-folded into Wq/bq)
    dim3 gg(DMODEL / 128, MTOT / 128);
    for (int i = 0; i < 3; i++)
        gemm_mma<1><<<gg, 256, GSMEM>>>(mA[i], mBseg[i], pbc + i * DMODEL, nullptr,
                                        pqkv + (size_t)(2*i) * QKVPART);

    // 3. attention (fp16 HMMA), writes split AO
    attn_mma<<<dim3(SEQ / QT, BHTOT), 256, ASMEM>>>(
        mQKV[0], mQKV[1], mQKV[2], mQKV[3], mQKV[4], mQKV[5], pao);

    // 4. output projection
    gemm_mma<0><<<gg, 256, GSMEM>>>(mAao, mBo, bia[3], out, nullptr);
}

// round 8
// speedup vs baseline: 3.2669x; 1.0342x over previous
#include <cuda_runtime.h>
#include <cuda.h>
#include <cuda_bf16.h>
#include <cuda_fp16.h>
#include <cstdint>

#define BATCH 2
#define SEQ   2048
#define DMODEL 1024
#define NHEAD 16
#define DHEAD 64
#define MTOT  (BATCH*SEQ)          // 4096
#define BHTOT (BATCH*NHEAD)        // 32
#define QKVPART ((size_t)BHTOT*SEQ*DHEAD)

// 0.125 * log2(e), folded into Wq/bq at preprocessing time.
#define QSCALE 0.1803368801111832f

// ---------------------------------------------------------------------------
// Device scratch
// ---------------------------------------------------------------------------
__device__ __nv_bfloat16 g_act[3u*MTOT*2*DMODEL];    // activations split (hi|lo)
__device__ __nv_bfloat16 g_wt[4u*DMODEL*2*DMODEL];   // W^T split; segs q,k,v,o
__device__ __nv_bfloat16 g_ao[(size_t)MTOT*2*DMODEL];// attention out split
__device__ __half g_qkvs[6*QKVPART];                 // Qh,Ql,Kh,Kl,Vh,Vl (fp16)
__device__ float g_biasc[3*DMODEL];                  // concat bq*QSCALE|bk|bv

// ---------------------------------------------------------------------------
// PTX helpers (legal at virtual arch compute_103)
// ---------------------------------------------------------------------------
__device__ __forceinline__ uint32_t smem_u32(const void* p) {
    uint32_t a;
    asm("{ .reg .u64 t; cvta.to.shared.u64 t, %1; cvt.u32.u64 %0, t; }" : "=r"(a) : "l"(p));
    return a;
}

#define MBARRIER_INIT(addr, cnt) \
    asm volatile("mbarrier.init.shared.b64 [%0], %1;" :: "r"((uint32_t)(addr)), "r"((uint32_t)(cnt)) : "memory")
#define MBARRIER_EXPECT_TX(addr, bytes) \
    asm volatile("mbarrier.arrive.expect_tx.shared.b64 _, [%0], %1;" :: "r"((uint32_t)(addr)), "r"((uint32_t)(bytes)) : "memory")
#define MBARRIER_ARRIVE(addr) \
    asm volatile("mbarrier.arrive.release.cta.shared::cta.b64 _, [%0];" :: "r"((uint32_t)(addr)) : "memory")

#define MBARRIER_WAIT_PARITY(mbar_smem_addr, phase_parity) do { \
    uint32_t _mbar = (uint32_t)(mbar_smem_addr); \
    uint32_t _parity = (uint32_t)(phase_parity); \
    uint32_t _done; \
    asm volatile( \
        "{\n\t.reg .pred p;\n\t" \
        "mbarrier.try_wait.parity.acquire.cta.shared::cta.b64 p, [%1], %2;\n\t" \
        "selp.b32 %0, 1, 0, p;\n\t}" \
        : "=r"(_done) : "r"(_mbar), "r"(_parity) : "memory"); \
    if (!_done) { \
        asm volatile( \
            "{\n\t.reg .pred P1;\n\t" \
            "WAIT_LOOP_%=:\n\t" \
            "mbarrier.try_wait.parity.acquire.cta.shared::cta.b64 P1, [%0], %1, 0x989680;\n\t" \
            "@P1 bra.uni WAIT_DONE_%=;\n\t" \
            "bra.uni WAIT_LOOP_%=;\n\t" \
            "WAIT_DONE_%=:\n\t}" \
            :: "r"(_mbar), "r"(_parity) : "memory"); \
    } \
} while(0)

__device__ __forceinline__ void tma2d(uint32_t dst, const CUtensorMap* m, int x, int y, uint32_t bar) {
    asm volatile(
        "cp.async.bulk.tensor.2d.shared::cta.global.tile.mbarrier::complete_tx::bytes "
        "[%0], [%1, {%2, %3}], [%4];"
        :: "r"(dst), "l"(m), "r"(x), "r"(y), "r"(bar) : "memory");
}

__device__ __forceinline__ void ldsm_x4(uint32_t& r0, uint32_t& r1, uint32_t& r2, uint32_t& r3,
                                        uint32_t addr) {
    asm volatile("ldmatrix.sync.aligned.m8n8.x4.shared.b16 {%0,%1,%2,%3}, [%4];"
                 : "=r"(r0), "=r"(r1), "=r"(r2), "=r"(r3) : "r"(addr));
}
__device__ __forceinline__ void ldsm_x4_t(uint32_t& r0, uint32_t& r1, uint32_t& r2, uint32_t& r3,
                                          uint32_t addr) {
    asm volatile("ldmatrix.sync.aligned.m8n8.x4.trans.shared.b16 {%0,%1,%2,%3}, [%4];"
                 : "=r"(r0), "=r"(r1), "=r"(r2), "=r"(r3) : "r"(addr));
}

// bf16 mma (GEMMs)
__device__ __forceinline__ void mma16816(float* c, const uint32_t* a, uint32_t b0, uint32_t b1) {
    asm volatile(
        "mma.sync.aligned.m16n8k16.row.col.f32.bf16.bf16.f32 "
        "{%0,%1,%2,%3}, {%4,%5,%6,%7}, {%8,%9}, {%0,%1,%2,%3};"
        : "+f"(c[0]), "+f"(c[1]), "+f"(c[2]), "+f"(c[3])
        : "r"(a[0]), "r"(a[1]), "r"(a[2]), "r"(a[3]), "r"(b0), "r"(b1));
}
// fp16 mma (attention)
__device__ __forceinline__ void mma16816h(float* c, const uint32_t* a, uint32_t b0, uint32_t b1) {
    asm volatile(
        "mma.sync.aligned.m16n8k16.row.col.f32.f16.f16.f32 "
        "{%0,%1,%2,%3}, {%4,%5,%6,%7}, {%8,%9}, {%0,%1,%2,%3};"
        : "+f"(c[0]), "+f"(c[1]), "+f"(c[2]), "+f"(c[3])
        : "r"(a[0]), "r"(a[1]), "r"(a[2]), "r"(a[3]), "r"(b0), "r"(b1));
}

__device__ __forceinline__ void split_bf16(float x, __nv_bfloat16& h, __nv_bfloat16& l) {
    h = __float2bfloat16(x);
    l = __float2bfloat16(x - __bfloat162float(h));
}
__device__ __forceinline__ void split_pack2_bf16(float x0, float x1, uint32_t& hp, uint32_t& lp) {
    __nv_bfloat16 h0,l0,h1,l1;
    split_bf16(x0,h0,l0); split_bf16(x1,h1,l1);
    hp = (uint32_t)__bfloat16_as_ushort(h0) | ((uint32_t)__bfloat16_as_ushort(h1) << 16);
    lp = (uint32_t)__bfloat16_as_ushort(l0) | ((uint32_t)__bfloat16_as_ushort(l1) << 16);
}
__device__ __forceinline__ uint32_t pack2_f16(float x0, float x1) {
    uint32_t u;
    asm("cvt.rn.f16x2.f32 %0, %1, %2;" : "=r"(u) : "f"(x1), "f"(x0));
    return u;
}
__device__ __forceinline__ void split_pack2_f16(float x0, float x1, uint32_t& hp, uint32_t& lp) {
    hp = pack2_f16(x0, x1);
    __half2 hh = *reinterpret_cast<__half2*>(&hp);
    lp = pack2_f16(x0 - __low2float(hh), x1 - __high2float(hh));
}
__device__ __forceinline__ float ex2(float x) {
    float y; asm("ex2.approx.f32 %0, %1;" : "=f"(y) : "f"(x)); return y;
}

// smem address for 16B unit `u` of row `r` in a SW128 tile (128B rows)
__device__ __forceinline__ uint32_t ldsm_addr(uint32_t base, int r, int u) {
    return base + (uint32_t)r * 128u + (uint32_t)((u ^ (r & 7)) << 4);
}

// ---------------------------------------------------------------------------
// Fused preprocessing
// ---------------------------------------------------------------------------
__global__ void __launch_bounds__(256)
split_rows_kernel(const float* __restrict__ q, const float* __restrict__ k,
                  const float* __restrict__ v, __nv_bfloat16* __restrict__ dstbase)
{
    const float* x = (blockIdx.y == 0) ? q : (blockIdx.y == 1) ? k : v;
    __nv_bfloat16* dst = dstbase + (size_t)blockIdx.y * MTOT * 2 * DMODEL;
    const int m = blockIdx.x;
    const int k4 = threadIdx.x * 4;
    float4 val = *(const float4*)&x[(size_t)m * DMODEL + k4];
    uint32_t hp0, lp0, hp1, lp1;
    split_pack2_bf16(val.x, val.y, hp0, lp0);
    split_pack2_bf16(val.z, val.w, hp1, lp1);
    __nv_bfloat16* hi = dst + (size_t)m * 2 * DMODEL + k4;
    *(uint32_t*)(hi)          = hp0;
    *(uint32_t*)(hi + 2)      = hp1;
    *(uint32_t*)(hi + DMODEL)     = lp0;
    *(uint32_t*)(hi + DMODEL + 2) = lp1;
}

__global__ void __launch_bounds__(256)
wt_split_kernel(const float* __restrict__ Wq, const float* __restrict__ Wk,
                const float* __restrict__ Wv, const float* __restrict__ Wo,
                __nv_bfloat16* __restrict__ Tbase)
{
    const float* W = (blockIdx.z == 0) ? Wq : (blockIdx.z == 1) ? Wk
                   : (blockIdx.z == 2) ? Wv : Wo;
    const float sc = (blockIdx.z == 0) ? QSCALE : 1.0f;
    __nv_bfloat16* T = Tbase + (size_t)blockIdx.z * DMODEL * 2 * DMODEL;
    __shared__ float t[32][33];
    const int n0 = blockIdx.x * 32, k0 = blockIdx.y * 32;
    const int tx = threadIdx.x, ty = threadIdx.y;   // (32, 8)
#pragma unroll
    for (int i = 0; i < 4; i++)
        t[ty + 8*i][tx] = W[(size_t)(k0 + ty + 8*i) * DMODEL + n0 + tx];
    __syncthreads();
#pragma unroll
    for (int i = 0; i < 4; i++) {
        const int n = n0 + ty + 8*i;
        const int k = k0 + tx;
        float v = t[tx][ty + 8*i] * sc;
        __nv_bfloat16 h, l; split_bf16(v, h, l);
        T[(size_t)n * 2 * DMODEL + k] = h;
        T[(size_t)n * 2 * DMODEL + DMODEL + k] = l;
    }
}

__global__ void __launch_bounds__(256)
bias_concat_kernel(const float* __restrict__ bq, const float* __restrict__ bk,
                   const float* __restrict__ bv, float* __restrict__ dst)
{
    const int i = blockIdx.x * 256 + threadIdx.x;       // 0..3071
    const float* s = (i < 1024) ? bq : (i < 2048) ? bk : bv;
    const float sc = (i < 1024) ? QSCALE : 1.0f;
    dst[i] = s[i & 1023] * sc;
}

// ---------------------------------------------------------------------------
// HMMA GEMM core, 3-term compensated bf16 split, K'=3072, EMPTY-mbarrier
// producer/consumer pipeline (no full-CTA sync in the mainloop).
// MODE 0: row-major fp32 C.  MODE 1: fp16 split scatter to [BH][S][64] hi/lo.
// ---------------------------------------------------------------------------
#define BK       64
#define NCHUNK   48
#define STAGES   3
#define TILEA_SZ 16384
#define TILEB_SZ 16384
#define STAGE_SZ (TILEA_SZ + TILEB_SZ)
#define GSMEM    (1024 + STAGES * STAGE_SZ)

template<int MODE>
__device__ __forceinline__ void gemm_core(
    const CUtensorMap* tmA, const CUtensorMap* tmB,
    const float* __restrict__ bias, float* __restrict__ C,
    __half* __restrict__ qkv, int bm, int bn)
{
    extern __shared__ char sm_raw[];
    const uint32_t sb = smem_u32(sm_raw);
    const uint32_t tiles = (sb + 1024) & ~1023u;
    const int tid = threadIdx.x;
    const int lane = tid & 31, wid = tid >> 5;
    const int wm = wid & 3, wn = wid >> 2;

    const uint32_t FULL = sb;            // 3 x 8B
    const uint32_t EMPTY = sb + 24;      // 3 x 8B

    if (tid == 0) {
#pragma unroll
        for (int s = 0; s < STAGES; s++) {
            MBARRIER_INIT(FULL + 8*s, 1);
            MBARRIER_INIT(EMPTY + 8*s, 256);
        }
    }
    __syncthreads();

    auto coords = [](int c, int& ax, int& bx) {
        const int seg = c >> 4;
        const int kk = (c & 15) * BK;
        ax = (seg == 2) ? DMODEL + kk : kk;
        bx = (seg == 1) ? DMODEL + kk : kk;
    };

    if (tid == 0) {
#pragma unroll
        for (int s = 0; s < STAGES; s++) {
            int ax, bx; coords(s, ax, bx);
            MBARRIER_EXPECT_TX(FULL + 8*s, STAGE_SZ);
            tma2d(tiles + s*STAGE_SZ,            tmA, ax, bm, FULL + 8*s);
            tma2d(tiles + s*STAGE_SZ + TILEA_SZ, tmB, bx, bn, FULL + 8*s);
        }
    }

    float acc[2][8][4];
#pragma unroll
    for (int i = 0; i < 2; i++)
#pragma unroll
        for (int j = 0; j < 8; j++)
#pragma unroll
            for (int q = 0; q < 4; q++) acc[i][j][q] = 0.f;

    const int lrow = lane & 15;
    const int lcolhalf = lane >> 4;
    const int sw = lane & 7;

    for (int c = 0; c < NCHUNK; c++) {
        const int s = c % STAGES;
        const int ph = (c / STAGES) & 1;
        MBARRIER_WAIT_PARITY(FULL + 8*s, ph);

        const uint32_t As = tiles + s*STAGE_SZ;
        const uint32_t Bs = As + TILEA_SZ;

#pragma unroll
        for (int kk = 0; kk < 4; kk++) {
            const int cidx = 2*kk + lcolhalf;
            const uint32_t coff = (uint32_t)((cidx ^ sw) << 4);

            uint32_t a[2][4];
#pragma unroll
            for (int mi = 0; mi < 2; mi++) {
                const int r = wm*32 + mi*16 + lrow;
                ldsm_x4(a[mi][0], a[mi][1], a[mi][2], a[mi][3],
                        As + (uint32_t)r*128 + coff);
            }
            uint32_t b[4][4];
#pragma unroll
            for (int ni = 0; ni < 4; ni++) {
                const int r = wn*64 + ni*16 + lrow;
                ldsm_x4(b[ni][0], b[ni][1], b[ni][2], b[ni][3],
                        Bs + (uint32_t)r*128 + coff);
            }
#pragma unroll
            for (int mi = 0; mi < 2; mi++)
#pragma unroll
                for (int ni = 0; ni < 4; ni++) {
                    mma16816(acc[mi][2*ni+0], a[mi], b[ni][0], b[ni][2]);
                    mma16816(acc[mi][2*ni+1], a[mi], b[ni][1], b[ni][3]);
                }
        }
        // consumer release: every thread arrives; only tid0 waits before reissue
        MBARRIER_ARRIVE(EMPTY + 8*s);
        if (tid == 0 && c + STAGES < NCHUNK) {
            MBARRIER_WAIT_PARITY(EMPTY + 8*s, ph);
            int ax, bx; coords(c + STAGES, ax, bx);
            MBARRIER_EXPECT_TX(FULL + 8*s, STAGE_SZ);
            tma2d(As, tmA, ax, bm, FULL + 8*s);
            tma2d(Bs, tmB, bx, bn, FULL + 8*s);
        }
    }

    const int grp = lane >> 2;
    const int qd  = lane & 3;
#pragma unroll
    for (int mi = 0; mi < 2; mi++) {
#pragma unroll
        for (int nj = 0; nj < 8; nj++) {
            const int col = bn + wn*64 + nj*8 + qd*2;
            const float b0 = __ldg(&bias[col]);
            const float b1 = __ldg(&bias[col + 1]);
#pragma unroll
            for (int half = 0; half < 2; half++) {
                const int m = bm + wm*32 + mi*16 + grp + half*8;
                const float v0 = acc[mi][nj][2*half+0] + b0;
                const float v1 = acc[mi][nj][2*half+1] + b1;
                if (MODE == 0) {
                    *(float2*)&C[(size_t)m * DMODEL + col] = make_float2(v0, v1);
                } else {
                    const int b = m >> 11, srow = m & 2047;
                    const int h = col >> 6, d = col & 63;
                    const size_t off = (((size_t)b * NHEAD + h) * SEQ + srow) * DHEAD + d;
                    uint32_t hp, lp;
                    split_pack2_f16(v0, v1, hp, lp);
                    *(uint32_t*)&qkv[off]            = hp;
                    *(uint32_t*)&qkv[off + QKVPART]  = lp;
                }
            }
        }
    }
}

// Fused QKV: grid.z in {0,1,2} selects {A map, B seg, bias seg, output part}.
struct QkvMaps { CUtensorMap a[3]; CUtensorMap b[3]; };

__global__ void __launch_bounds__(256, 2)
gemm_qkv(const __grid_constant__ QkvMaps maps,
         const float* __restrict__ biasc, __half* __restrict__ qkvbase)
{
    const int i = blockIdx.z;
    gemm_core<1>(&maps.a[i], &maps.b[i], biasc + i * DMODEL, nullptr,
                 qkvbase + (size_t)(2*i) * QKVPART,
                 blockIdx.y * 128, blockIdx.x * 128);
}

__global__ void __launch_bounds__(256, 2)
gemm_out(const __grid_constant__ CUtensorMap tmA,
         const __grid_constant__ CUtensorMap tmB,
         const float* __restrict__ bias, float* __restrict__ C)
{
    gemm_core<0>(&tmA, &tmB, bias, C, nullptr, blockIdx.y * 128, blockIdx.x * 128);
}

// ---------------------------------------------------------------------------
// Flash attention on fp16 HMMA. QK: 3-product split; PV: 2-product (P≈Ph).
// exp2-domain softmax. EMPTY-mbarrier KV pipeline (no full-CTA sync in loop).
// ---------------------------------------------------------------------------
#define QT 128
#define KT 64
#define AT_TILEQ  16384
#define AT_TILEKV 8192
#define AT_STAGE  (4*AT_TILEKV)
#define ASMEM (1024 + 2*AT_TILEQ + 2*AT_STAGE)

__global__ void __launch_bounds__(256)
attn_mma(const __grid_constant__ CUtensorMap tmQh, const __grid_constant__ CUtensorMap tmQl,
         const __grid_constant__ CUtensorMap tmKh, const __grid_constant__ CUtensorMap tmKl,
         const __grid_constant__ CUtensorMap tmVh, const __grid_constant__ CUtensorMap tmVl,
         __nv_bfloat16* __restrict__ AO)
{
    extern __shared__ char smraw[];
    const uint32_t sb = smem_u32(smraw);
    const uint32_t tiles = (sb + 1024) & ~1023u;
    const uint32_t QHs = tiles, QLs = tiles + AT_TILEQ;
    const uint32_t STG = tiles + 2*AT_TILEQ;
    const int tid = threadIdx.x, lane = tid & 31, wid = tid >> 5;
    const int bh = blockIdx.y;
    const int q0 = blockIdx.x * QT;
    const int gy = bh * SEQ;

    const uint32_t BQ = sb, BF = sb + 8, BE = sb + 24;  // BF[2], BE[2]
    if (tid == 0) {
        MBARRIER_INIT(BQ, 1);
        MBARRIER_INIT(BF + 0, 1);
        MBARRIER_INIT(BF + 8, 1);
        MBARRIER_INIT(BE + 0, 256);
        MBARRIER_INIT(BE + 8, 256);
    }
    __syncthreads();
    if (tid == 0) {
        MBARRIER_EXPECT_TX(BQ, 2*AT_TILEQ);
        tma2d(QHs, &tmQh, 0, gy + q0, BQ);
        tma2d(QLs, &tmQl, 0, gy + q0, BQ);
#pragma unroll
        for (int s = 0; s < 2; s++) {
            const uint32_t st = STG + s*AT_STAGE;
            MBARRIER_EXPECT_TX(BF + 8*s, AT_STAGE);
            tma2d(st,                &tmKh, 0, gy + s*KT, BF + 8*s);
            tma2d(st +   AT_TILEKV,  &tmKl, 0, gy + s*KT, BF + 8*s);
            tma2d(st + 2*AT_TILEKV,  &tmVh, 0, gy + s*KT, BF + 8*s);
            tma2d(st + 3*AT_TILEKV,  &tmVl, 0, gy + s*KT, BF + 8*s);
        }
    }

    float m_run[2] = { -1e30f, -1e30f };
    float l_run[2] = { 0.f, 0.f };
    float o_acc[8][4];
#pragma unroll
    for (int i = 0; i < 8; i++)
#pragma unroll
        for (int j = 0; j < 4; j++) o_acc[i][j] = 0.f;

    MBARRIER_WAIT_PARITY(BQ, 0);

    const int r0q = wid * 16;
    const int la7 = lane & 7;
    const int g01 = (lane >> 3) & 1;
    const int g23 = lane >> 4;

    for (int kt = 0; kt < SEQ / KT; kt++) {
        const int s = kt & 1, ph = (kt >> 1) & 1;
        MBARRIER_WAIT_PARITY(BF + 8*s, ph);
        const uint32_t Kh = STG + s*AT_STAGE;
        const uint32_t Kl = Kh + AT_TILEKV;
        const uint32_t Vh = Kh + 2*AT_TILEKV;
        const uint32_t Vl = Kh + 3*AT_TILEKV;

        float sf[8][4];
#pragma unroll
        for (int i = 0; i < 8; i++)
#pragma unroll
            for (int j = 0; j < 4; j++) sf[i][j] = 0.f;

        // ---- S = Q K^T, fp16 3-product ----
#pragma unroll
        for (int j = 0; j < 4; j++) {
            uint32_t qh[4], ql[4];
            {
                const int rr = r0q + la7 + g01*8;
                const int uu = 2*j + g23;
                ldsm_x4(qh[0],qh[1],qh[2],qh[3], ldsm_addr(QHs, rr, uu));
                ldsm_x4(ql[0],ql[1],ql[2],ql[3], ldsm_addr(QLs, rr, uu));
            }
#pragma unroll
            for (int np = 0; np < 4; np++) {
                const int rr = np*16 + la7 + g23*8;
                const int uu = 2*j + g01;
                uint32_t k0,k1,k2,k3, m0,m1,m2,m3;
                ldsm_x4(k0,k1,k2,k3, ldsm_addr(Kh, rr, uu));
                ldsm_x4(m0,m1,m2,m3, ldsm_addr(Kl, rr, uu));
                mma16816h(sf[2*np+0], qh, k0, k1);
                mma16816h(sf[2*np+1], qh, k2, k3);
                mma16816h(sf[2*np+0], qh, m0, m1);
                mma16816h(sf[2*np+1], qh, m2, m3);
                mma16816h(sf[2*np+0], ql, k0, k1);
                mma16816h(sf[2*np+1], ql, k2, k3);
            }
        }

        // ---- online softmax in exp2 domain ----
#pragma unroll
        for (int hf = 0; hf < 2; hf++) {
            float mx = -1e30f;
#pragma unroll
            for (int nt = 0; nt < 8; nt++)
                mx = fmaxf(mx, fmaxf(sf[nt][2*hf], sf[nt][2*hf+1]));
            mx = fmaxf(mx, __shfl_xor_sync(0xffffffffu, mx, 1));
            mx = fmaxf(mx, __shfl_xor_sync(0xffffffffu, mx, 2));
            const float mnew = fmaxf(m_run[hf], mx);
            const float corr = ex2(m_run[hf] - mnew);
            float sum = 0.f;
#pragma unroll
            for (int nt = 0; nt < 8; nt++) {
                const float p0 = ex2(sf[nt][2*hf]   - mnew);
                const float p1 = ex2(sf[nt][2*hf+1] - mnew);
                sf[nt][2*hf] = p0; sf[nt][2*hf+1] = p1;
                sum += p0 + p1;
            }
            sum += __shfl_xor_sync(0xffffffffu, sum, 1);
            sum += __shfl_xor_sync(0xffffffffu, sum, 2);
            l_run[hf] = l_run[hf] * corr + sum;
            m_run[hf] = mnew;
#pragma unroll
            for (int nt = 0; nt < 8; nt++) {
                o_acc[nt][2*hf]   *= corr;
                o_acc[nt][2*hf+1] *= corr;
            }
        }

        // ---- O += P V, fp16 2-product (P = Ph only; V split) ----
#pragma unroll
        for (int j = 0; j < 4; j++) {
            uint32_t ph16[4];
#pragma unroll
            for (int t = 0; t < 4; t++) {
                const int nt = 2*j + (t >> 1);
                const int vv = (t & 1) * 2;
                ph16[t] = pack2_f16(sf[nt][vv+0], sf[nt][vv+1]);
            }
#pragma unroll
            for (int np = 0; np < 4; np++) {
                const int rr = 16*j + la7 + g01*8;
                const int uu = 2*np + g23;
                uint32_t v0,v1,v2,v3, w0,w1,w2,w3;
                ldsm_x4_t(v0,v1,v2,v3, ldsm_addr(Vh, rr, uu));
                ldsm_x4_t(w0,w1,w2,w3, ldsm_addr(Vl, rr, uu));
                mma16816h(o_acc[2*np+0], ph16, v0, v1);
                mma16816h(o_acc[2*np+1], ph16, v2, v3);
                mma16816h(o_acc[2*np+0], ph16, w0, w1);
                mma16816h(o_acc[2*np+1], ph16, w2, w3);
            }
        }

        // consumer release + producer-only wait
        MBARRIER_ARRIVE(BE + 8*s);
        if (tid == 0 && kt + 2 < SEQ / KT) {
            MBARRIER_WAIT_PARITY(BE + 8*s, ph);
            const uint32_t st = STG + s*AT_STAGE;
            MBARRIER_EXPECT_TX(BF + 8*s, AT_STAGE);
            tma2d(st,               &tmKh, 0, gy + (kt+2)*KT, BF + 8*s);
            tma2d(st +   AT_TILEKV, &tmKl, 0, gy + (kt+2)*KT, BF + 8*s);
            tma2d(st + 2*AT_TILEKV, &tmVh, 0, gy + (kt+2)*KT, BF + 8*s);
            tma2d(st + 3*AT_TILEKV, &tmVl, 0, gy + (kt+2)*KT, BF + 8*s);
        }
    }

    // ---- epilogue: AO split bf16 [m][2048] ----
    const int b = bh >> 4, h = bh & 15;
#pragma unroll
    for (int hf = 0; hf < 2; hf++) {
        const float inv = 1.f / l_run[hf];
        const int srow = q0 + r0q + (lane >> 2) + hf*8;
#pragma unroll
        for (int nt = 0; nt < 8; nt++) {
            const int d = nt*8 + (lane & 3)*2;
            const float f0 = o_acc[nt][2*hf]   * inv;
            const float f1 = o_acc[nt][2*hf+1] * inv;
            uint32_t hp, lp;
            split_pack2_bf16(f0, f1, hp, lp);
            const size_t base = ((size_t)b * SEQ + srow) * 2 * DMODEL + h * DHEAD + d;
            *(uint32_t*)&AO[base]          = hp;
            *(uint32_t*)&AO[base + DMODEL] = lp;
        }
    }
}

// ---------------------------------------------------------------------------
// Host
// ---------------------------------------------------------------------------
typedef CUresult (*PFN_tmEncode)(CUtensorMap*, CUtensorMapDataType, cuuint32_t, void*,
                                 const cuuint64_t*, const cuuint64_t*, const cuuint32_t*,
                                 const cuuint32_t*, CUtensorMapInterleave, CUtensorMapSwizzle,
                                 CUtensorMapL2promotion, CUtensorMapFloatOOBfill);

static void make_map(PFN_tmEncode enc, CUtensorMap* m, void* p, uint64_t rows,
                     uint64_t width, uint32_t b0, uint32_t b1, CUtensorMapDataType dt)
{
    cuuint64_t dims[2]    = { width, rows };
    cuuint64_t strides[1] = { width * 2 };
    cuuint32_t box[2]     = { b0, b1 };
    cuuint32_t es[2]      = { 1, 1 };
    enc(m, dt, 2, p, dims, strides, box, es,
        CU_TENSOR_MAP_INTERLEAVE_NONE, CU_TENSOR_MAP_SWIZZLE_128B,
        CU_TENSOR_MAP_L2_PROMOTION_L2_128B, CU_TENSOR_MAP_FLOAT_OOB_FILL_NONE);
}

extern "C" void kernel_launch(void* const* d_in, const int* in_sizes, int n_in,
                              void* d_out, int out_size)
{
    const float* act[3] = { (const float*)d_in[0], (const float*)d_in[1], (const float*)d_in[2] };
    const float* W[4]   = { (const float*)d_in[3], (const float*)d_in[5], (const float*)d_in[7], (const float*)d_in[9] };
    const float* bia[4] = { (const float*)d_in[4], (const float*)d_in[6], (const float*)d_in[8], (const float*)d_in[10] };
    float* out = (float*)d_out;

    __nv_bfloat16 *pact, *pwt, *pao;
    __half* pqkv;
    float* pbc;
    cudaGetSymbolAddress((void**)&pact, g_act);
    cudaGetSymbolAddress((void**)&pwt,  g_wt);
    cudaGetSymbolAddress((void**)&pao,  g_ao);
    cudaGetSymbolAddress((void**)&pqkv, g_qkvs);
    cudaGetSymbolAddress((void**)&pbc,  g_biasc);

    PFN_tmEncode enc = nullptr;
    cudaDriverEntryPointQueryResult qr;
    cudaGetDriverEntryPointByVersion("cuTensorMapEncodeTiled", (void**)&enc, 12000,
                                     cudaEnableDefault, &qr);

    const size_t WM2 = (size_t)DMODEL * 2 * DMODEL;

    static QkvMaps qkvmaps;
    static CUtensorMap mAao, mBo, mQKV[6];
    const CUtensorMapDataType BF = CU_TENSOR_MAP_DATA_TYPE_BFLOAT16;
    const CUtensorMapDataType F16 = CU_TENSOR_MAP_DATA_TYPE_FLOAT16;
    for (int i = 0; i < 3; i++) {
        make_map(enc, &qkvmaps.a[i], pact + (size_t)i * MTOT * 2 * DMODEL, MTOT, 2*DMODEL, BK, 128, BF);
        make_map(enc, &qkvmaps.b[i], pwt + (size_t)i * WM2, DMODEL, 2*DMODEL, BK, 128, BF);
    }
    make_map(enc, &mAao, pao, MTOT, 2*DMODEL, BK, 128, BF);
    make_map(enc, &mBo, pwt + 3*WM2, DMODEL, 2*DMODEL, BK, 128, BF);
    for (int i = 0; i < 6; i++)
        make_map(enc, &mQKV[i], pqkv + i * QKVPART, (uint64_t)BHTOT * SEQ, DHEAD,
                 DHEAD, (i < 2) ? QT : KT, F16);

    cudaFuncSetAttribute(gemm_qkv, cudaFuncAttributeMaxDynamicSharedMemorySize, GSMEM);
    cudaFuncSetAttribute(gemm_out, cudaFuncAttributeMaxDynamicSharedMemorySize, GSMEM);
    cudaFuncSetAttribute(attn_mma, cudaFuncAttributeMaxDynamicSharedMemorySize, ASMEM);

    // 1. fused preprocessing
    split_rows_kernel<<<dim3(MTOT, 3), 256>>>(act[0], act[1], act[2], pact);
    wt_split_kernel<<<dim3(32, 32, 4), dim3(32, 8)>>>(W[0], W[1], W[2], W[3], pwt);
    bias_concat_kernel<<<12, 256>>>(bia[0], bia[1], bia[2], pbc);

    // 2. fused QKV projections (one launch, 768 CTAs) -> fp16 split QKV
    gemm_qkv<<<dim3(DMODEL/128, MTOT/128, 3), 256, GSMEM>>>(qkvmaps, pbc, pqkv);

    // 3. attention (fp16 HMMA), writes split AO
    attn_mma<<<dim3(SEQ / QT, BHTOT), 256, ASMEM>>>(
        mQKV[0], mQKV[1], mQKV[2], mQKV[3], mQKV[4], mQKV[5], pao);

    // 4. output projection
    gemm_out<<<dim3(DMODEL/128, MTOT/128), 256, GSMEM>>>(mAao, mBo, bia[3], out);
}

// round 9
// speedup vs baseline: 4.3022x; 1.3169x over previous
#include <cuda_runtime.h>
#include <cuda.h>
#include <cuda_bf16.h>
#include <cuda_fp16.h>
#include <cstdint>

#define BATCH 2
#define SEQ   2048
#define DMODEL 1024
#define NHEAD 16
#define DHEAD 64
#define MTOT  (BATCH*SEQ)          // 4096
#define BHTOT (BATCH*NHEAD)        // 32
#define QKVPART ((size_t)BHTOT*SEQ*DHEAD)

// 0.125 * log2(e), folded into Wq/bq at preprocessing time.
#define QSCALE 0.1803368801111832f

// ---------------------------------------------------------------------------
// Device scratch (all fp16 now)
// ---------------------------------------------------------------------------
__device__ __half g_act[3u*MTOT*2*DMODEL];   // activations split (hi|lo)
__device__ __half g_wt[4u*DMODEL*DMODEL];    // W^T fp16 hi only; segs q,k,v,o
__device__ __half g_ao[(size_t)MTOT*2*DMODEL]; // attention out split (hi|lo)
__device__ __half g_qkvs[5*QKVPART];         // Qh,Ql,Kh,Vh,Vl [BH][S][64]
__device__ float g_biasc[3*DMODEL];          // concat bq*QSCALE|bk|bv

// ---------------------------------------------------------------------------
// PTX helpers (legal at virtual arch compute_103)
// ---------------------------------------------------------------------------
__device__ __forceinline__ uint32_t smem_u32(const void* p) {
    uint32_t a;
    asm("{ .reg .u64 t; cvta.to.shared.u64 t, %1; cvt.u32.u64 %0, t; }" : "=r"(a) : "l"(p));
    return a;
}

#define MBARRIER_INIT(addr, cnt) \
    asm volatile("mbarrier.init.shared.b64 [%0], %1;" :: "r"((uint32_t)(addr)), "r"((uint32_t)(cnt)) : "memory")
#define MBARRIER_EXPECT_TX(addr, bytes) \
    asm volatile("mbarrier.arrive.expect_tx.shared.b64 _, [%0], %1;" :: "r"((uint32_t)(addr)), "r"((uint32_t)(bytes)) : "memory")
#define MBARRIER_ARRIVE(addr) \
    asm volatile("mbarrier.arrive.release.cta.shared::cta.b64 _, [%0];" :: "r"((uint32_t)(addr)) : "memory")

#define MBARRIER_WAIT_PARITY(mbar_smem_addr, phase_parity) do { \
    uint32_t _mbar = (uint32_t)(mbar_smem_addr); \
    uint32_t _parity = (uint32_t)(phase_parity); \
    uint32_t _done; \
    asm volatile( \
        "{\n\t.reg .pred p;\n\t" \
        "mbarrier.try_wait.parity.acquire.cta.shared::cta.b64 p, [%1], %2;\n\t" \
        "selp.b32 %0, 1, 0, p;\n\t}" \
        : "=r"(_done) : "r"(_mbar), "r"(_parity) : "memory"); \
    if (!_done) { \
        asm volatile( \
            "{\n\t.reg .pred P1;\n\t" \
            "WAIT_LOOP_%=:\n\t" \
            "mbarrier.try_wait.parity.acquire.cta.shared::cta.b64 P1, [%0], %1, 0x989680;\n\t" \
            "@P1 bra.uni WAIT_DONE_%=;\n\t" \
            "bra.uni WAIT_LOOP_%=;\n\t" \
            "WAIT_DONE_%=:\n\t}" \
            :: "r"(_mbar), "r"(_parity) : "memory"); \
    } \
} while(0)

__device__ __forceinline__ void tma2d(uint32_t dst, const CUtensorMap* m, int x, int y, uint32_t bar) {
    asm volatile(
        "cp.async.bulk.tensor.2d.shared::cta.global.tile.mbarrier::complete_tx::bytes "
        "[%0], [%1, {%2, %3}], [%4];"
        :: "r"(dst), "l"(m), "r"(x), "r"(y), "r"(bar) : "memory");
}

__device__ __forceinline__ void ldsm_x4(uint32_t& r0, uint32_t& r1, uint32_t& r2, uint32_t& r3,
                                        uint32_t addr) {
    asm volatile("ldmatrix.sync.aligned.m8n8.x4.shared.b16 {%0,%1,%2,%3}, [%4];"
                 : "=r"(r0), "=r"(r1), "=r"(r2), "=r"(r3) : "r"(addr));
}
__device__ __forceinline__ void ldsm_x4_t(uint32_t& r0, uint32_t& r1, uint32_t& r2, uint32_t& r3,
                                          uint32_t addr) {
    asm volatile("ldmatrix.sync.aligned.m8n8.x4.trans.shared.b16 {%0,%1,%2,%3}, [%4];"
                 : "=r"(r0), "=r"(r1), "=r"(r2), "=r"(r3) : "r"(addr));
}

// fp16 mma, fp32 accum
__device__ __forceinline__ void mma16816h(float* c, const uint32_t* a, uint32_t b0, uint32_t b1) {
    asm volatile(
        "mma.sync.aligned.m16n8k16.row.col.f32.f16.f16.f32 "
        "{%0,%1,%2,%3}, {%4,%5,%6,%7}, {%8,%9}, {%0,%1,%2,%3};"
        : "+f"(c[0]), "+f"(c[1]), "+f"(c[2]), "+f"(c[3])
        : "r"(a[0]), "r"(a[1]), "r"(a[2]), "r"(a[3]), "r"(b0), "r"(b1));
}

__device__ __forceinline__ uint32_t pack2_f16(float x0, float x1) {
    uint32_t u;
    asm("cvt.rn.f16x2.f32 %0, %1, %2;" : "=r"(u) : "f"(x1), "f"(x0));
    return u;
}
__device__ __forceinline__ void split_pack2_f16(float x0, float x1, uint32_t& hp, uint32_t& lp) {
    hp = pack2_f16(x0, x1);
    __half2 hh = *reinterpret_cast<__half2*>(&hp);
    lp = pack2_f16(x0 - __low2float(hh), x1 - __high2float(hh));
}
__device__ __forceinline__ float ex2(float x) {
    float y; asm("ex2.approx.f32 %0, %1;" : "=f"(y) : "f"(x)); return y;
}

// smem address for 16B unit `u` of row `r` in a SW128 tile (128B rows)
__device__ __forceinline__ uint32_t ldsm_addr(uint32_t base, int r, int u) {
    return base + (uint32_t)r * 128u + (uint32_t)((u ^ (r & 7)) << 4);
}

// ---------------------------------------------------------------------------
// Fused preprocessing
// ---------------------------------------------------------------------------
__global__ void __launch_bounds__(256)
split_rows_kernel(const float* __restrict__ q, const float* __restrict__ k,
                  const float* __restrict__ v, __half* __restrict__ dstbase)
{
    const float* x = (blockIdx.y == 0) ? q : (blockIdx.y == 1) ? k : v;
    __half* dst = dstbase + (size_t)blockIdx.y * MTOT * 2 * DMODEL;
    const int m = blockIdx.x;
    const int k4 = threadIdx.x * 4;
    float4 val = *(const float4*)&x[(size_t)m * DMODEL + k4];
    uint32_t hp0, lp0, hp1, lp1;
    split_pack2_f16(val.x, val.y, hp0, lp0);
    split_pack2_f16(val.z, val.w, hp1, lp1);
    __half* hi = dst + (size_t)m * 2 * DMODEL + k4;
    *(uint32_t*)(hi)          = hp0;
    *(uint32_t*)(hi + 2)      = hp1;
    *(uint32_t*)(hi + DMODEL)     = lp0;
    *(uint32_t*)(hi + DMODEL + 2) = lp1;
}

__global__ void __launch_bounds__(256)
wt_split_kernel(const float* __restrict__ Wq, const float* __restrict__ Wk,
                const float* __restrict__ Wv, const float* __restrict__ Wo,
                __half* __restrict__ Tbase)
{
    const float* W = (blockIdx.z == 0) ? Wq : (blockIdx.z == 1) ? Wk
                   : (blockIdx.z == 2) ? Wv : Wo;
    const float sc = (blockIdx.z == 0) ? QSCALE : 1.0f;
    __half* T = Tbase + (size_t)blockIdx.z * DMODEL * DMODEL;
    __shared__ float t[32][33];
    const int n0 = blockIdx.x * 32, k0 = blockIdx.y * 32;
    const int tx = threadIdx.x, ty = threadIdx.y;   // (32, 8)
#pragma unroll
    for (int i = 0; i < 4; i++)
        t[ty + 8*i][tx] = W[(size_t)(k0 + ty + 8*i) * DMODEL + n0 + tx];
    __syncthreads();
#pragma unroll
    for (int i = 0; i < 4; i++) {
        const int n = n0 + ty + 8*i;
        const int k = k0 + tx;
        T[(size_t)n * DMODEL + k] = __float2half(t[tx][ty + 8*i] * sc);
    }
}

__global__ void __launch_bounds__(256)
bias_concat_kernel(const float* __restrict__ bq, const float* __restrict__ bk,
                   const float* __restrict__ bv, float* __restrict__ dst)
{
    const int i = blockIdx.x * 256 + threadIdx.x;       // 0..3071
    const float* s = (i < 1024) ? bq : (i < 2048) ? bk : bv;
    const float sc = (i < 1024) ? QSCALE : 1.0f;
    dst[i] = s[i & 1023] * sc;
}

// ---------------------------------------------------------------------------
// fp16 HMMA GEMM core, 2-product split (Ah*Bh + Al*Bh), K=1024.
// Per chunk: one B tile shared by Ah and Al passes (halved B ldsm + TMA).
// MODE 0: row-major fp32 C.  MODE 1: fp16 scatter to [BH][S][64], hi + opt lo.
// ---------------------------------------------------------------------------
#define BK       64
#define NCHUNK   16
#define GTILE    16384              // 128 rows x 128B (one 64-col fp16 tile)
#define GSTAGE   (3*GTILE)          // Ah, Al, B
#define GSMEM    (1024 + 2*GSTAGE)

template<int MODE>
__device__ __forceinline__ void gemm_core(
    const CUtensorMap* tmA, const CUtensorMap* tmB,
    const float* __restrict__ bias, float* __restrict__ C,
    __half* __restrict__ Ohi, __half* __restrict__ Olo, int bm, int bn)
{
    extern __shared__ char sm_raw[];
    const uint32_t sb = smem_u32(sm_raw);
    const uint32_t tiles = (sb + 1024) & ~1023u;
    const int tid = threadIdx.x;
    const int lane = tid & 31, wid = tid >> 5;
    const int wm = wid & 3, wn = wid >> 2;

    const uint32_t FULL = sb;            // 2 x 8B
    const uint32_t EMPTY = sb + 16;      // 2 x 8B

    if (tid == 0) {
#pragma unroll
        for (int s = 0; s < 2; s++) {
            MBARRIER_INIT(FULL + 8*s, 1);
            MBARRIER_INIT(EMPTY + 8*s, 256);
        }
    }
    __syncthreads();

    if (tid == 0) {
#pragma unroll
        for (int s = 0; s < 2; s++) {
            MBARRIER_EXPECT_TX(FULL + 8*s, GSTAGE);
            tma2d(tiles + s*GSTAGE,           tmA, s*BK,          bm, FULL + 8*s);
            tma2d(tiles + s*GSTAGE + GTILE,   tmA, DMODEL + s*BK, bm, FULL + 8*s);
            tma2d(tiles + s*GSTAGE + 2*GTILE, tmB, s*BK,          bn, FULL + 8*s);
        }
    }

    float acc[2][8][4];
#pragma unroll
    for (int i = 0; i < 2; i++)
#pragma unroll
        for (int j = 0; j < 8; j++)
#pragma unroll
            for (int q = 0; q < 4; q++) acc[i][j][q] = 0.f;

    const int lrow = lane & 15;
    const int lcolhalf = lane >> 4;
    const int sw = lane & 7;

    for (int c = 0; c < NCHUNK; c++) {
        const int s = c & 1, ph = (c >> 1) & 1;
        MBARRIER_WAIT_PARITY(FULL + 8*s, ph);

        const uint32_t Ah = tiles + s*GSTAGE;
        const uint32_t Al = Ah + GTILE;
        const uint32_t Bs = Ah + 2*GTILE;

#pragma unroll
        for (int kk = 0; kk < 4; kk++) {
            const int cidx = 2*kk + lcolhalf;
            const uint32_t coff = (uint32_t)((cidx ^ sw) << 4);

            uint32_t ah[2][4], al[2][4];
#pragma unroll
            for (int mi = 0; mi < 2; mi++) {
                const int r = wm*32 + mi*16 + lrow;
                ldsm_x4(ah[mi][0], ah[mi][1], ah[mi][2], ah[mi][3],
                        Ah + (uint32_t)r*128 + coff);
                ldsm_x4(al[mi][0], al[mi][1], al[mi][2], al[mi][3],
                        Al + (uint32_t)r*128 + coff);
            }
            uint32_t b[4][4];
#pragma unroll
            for (int ni = 0; ni < 4; ni++) {
                const int r = wn*64 + ni*16 + lrow;
                ldsm_x4(b[ni][0], b[ni][1], b[ni][2], b[ni][3],
                        Bs + (uint32_t)r*128 + coff);
            }
#pragma unroll
            for (int mi = 0; mi < 2; mi++)
#pragma unroll
                for (int ni = 0; ni < 4; ni++) {
                    mma16816h(acc[mi][2*ni+0], ah[mi], b[ni][0], b[ni][2]);
                    mma16816h(acc[mi][2*ni+1], ah[mi], b[ni][1], b[ni][3]);
                    mma16816h(acc[mi][2*ni+0], al[mi], b[ni][0], b[ni][2]);
                    mma16816h(acc[mi][2*ni+1], al[mi], b[ni][1], b[ni][3]);
                }
        }
        MBARRIER_ARRIVE(EMPTY + 8*s);
        if (tid == 0 && c + 2 < NCHUNK) {
            MBARRIER_WAIT_PARITY(EMPTY + 8*s, ph);
            MBARRIER_EXPECT_TX(FULL + 8*s, GSTAGE);
            const int kx = (c + 2) * BK;
            tma2d(Ah, tmA, kx,          bm, FULL + 8*s);
            tma2d(Al, tmA, DMODEL + kx, bm, FULL + 8*s);
            tma2d(Bs, tmB, kx,          bn, FULL + 8*s);
        }
    }

    const int grp = lane >> 2;
    const int qd  = lane & 3;
#pragma unroll
    for (int mi = 0; mi < 2; mi++) {
#pragma unroll
        for (int nj = 0; nj < 8; nj++) {
            const int col = bn + wn*64 + nj*8 + qd*2;
            const float b0 = __ldg(&bias[col]);
            const float b1 = __ldg(&bias[col + 1]);
#pragma unroll
            for (int half = 0; half < 2; half++) {
                const int m = bm + wm*32 + mi*16 + grp + half*8;
                const float v0 = acc[mi][nj][2*half+0] + b0;
                const float v1 = acc[mi][nj][2*half+1] + b1;
                if (MODE == 0) {
                    *(float2*)&C[(size_t)m * DMODEL + col] = make_float2(v0, v1);
                } else {
                    const int b = m >> 11, srow = m & 2047;
                    const int h = col >> 6, d = col & 63;
                    const size_t off = (((size_t)b * NHEAD + h) * SEQ + srow) * DHEAD + d;
                    const uint32_t hp = pack2_f16(v0, v1);
                    *(uint32_t*)&Ohi[off] = hp;
                    if (Olo != nullptr) {
                        __half2 hh = *reinterpret_cast<const __half2*>(&hp);
                        const uint32_t lp = pack2_f16(v0 - __low2float(hh),
                                                      v1 - __high2float(hh));
                        *(uint32_t*)&Olo[off] = lp;
                    }
                }
            }
        }
    }
}

// Fused QKV: grid.z selects tensor. Q -> hi+lo, K -> hi only, V -> hi+lo.
struct QkvMaps { CUtensorMap a[3]; CUtensorMap b[3]; };

__global__ void __launch_bounds__(256, 2)
gemm_qkv(const __grid_constant__ QkvMaps maps,
         const float* __restrict__ biasc, __half* __restrict__ qkvbase)
{
    const int i = blockIdx.z;
    __half* hi; __half* lo;
    if (i == 0)      { hi = qkvbase;               lo = qkvbase + QKVPART; }
    else if (i == 1) { hi = qkvbase + 2*QKVPART;   lo = nullptr; }
    else             { hi = qkvbase + 3*QKVPART;   lo = qkvbase + 4*QKVPART; }
    gemm_core<1>(&maps.a[i], &maps.b[i], biasc + i * DMODEL, nullptr, hi, lo,
                 blockIdx.y * 128, blockIdx.x * 128);
}

__global__ void __launch_bounds__(256, 2)
gemm_out(const __grid_constant__ CUtensorMap tmA,
         const __grid_constant__ CUtensorMap tmB,
         const float* __restrict__ bias, float* __restrict__ C)
{
    gemm_core<0>(&tmA, &tmB, bias, C, nullptr, nullptr,
                 blockIdx.y * 128, blockIdx.x * 128);
}

// ---------------------------------------------------------------------------
// Flash attention, fp16 HMMA. QK: 2-product (Qh,Ql vs Kh); PV: 2-product
// (Ph vs Vh,Vl). exp2-domain softmax. EMPTY-mbarrier KV pipeline.
// ---------------------------------------------------------------------------
#define QT 128
#define KT 64
#define AT_TILEQ  16384
#define AT_TILEKV 8192
#define AT_STAGE  (3*AT_TILEKV)      // Kh, Vh, Vl
#define ASMEM (1024 + 2*AT_TILEQ + 2*AT_STAGE)

__global__ void __launch_bounds__(256)
attn_mma(const __grid_constant__ CUtensorMap tmQh, const __grid_constant__ CUtensorMap tmQl,
         const __grid_constant__ CUtensorMap tmKh,
         const __grid_constant__ CUtensorMap tmVh, const __grid_constant__ CUtensorMap tmVl,
         __half* __restrict__ AO)
{
    extern __shared__ char smraw[];
    const uint32_t sb = smem_u32(smraw);
    const uint32_t tiles = (sb + 1024) & ~1023u;
    const uint32_t QHs = tiles, QLs = tiles + AT_TILEQ;
    const uint32_t STG = tiles + 2*AT_TILEQ;
    const int tid = threadIdx.x, lane = tid & 31, wid = tid >> 5;
    const int bh = blockIdx.y;
    const int q0 = blockIdx.x * QT;
    const int gy = bh * SEQ;

    const uint32_t BQ = sb, BF = sb + 8, BE = sb + 24;
    if (tid == 0) {
        MBARRIER_INIT(BQ, 1);
        MBARRIER_INIT(BF + 0, 1);
        MBARRIER_INIT(BF + 8, 1);
        MBARRIER_INIT(BE + 0, 256);
        MBARRIER_INIT(BE + 8, 256);
    }
    __syncthreads();
    if (tid == 0) {
        MBARRIER_EXPECT_TX(BQ, 2*AT_TILEQ);
        tma2d(QHs, &tmQh, 0, gy + q0, BQ);
        tma2d(QLs, &tmQl, 0, gy + q0, BQ);
#pragma unroll
        for (int s = 0; s < 2; s++) {
            const uint32_t st = STG + s*AT_STAGE;
            MBARRIER_EXPECT_TX(BF + 8*s, AT_STAGE);
            tma2d(st,                &tmKh, 0, gy + s*KT, BF + 8*s);
            tma2d(st +   AT_TILEKV,  &tmVh, 0, gy + s*KT, BF + 8*s);
            tma2d(st + 2*AT_TILEKV,  &tmVl, 0, gy + s*KT, BF + 8*s);
        }
    }

    float m_run[2] = { -1e30f, -1e30f };
    float l_run[2] = { 0.f, 0.f };
    float o_acc[8][4];
#pragma unroll
    for (int i = 0; i < 8; i++)
#pragma unroll
        for (int j = 0; j < 4; j++) o_acc[i][j] = 0.f;

    MBARRIER_WAIT_PARITY(BQ, 0);

    const int r0q = wid * 16;
    const int la7 = lane & 7;
    const int g01 = (lane >> 3) & 1;
    const int g23 = lane >> 4;

    for (int kt = 0; kt < SEQ / KT; kt++) {
        const int s = kt & 1, ph = (kt >> 1) & 1;
        MBARRIER_WAIT_PARITY(BF + 8*s, ph);
        const uint32_t Kh = STG + s*AT_STAGE;
        const uint32_t Vh = Kh + AT_TILEKV;
        const uint32_t Vl = Kh + 2*AT_TILEKV;

        float sf[8][4];
#pragma unroll
        for (int i = 0; i < 8; i++)
#pragma unroll
            for (int j = 0; j < 4; j++) sf[i][j] = 0.f;

        // ---- S = Q K^T, fp16 2-product (Qh + Ql vs Kh) ----
#pragma unroll
        for (int j = 0; j < 4; j++) {
            uint32_t qh[4], ql[4];
            {
                const int rr = r0q + la7 + g01*8;
                const int uu = 2*j + g23;
                ldsm_x4(qh[0],qh[1],qh[2],qh[3], ldsm_addr(QHs, rr, uu));
                ldsm_x4(ql[0],ql[1],ql[2],ql[3], ldsm_addr(QLs, rr, uu));
            }
#pragma unroll
            for (int np = 0; np < 4; np++) {
                const int rr = np*16 + la7 + g23*8;
                const int uu = 2*j + g01;
                uint32_t k0,k1,k2,k3;
                ldsm_x4(k0,k1,k2,k3, ldsm_addr(Kh, rr, uu));
                mma16816h(sf[2*np+0], qh, k0, k1);
                mma16816h(sf[2*np+1], qh, k2, k3);
                mma16816h(sf[2*np+0], ql, k0, k1);
                mma16816h(sf[2*np+1], ql, k2, k3);
            }
        }

        // ---- online softmax in exp2 domain ----
#pragma unroll
        for (int hf = 0; hf < 2; hf++) {
            float mx = -1e30f;
#pragma unroll
            for (int nt = 0; nt < 8; nt++)
                mx = fmaxf(mx, fmaxf(sf[nt][2*hf], sf[nt][2*hf+1]));
            mx = fmaxf(mx, __shfl_xor_sync(0xffffffffu, mx, 1));
            mx = fmaxf(mx, __shfl_xor_sync(0xffffffffu, mx, 2));
            const float mnew = fmaxf(m_run[hf], mx);
            const float corr = ex2(m_run[hf] - mnew);
            float sum = 0.f;
#pragma unroll
            for (int nt = 0; nt < 8; nt++) {
                const float p0 = ex2(sf[nt][2*hf]   - mnew);
                const float p1 = ex2(sf[nt][2*hf+1] - mnew);
                sf[nt][2*hf] = p0; sf[nt][2*hf+1] = p1;
                sum += p0 + p1;
            }
            sum += __shfl_xor_sync(0xffffffffu, sum, 1);
            sum += __shfl_xor_sync(0xffffffffu, sum, 2);
            l_run[hf] = l_run[hf] * corr + sum;
            m_run[hf] = mnew;
#pragma unroll
            for (int nt = 0; nt < 8; nt++) {
                o_acc[nt][2*hf]   *= corr;
                o_acc[nt][2*hf+1] *= corr;
            }
        }

        // ---- O += P V, fp16 2-product (Ph vs Vh + Vl) ----
#pragma unroll
        for (int j = 0; j < 4; j++) {
            uint32_t ph16[4];
#pragma unroll
            for (int t = 0; t < 4; t++) {
                const int nt = 2*j + (t >> 1);
                const int vv = (t & 1) * 2;
                ph16[t] = pack2_f16(sf[nt][vv+0], sf[nt][vv+1]);
            }
#pragma unroll
            for (int np = 0; np < 4; np++) {
                const int rr = 16*j + la7 + g01*8;
                const int uu = 2*np + g23;
                uint32_t v0,v1,v2,v3, w0,w1,w2,w3;
                ldsm_x4_t(v0,v1,v2,v3, ldsm_addr(Vh, rr, uu));
                ldsm_x4_t(w0,w1,w2,w3, ldsm_addr(Vl, rr, uu));
                mma16816h(o_acc[2*np+0], ph16, v0, v1);
                mma16816h(o_acc[2*np+1], ph16, v2, v3);
                mma16816h(o_acc[2*np+0], ph16, w0, w1);
                mma16816h(o_acc[2*np+1], ph16, w2, w3);
            }
        }

        MBARRIER_ARRIVE(BE + 8*s);
        if (tid == 0 && kt + 2 < SEQ / KT) {
            MBARRIER_WAIT_PARITY(BE + 8*s, ph);
            const uint32_t st = STG + s*AT_STAGE;
            MBARRIER_EXPECT_TX(BF + 8*s, AT_STAGE);
            tma2d(st,               &tmKh, 0, gy + (kt+2)*KT, BF + 8*s);
            tma2d(st +   AT_TILEKV, &tmVh, 0, gy + (kt+2)*KT, BF + 8*s);
            tma2d(st + 2*AT_TILEKV, &tmVl, 0, gy + (kt+2)*KT, BF + 8*s);
        }
    }

    // ---- epilogue: AO split fp16 [m][2048] ----
    const int b = bh >> 4, h = bh & 15;
#pragma unroll
    for (int hf = 0; hf < 2; hf++) {
        const float inv = 1.f / l_run[hf];
        const int srow = q0 + r0q + (lane >> 2) + hf*8;
#pragma unroll
        for (int nt = 0; nt < 8; nt++) {
            const int d = nt*8 + (lane & 3)*2;
            const float f0 = o_acc[nt][2*hf]   * inv;
            const float f1 = o_acc[nt][2*hf+1] * inv;
            uint32_t hp, lp;
            split_pack2_f16(f0, f1, hp, lp);
            const size_t base = ((size_t)b * SEQ + srow) * 2 * DMODEL + h * DHEAD + d;
            *(uint32_t*)&AO[base]          = hp;
            *(uint32_t*)&AO[base + DMODEL] = lp;
        }
    }
}

// ---------------------------------------------------------------------------
// Host
// ---------------------------------------------------------------------------
typedef CUresult (*PFN_tmEncode)(CUtensorMap*, CUtensorMapDataType, cuuint32_t, void*,
                                 const cuuint64_t*, const cuuint64_t*, const cuuint32_t*,
                                 const cuuint32_t*, CUtensorMapInterleave, CUtensorMapSwizzle,
                                 CUtensorMapL2promotion, CUtensorMapFloatOOBfill);

static void make_map(PFN_tmEncode enc, CUtensorMap* m, void* p, uint64_t rows,
                     uint64_t width, uint32_t b0, uint32_t b1)
{
    cuuint64_t dims[2]    = { width, rows };
    cuuint64_t strides[1] = { width * 2 };
    cuuint32_t box[2]     = { b0, b1 };
    cuuint32_t es[2]      = { 1, 1 };
    enc(m, CU_TENSOR_MAP_DATA_TYPE_FLOAT16, 2, p, dims, strides, box, es,
        CU_TENSOR_MAP_INTERLEAVE_NONE, CU_TENSOR_MAP_SWIZZLE_128B,
        CU_TENSOR_MAP_L2_PROMOTION_L2_128B, CU_TENSOR_MAP_FLOAT_OOB_FILL_NONE);
}

extern "C" void kernel_launch(void* const* d_in, const int* in_sizes, int n_in,
                              void* d_out, int out_size)
{
    const float* act[3] = { (const float*)d_in[0], (const float*)d_in[1], (const float*)d_in[2] };
    const float* W[4]   = { (const float*)d_in[3], (const float*)d_in[5], (const float*)d_in[7], (const float*)d_in[9] };
    const float* bia[4] = { (const float*)d_in[4], (const float*)d_in[6], (const float*)d_in[8], (const float*)d_in[10] };
    float* out = (float*)d_out;

    __half *pact, *pwt, *pao, *pqkv;
    float* pbc;
    cudaGetSymbolAddress((void**)&pact, g_act);
    cudaGetSymbolAddress((void**)&pwt,  g_wt);
    cudaGetSymbolAddress((void**)&pao,  g_ao);
    cudaGetSymbolAddress((void**)&pqkv, g_qkvs);
    cudaGetSymbolAddress((void**)&pbc,  g_biasc);

    PFN_tmEncode enc = nullptr;
    cudaDriverEntryPointQueryResult qr;
    cudaGetDriverEntryPointByVersion("cuTensorMapEncodeTiled", (void**)&enc, 12000,
                                     cudaEnableDefault, &qr);

    const size_t WM = (size_t)DMODEL * DMODEL;

    static QkvMaps qkvmaps;
    static CUtensorMap mAao, mBo, mQKV[5];
    for (int i = 0; i < 3; i++) {
        make_map(enc, &qkvmaps.a[i], pact + (size_t)i * MTOT * 2 * DMODEL, MTOT, 2*DMODEL, BK, 128);
        make_map(enc, &qkvmaps.b[i], pwt + (size_t)i * WM, DMODEL, DMODEL, BK, 128);
    }
    make_map(enc, &mAao, pao, MTOT, 2*DMODEL, BK, 128);
    make_map(enc, &mBo, pwt + 3*WM, DMODEL, DMODEL, BK, 128);
    // parts: 0=Qh, 1=Ql, 2=Kh, 3=Vh, 4=Vl
    for (int i = 0; i < 5; i++)
        make_map(enc, &mQKV[i], pqkv + i * QKVPART, (uint64_t)BHTOT * SEQ, DHEAD,
                 DHEAD, (i < 2) ? QT : KT);

    cudaFuncSetAttribute(gemm_qkv, cudaFuncAttributeMaxDynamicSharedMemorySize, GSMEM);
    cudaFuncSetAttribute(gemm_out, cudaFuncAttributeMaxDynamicSharedMemorySize, GSMEM);
    cudaFuncSetAttribute(attn_mma, cudaFuncAttributeMaxDynamicSharedMemorySize, ASMEM);

    // 1. fused preprocessing
    split_rows_kernel<<<dim3(MTOT, 3), 256>>>(act[0], act[1], act[2], pact);
    wt_split_kernel<<<dim3(32, 32, 4), dim3(32, 8)>>>(W[0], W[1], W[2], W[3], pwt);
    bias_concat_kernel<<<12, 256>>>(bia[0], bia[1], bia[2], pbc);

    // 2. fused QKV projections (one launch, 768 CTAs) -> fp16 QKV
    gemm_qkv<<<dim3(DMODEL/128, MTOT/128, 3), 256, GSMEM>>>(qkvmaps, pbc, pqkv);

    // 3. attention (fp16 HMMA), writes split AO
    attn_mma<<<dim3(SEQ / QT, BHTOT), 256, ASMEM>>>(
        mQKV[0], mQKV[1], mQKV[2], mQKV[3], mQKV[4], pao);

    // 4. output projection
    gemm_out<<<dim3(DMODEL/128, MTOT/128), 256, GSMEM>>>(mAao, mBo, bia[3], out);
}

// round 10
// speedup vs baseline: 5.1756x; 1.2030x over previous
#include <cuda_runtime.h>
#include <cuda.h>
#include <cuda_fp16.h>
#include <cstdint>

#define BATCH 2
#define SEQ   2048
#define DMODEL 1024
#define NHEAD 16
#define DHEAD 64
#define MTOT  (BATCH*SEQ)          // 4096
#define BHTOT (BATCH*NHEAD)        // 32
#define QKVPART ((size_t)BHTOT*SEQ*DHEAD)

// 0.125 * log2(e), folded into Wq/bq at preprocessing time.
#define QSCALE 0.1803368801111832f

// ---------------------------------------------------------------------------
// Device scratch
// ---------------------------------------------------------------------------
__device__ __half g_act[3u*MTOT*2*DMODEL];     // activations split (hi|lo)
__device__ __half g_wt[4u*DMODEL*DMODEL];      // W^T fp16 hi only; segs q,k,v,o
__device__ __half g_ao[(size_t)MTOT*2*DMODEL]; // attention out split (hi|lo)
__device__ __half g_qkvs[3*QKVPART];           // Qh,Kh,Vh [BH][S][64] (pure fp16)
__device__ float g_biasc[3*DMODEL];            // concat bq*QSCALE|bk|bv

// ---------------------------------------------------------------------------
// PTX helpers (legal at virtual arch compute_103)
// ---------------------------------------------------------------------------
__device__ __forceinline__ uint32_t smem_u32(const void* p) {
    uint32_t a;
    asm("{ .reg .u64 t; cvta.to.shared.u64 t, %1; cvt.u32.u64 %0, t; }" : "=r"(a) : "l"(p));
    return a;
}

#define MBARRIER_INIT(addr, cnt) \
    asm volatile("mbarrier.init.shared.b64 [%0], %1;" :: "r"((uint32_t)(addr)), "r"((uint32_t)(cnt)) : "memory")
#define MBARRIER_EXPECT_TX(addr, bytes) \
    asm volatile("mbarrier.arrive.expect_tx.shared.b64 _, [%0], %1;" :: "r"((uint32_t)(addr)), "r"((uint32_t)(bytes)) : "memory")
#define MBARRIER_ARRIVE(addr) \
    asm volatile("mbarrier.arrive.release.cta.shared::cta.b64 _, [%0];" :: "r"((uint32_t)(addr)) : "memory")

#define MBARRIER_WAIT_PARITY(mbar_smem_addr, phase_parity) do { \
    uint32_t _mbar = (uint32_t)(mbar_smem_addr); \
    uint32_t _parity = (uint32_t)(phase_parity); \
    uint32_t _done; \
    asm volatile( \
        "{\n\t.reg .pred p;\n\t" \
        "mbarrier.try_wait.parity.acquire.cta.shared::cta.b64 p, [%1], %2;\n\t" \
        "selp.b32 %0, 1, 0, p;\n\t}" \
        : "=r"(_done) : "r"(_mbar), "r"(_parity) : "memory"); \
    if (!_done) { \
        asm volatile( \
            "{\n\t.reg .pred P1;\n\t" \
            "WAIT_LOOP_%=:\n\t" \
            "mbarrier.try_wait.parity.acquire.cta.shared::cta.b64 P1, [%0], %1, 0x989680;\n\t" \
            "@P1 bra.uni WAIT_DONE_%=;\n\t" \
            "bra.uni WAIT_LOOP_%=;\n\t" \
            "WAIT_DONE_%=:\n\t}" \
            :: "r"(_mbar), "r"(_parity) : "memory"); \
    } \
} while(0)

__device__ __forceinline__ void tma2d(uint32_t dst, const CUtensorMap* m, int x, int y, uint32_t bar) {
    asm volatile(
        "cp.async.bulk.tensor.2d.shared::cta.global.tile.mbarrier::complete_tx::bytes "
        "[%0], [%1, {%2, %3}], [%4];"
        :: "r"(dst), "l"(m), "r"(x), "r"(y), "r"(bar) : "memory");
}

__device__ __forceinline__ void ldsm_x4(uint32_t& r0, uint32_t& r1, uint32_t& r2, uint32_t& r3,
                                        uint32_t addr) {
    asm volatile("ldmatrix.sync.aligned.m8n8.x4.shared.b16 {%0,%1,%2,%3}, [%4];"
                 : "=r"(r0), "=r"(r1), "=r"(r2), "=r"(r3) : "r"(addr));
}
__device__ __forceinline__ void ldsm_x4_t(uint32_t& r0, uint32_t& r1, uint32_t& r2, uint32_t& r3,
                                          uint32_t addr) {
    asm volatile("ldmatrix.sync.aligned.m8n8.x4.trans.shared.b16 {%0,%1,%2,%3}, [%4];"
                 : "=r"(r0), "=r"(r1), "=r"(r2), "=r"(r3) : "r"(addr));
}

// fp16 mma, fp32 accum
__device__ __forceinline__ void mma16816h(float* c, const uint32_t* a, uint32_t b0, uint32_t b1) {
    asm volatile(
        "mma.sync.aligned.m16n8k16.row.col.f32.f16.f16.f32 "
        "{%0,%1,%2,%3}, {%4,%5,%6,%7}, {%8,%9}, {%0,%1,%2,%3};"
        : "+f"(c[0]), "+f"(c[1]), "+f"(c[2]), "+f"(c[3])
        : "r"(a[0]), "r"(a[1]), "r"(a[2]), "r"(a[3]), "r"(b0), "r"(b1));
}

__device__ __forceinline__ uint32_t pack2_f16(float x0, float x1) {
    uint32_t u;
    asm("cvt.rn.f16x2.f32 %0, %1, %2;" : "=r"(u) : "f"(x1), "f"(x0));
    return u;
}
__device__ __forceinline__ void split_pack2_f16(float x0, float x1, uint32_t& hp, uint32_t& lp) {
    hp = pack2_f16(x0, x1);
    __half2 hh = *reinterpret_cast<__half2*>(&hp);
    lp = pack2_f16(x0 - __low2float(hh), x1 - __high2float(hh));
}
__device__ __forceinline__ float ex2(float x) {
    float y; asm("ex2.approx.f32 %0, %1;" : "=f"(y) : "f"(x)); return y;
}

// smem address for 16B unit `u` of row `r` in a SW128 tile (128B rows)
__device__ __forceinline__ uint32_t ldsm_addr(uint32_t base, int r, int u) {
    return base + (uint32_t)r * 128u + (uint32_t)((u ^ (r & 7)) << 4);
}

// ---------------------------------------------------------------------------
// Fused preprocessing
// ---------------------------------------------------------------------------
__global__ void __launch_bounds__(256)
split_rows_kernel(const float* __restrict__ q, const float* __restrict__ k,
                  const float* __restrict__ v, __half* __restrict__ dstbase)
{
    const float* x = (blockIdx.y == 0) ? q : (blockIdx.y == 1) ? k : v;
    __half* dst = dstbase + (size_t)blockIdx.y * MTOT * 2 * DMODEL;
    const int m = blockIdx.x;
    const int k4 = threadIdx.x * 4;
    float4 val = *(const float4*)&x[(size_t)m * DMODEL + k4];
    uint32_t hp0, lp0, hp1, lp1;
    split_pack2_f16(val.x, val.y, hp0, lp0);
    split_pack2_f16(val.z, val.w, hp1, lp1);
    __half* hi = dst + (size_t)m * 2 * DMODEL + k4;
    *(uint32_t*)(hi)          = hp0;
    *(uint32_t*)(hi + 2)      = hp1;
    *(uint32_t*)(hi + DMODEL)     = lp0;
    *(uint32_t*)(hi + DMODEL + 2) = lp1;
}

__global__ void __launch_bounds__(256)
wt_split_kernel(const float* __restrict__ Wq, const float* __restrict__ Wk,
                const float* __restrict__ Wv, const float* __restrict__ Wo,
                __half* __restrict__ Tbase)
{
    const float* W = (blockIdx.z == 0) ? Wq : (blockIdx.z == 1) ? Wk
                   : (blockIdx.z == 2) ? Wv : Wo;
    const float sc = (blockIdx.z == 0) ? QSCALE : 1.0f;
    __half* T = Tbase + (size_t)blockIdx.z * DMODEL * DMODEL;
    __shared__ float t[32][33];
    const int n0 = blockIdx.x * 32, k0 = blockIdx.y * 32;
    const int tx = threadIdx.x, ty = threadIdx.y;   // (32, 8)
#pragma unroll
    for (int i = 0; i < 4; i++)
        t[ty + 8*i][tx] = W[(size_t)(k0 + ty + 8*i) * DMODEL + n0 + tx];
    __syncthreads();
#pragma unroll
    for (int i = 0; i < 4; i++) {
        const int n = n0 + ty + 8*i;
        const int k = k0 + tx;
        T[(size_t)n * DMODEL + k] = __float2half(t[tx][ty + 8*i] * sc);
    }
}

__global__ void __launch_bounds__(256)
bias_concat_kernel(const float* __restrict__ bq, const float* __restrict__ bk,
                   const float* __restrict__ bv, float* __restrict__ dst)
{
    const int i = blockIdx.x * 256 + threadIdx.x;       // 0..3071
    const float* s = (i < 1024) ? bq : (i < 2048) ? bk : bv;
    const float sc = (i < 1024) ? QSCALE : 1.0f;
    dst[i] = s[i & 1023] * sc;
}

// ---------------------------------------------------------------------------
// fp16 HMMA GEMM core, 2-product split (Ah*Bh + Al*Bh), K=1024.
// MODE 0: row-major fp32 C.  MODE 1: fp16 (hi only) scatter to [BH][S][64].
// ---------------------------------------------------------------------------
#define BK       64
#define NCHUNK   16
#define GTILE    16384              // 128 rows x 128B
#define GSTAGE   (3*GTILE)          // Ah, Al, B
#define GSMEM    (1024 + 2*GSTAGE)

template<int MODE>
__device__ __forceinline__ void gemm_core(
    const CUtensorMap* tmA, const CUtensorMap* tmB,
    const float* __restrict__ bias, float* __restrict__ C,
    __half* __restrict__ Ohi, int bm, int bn)
{
    extern __shared__ char sm_raw[];
    const uint32_t sb = smem_u32(sm_raw);
    const uint32_t tiles = (sb + 1024) & ~1023u;
    const int tid = threadIdx.x;
    const int lane = tid & 31, wid = tid >> 5;
    const int wm = wid & 3, wn = wid >> 2;

    const uint32_t FULL = sb;            // 2 x 8B
    const uint32_t EMPTY = sb + 16;      // 2 x 8B

    if (tid == 0) {
#pragma unroll
        for (int s = 0; s < 2; s++) {
            MBARRIER_INIT(FULL + 8*s, 1);
            MBARRIER_INIT(EMPTY + 8*s, 256);
        }
    }
    __syncthreads();

    if (tid == 0) {
#pragma unroll
        for (int s = 0; s < 2; s++) {
            MBARRIER_EXPECT_TX(FULL + 8*s, GSTAGE);
            tma2d(tiles + s*GSTAGE,           tmA, s*BK,          bm, FULL + 8*s);
            tma2d(tiles + s*GSTAGE + GTILE,   tmA, DMODEL + s*BK, bm, FULL + 8*s);
            tma2d(tiles + s*GSTAGE + 2*GTILE, tmB, s*BK,          bn, FULL + 8*s);
        }
    }

    float acc[2][8][4];
#pragma unroll
    for (int i = 0; i < 2; i++)
#pragma unroll
        for (int j = 0; j < 8; j++)
#pragma unroll
            for (int q = 0; q < 4; q++) acc[i][j][q] = 0.f;

    const int lrow = lane & 15;
    const int lcolhalf = lane >> 4;
    const int sw = lane & 7;

    for (int c = 0; c < NCHUNK; c++) {
        const int s = c & 1, ph = (c >> 1) & 1;
        MBARRIER_WAIT_PARITY(FULL + 8*s, ph);

        const uint32_t Ah = tiles + s*GSTAGE;
        const uint32_t Al = Ah + GTILE;
        const uint32_t Bs = Ah + 2*GTILE;

#pragma unroll
        for (int kk = 0; kk < 4; kk++) {
            const int cidx = 2*kk + lcolhalf;
            const uint32_t coff = (uint32_t)((cidx ^ sw) << 4);

            uint32_t ah[2][4], al[2][4];
#pragma unroll
            for (int mi = 0; mi < 2; mi++) {
                const int r = wm*32 + mi*16 + lrow;
                ldsm_x4(ah[mi][0], ah[mi][1], ah[mi][2], ah[mi][3],
                        Ah + (uint32_t)r*128 + coff);
                ldsm_x4(al[mi][0], al[mi][1], al[mi][2], al[mi][3],
                        Al + (uint32_t)r*128 + coff);
            }
            uint32_t b[4][4];
#pragma unroll
            for (int ni = 0; ni < 4; ni++) {
                const int r = wn*64 + ni*16 + lrow;
                ldsm_x4(b[ni][0], b[ni][1], b[ni][2], b[ni][3],
                        Bs + (uint32_t)r*128 + coff);
            }
#pragma unroll
            for (int mi = 0; mi < 2; mi++)
#pragma unroll
                for (int ni = 0; ni < 4; ni++) {
                    mma16816h(acc[mi][2*ni+0], ah[mi], b[ni][0], b[ni][2]);
                    mma16816h(acc[mi][2*ni+1], ah[mi], b[ni][1], b[ni][3]);
                    mma16816h(acc[mi][2*ni+0], al[mi], b[ni][0], b[ni][2]);
                    mma16816h(acc[mi][2*ni+1], al[mi], b[ni][1], b[ni][3]);
                }
        }
        MBARRIER_ARRIVE(EMPTY + 8*s);
        if (tid == 0 && c + 2 < NCHUNK) {
            MBARRIER_WAIT_PARITY(EMPTY + 8*s, ph);
            MBARRIER_EXPECT_TX(FULL + 8*s, GSTAGE);
            const int kx = (c + 2) * BK;
            tma2d(Ah, tmA, kx,          bm, FULL + 8*s);
            tma2d(Al, tmA, DMODEL + kx, bm, FULL + 8*s);
            tma2d(Bs, tmB, kx,          bn, FULL + 8*s);
        }
    }

    const int grp = lane >> 2;
    const int qd  = lane & 3;
#pragma unroll
    for (int mi = 0; mi < 2; mi++) {
#pragma unroll
        for (int nj = 0; nj < 8; nj++) {
            const int col = bn + wn*64 + nj*8 + qd*2;
            const float b0 = __ldg(&bias[col]);
            const float b1 = __ldg(&bias[col + 1]);
#pragma unroll
            for (int half = 0; half < 2; half++) {
                const int m = bm + wm*32 + mi*16 + grp + half*8;
                const float v0 = acc[mi][nj][2*half+0] + b0;
                const float v1 = acc[mi][nj][2*half+1] + b1;
                if (MODE == 0) {
                    *(float2*)&C[(size_t)m * DMODEL + col] = make_float2(v0, v1);
                } else {
                    const int b = m >> 11, srow = m & 2047;
                    const int h = col >> 6, d = col & 63;
                    const size_t off = (((size_t)b * NHEAD + h) * SEQ + srow) * DHEAD + d;
                    *(uint32_t*)&Ohi[off] = pack2_f16(v0, v1);
                }
            }
        }
    }
}

// Fused QKV: grid.z selects tensor; all outputs fp16 hi only.
struct QkvMaps { CUtensorMap a[3]; CUtensorMap b[3]; };

__global__ void __launch_bounds__(256, 2)
gemm_qkv(const __grid_constant__ QkvMaps maps,
         const float* __restrict__ biasc, __half* __restrict__ qkvbase)
{
    const int i = blockIdx.z;
    gemm_core<1>(&maps.a[i], &maps.b[i], biasc + i * DMODEL, nullptr,
                 qkvbase + (size_t)i * QKVPART,
                 blockIdx.y * 128, blockIdx.x * 128);
}

__global__ void __launch_bounds__(256, 2)
gemm_out(const __grid_constant__ CUtensorMap tmA,
         const __grid_constant__ CUtensorMap tmB,
         const float* __restrict__ bias, float* __restrict__ C)
{
    gemm_core<0>(&tmA, &tmB, bias, C, nullptr, blockIdx.y * 128, blockIdx.x * 128);
}

// ---------------------------------------------------------------------------
// Flash attention, pure fp16 HMMA (QK = Qh*Kh, PV = Ph*Vh), exp2 softmax,
// EMPTY-mbarrier KV pipeline. Output written as split fp16 AO for Wo GEMM.
// ---------------------------------------------------------------------------
#define QT 128
#define KT 64
#define AT_TILEQ  16384              // 128 x 128B
#define AT_TILEKV 8192               // 64 x 128B
#define AT_STAGE  (2*AT_TILEKV)      // Kh, Vh
#define ASMEM (1024 + AT_TILEQ + 2*AT_STAGE)

__global__ void __launch_bounds__(256)
attn_mma(const __grid_constant__ CUtensorMap tmQ,
         const __grid_constant__ CUtensorMap tmK,
         const __grid_constant__ CUtensorMap tmV,
         __half* __restrict__ AO)
{
    extern __shared__ char smraw[];
    const uint32_t sb = smem_u32(smraw);
    const uint32_t tiles = (sb + 1024) & ~1023u;
    const uint32_t Qs = tiles;
    const uint32_t STG = tiles + AT_TILEQ;
    const int tid = threadIdx.x, lane = tid & 31, wid = tid >> 5;
    const int bh = blockIdx.y;
    const int q0 = blockIdx.x * QT;
    const int gy = bh * SEQ;

    const uint32_t BQ = sb, BF = sb + 8, BE = sb + 24;
    if (tid == 0) {
        MBARRIER_INIT(BQ, 1);
        MBARRIER_INIT(BF + 0, 1);
        MBARRIER_INIT(BF + 8, 1);
        MBARRIER_INIT(BE + 0, 256);
        MBARRIER_INIT(BE + 8, 256);
    }
    __syncthreads();
    if (tid == 0) {
        MBARRIER_EXPECT_TX(BQ, AT_TILEQ);
        tma2d(Qs, &tmQ, 0, gy + q0, BQ);
#pragma unroll
        for (int s = 0; s < 2; s++) {
            const uint32_t st = STG + s*AT_STAGE;
            MBARRIER_EXPECT_TX(BF + 8*s, AT_STAGE);
            tma2d(st,              &tmK, 0, gy + s*KT, BF + 8*s);
            tma2d(st + AT_TILEKV,  &tmV, 0, gy + s*KT, BF + 8*s);
        }
    }

    float m_run[2] = { -1e30f, -1e30f };
    float l_run[2] = { 0.f, 0.f };
    float o_acc[8][4];
#pragma unroll
    for (int i = 0; i < 8; i++)
#pragma unroll
        for (int j = 0; j < 4; j++) o_acc[i][j] = 0.f;

    MBARRIER_WAIT_PARITY(BQ, 0);

    const int r0q = wid * 16;
    const int la7 = lane & 7;
    const int g01 = (lane >> 3) & 1;
    const int g23 = lane >> 4;

    // Q fragments are loop-invariant: load once (16 regs).
    uint32_t qf[4][4];
#pragma unroll
    for (int j = 0; j < 4; j++) {
        const int rr = r0q + la7 + g01*8;
        const int uu = 2*j + g23;
        ldsm_x4(qf[j][0], qf[j][1], qf[j][2], qf[j][3], ldsm_addr(Qs, rr, uu));
    }

    for (int kt = 0; kt < SEQ / KT; kt++) {
        const int s = kt & 1, ph = (kt >> 1) & 1;
        MBARRIER_WAIT_PARITY(BF + 8*s, ph);
        const uint32_t Kh = STG + s*AT_STAGE;
        const uint32_t Vh = Kh + AT_TILEKV;

        float sf[8][4];
#pragma unroll
        for (int i = 0; i < 8; i++)
#pragma unroll
            for (int j = 0; j < 4; j++) sf[i][j] = 0.f;

        // ---- S = Q K^T (pure fp16) ----
#pragma unroll
        for (int j = 0; j < 4; j++) {
#pragma unroll
            for (int np = 0; np < 4; np++) {
                const int rr = np*16 + la7 + g23*8;
                const int uu = 2*j + g01;
                uint32_t k0,k1,k2,k3;
                ldsm_x4(k0,k1,k2,k3, ldsm_addr(Kh, rr, uu));
                mma16816h(sf[2*np+0], qf[j], k0, k1);
                mma16816h(sf[2*np+1], qf[j], k2, k3);
            }
        }

        // ---- online softmax in exp2 domain ----
#pragma unroll
        for (int hf = 0; hf < 2; hf++) {
            float mx = -1e30f;
#pragma unroll
            for (int nt = 0; nt < 8; nt++)
                mx = fmaxf(mx, fmaxf(sf[nt][2*hf], sf[nt][2*hf+1]));
            mx = fmaxf(mx, __shfl_xor_sync(0xffffffffu, mx, 1));
            mx = fmaxf(mx, __shfl_xor_sync(0xffffffffu, mx, 2));
            const float mnew = fmaxf(m_run[hf], mx);
            const float corr = ex2(m_run[hf] - mnew);
            float sum = 0.f;
#pragma unroll
            for (int nt = 0; nt < 8; nt++) {
                const float p0 = ex2(sf[nt][2*hf]   - mnew);
                const float p1 = ex2(sf[nt][2*hf+1] - mnew);
                sf[nt][2*hf] = p0; sf[nt][2*hf+1] = p1;
                sum += p0 + p1;
            }
            sum += __shfl_xor_sync(0xffffffffu, sum, 1);
            sum += __shfl_xor_sync(0xffffffffu, sum, 2);
            l_run[hf] = l_run[hf] * corr + sum;
            m_run[hf] = mnew;
#pragma unroll
            for (int nt = 0; nt < 8; nt++) {
                o_acc[nt][2*hf]   *= corr;
                o_acc[nt][2*hf+1] *= corr;
            }
        }

        // ---- O += P V (pure fp16) ----
#pragma unroll
        for (int j = 0; j < 4; j++) {
            uint32_t ph16[4];
#pragma unroll
            for (int t = 0; t < 4; t++) {
                const int nt = 2*j + (t >> 1);
                const int vv = (t & 1) * 2;
                ph16[t] = pack2_f16(sf[nt][vv+0], sf[nt][vv+1]);
            }
#pragma unroll
            for (int np = 0; np < 4; np++) {
                const int rr = 16*j + la7 + g01*8;
                const int uu = 2*np + g23;
                uint32_t v0,v1,v2,v3;
                ldsm_x4_t(v0,v1,v2,v3, ldsm_addr(Vh, rr, uu));
                mma16816h(o_acc[2*np+0], ph16, v0, v1);
                mma16816h(o_acc[2*np+1], ph16, v2, v3);
            }
        }

        MBARRIER_ARRIVE(BE + 8*s);
        if (tid == 0 && kt + 2 < SEQ / KT) {
            MBARRIER_WAIT_PARITY(BE + 8*s, ph);
            const uint32_t st = STG + s*AT_STAGE;
            MBARRIER_EXPECT_TX(BF + 8*s, AT_STAGE);
            tma2d(st,             &tmK, 0, gy + (kt+2)*KT, BF + 8*s);
            tma2d(st + AT_TILEKV, &tmV, 0, gy + (kt+2)*KT, BF + 8*s);
        }
    }

    // ---- epilogue: AO split fp16 [m][2048] (hi|lo) for the Wo 2-product ----
    const int b = bh >> 4, h = bh & 15;
#pragma unroll
    for (int hf = 0; hf < 2; hf++) {
        const float inv = 1.f / l_run[hf];
        const int srow = q0 + r0q + (lane >> 2) + hf*8;
#pragma unroll
        for (int nt = 0; nt < 8; nt++) {
            const int d = nt*8 + (lane & 3)*2;
            const float f0 = o_acc[nt][2*hf]   * inv;
            const float f1 = o_acc[nt][2*hf+1] * inv;
            uint32_t hp, lp;
            split_pack2_f16(f0, f1, hp, lp);
            const size_t base = ((size_t)b * SEQ + srow) * 2 * DMODEL + h * DHEAD + d;
            *(uint32_t*)&AO[base]          = hp;
            *(uint32_t*)&AO[base + DMODEL] = lp;
        }
    }
}

// ---------------------------------------------------------------------------
// Host
// ---------------------------------------------------------------------------
typedef CUresult (*PFN_tmEncode)(CUtensorMap*, CUtensorMapDataType, cuuint32_t, void*,
                                 const cuuint64_t*, const cuuint64_t*, const cuuint32_t*,
                                 const cuuint32_t*, CUtensorMapInterleave, CUtensorMapSwizzle,
                                 CUtensorMapL2promotion, CUtensorMapFloatOOBfill);

static void make_map(PFN_tmEncode enc, CUtensorMap* m, void* p, uint64_t rows,
                     uint64_t width, uint32_t b0, uint32_t b1)
{
    cuuint64_t dims[2]    = { width, rows };
    cuuint64_t strides[1] = { width * 2 };
    cuuint32_t box[2]     = { b0, b1 };
    cuuint32_t es[2]      = { 1, 1 };
    enc(m, CU_TENSOR_MAP_DATA_TYPE_FLOAT16, 2, p, dims, strides, box, es,
        CU_TENSOR_MAP_INTERLEAVE_NONE, CU_TENSOR_MAP_SWIZZLE_128B,
        CU_TENSOR_MAP_L2_PROMOTION_L2_128B, CU_TENSOR_MAP_FLOAT_OOB_FILL_NONE);
}

extern "C" void kernel_launch(void* const* d_in, const int* in_sizes, int n_in,
                              void* d_out, int out_size)
{
    const float* act[3] = { (const float*)d_in[0], (const float*)d_in[1], (const float*)d_in[2] };
    const float* W[4]   = { (const float*)d_in[3], (const float*)d_in[5], (const float*)d_in[7], (const float*)d_in[9] };
    const float* bia[4] = { (const float*)d_in[4], (const float*)d_in[6], (const float*)d_in[8], (const float*)d_in[10] };
    float* out = (float*)d_out;

    __half *pact, *pwt, *pao, *pqkv;
    float* pbc;
    cudaGetSymbolAddress((void**)&pact, g_act);
    cudaGetSymbolAddress((void**)&pwt,  g_wt);
    cudaGetSymbolAddress((void**)&pao,  g_ao);
    cudaGetSymbolAddress((void**)&pqkv, g_qkvs);
    cudaGetSymbolAddress((void**)&pbc,  g_biasc);

    PFN_tmEncode enc = nullptr;
    cudaDriverEntryPointQueryResult qr;
    cudaGetDriverEntryPointByVersion("cuTensorMapEncodeTiled", (void**)&enc, 12000,
                                     cudaEnableDefault, &qr);

    const size_t WM = (size_t)DMODEL * DMODEL;

    static QkvMaps qkvmaps;
    static CUtensorMap mAao, mBo, mQKV[3];
    for (int i = 0; i < 3; i++) {
        make_map(enc, &qkvmaps.a[i], pact + (size_t)i * MTOT * 2 * DMODEL, MTOT, 2*DMODEL, BK, 128);
        make_map(enc, &qkvmaps.b[i], pwt + (size_t)i * WM, DMODEL, DMODEL, BK, 128);
    }
    make_map(enc, &mAao, pao, MTOT, 2*DMODEL, BK, 128);
    make_map(enc, &mBo, pwt + 3*WM, DMODEL, DMODEL, BK, 128);
    // parts: 0=Qh, 1=Kh, 2=Vh
    for (int i = 0; i < 3; i++)
        make_map(enc, &mQKV[i], pqkv + i * QKVPART, (uint64_t)BHTOT * SEQ, DHEAD,
                 DHEAD, (i == 0) ? QT : KT);

    cudaFuncSetAttribute(gemm_qkv, cudaFuncAttributeMaxDynamicSharedMemorySize, GSMEM);
    cudaFuncSetAttribute(gemm_out, cudaFuncAttributeMaxDynamicSharedMemorySize, GSMEM);
    cudaFuncSetAttribute(attn_mma, cudaFuncAttributeMaxDynamicSharedMemorySize, ASMEM);

    // 1. fused preprocessing
    split_rows_kernel<<<dim3(MTOT, 3), 256>>>(act[0], act[1], act[2], pact);
    wt_split_kernel<<<dim3(32, 32, 4), dim3(32, 8)>>>(W[0], W[1], W[2], W[3], pwt);
    bias_concat_kernel<<<12, 256>>>(bia[0], bia[1], bia[2], pbc);

    // 2. fused QKV projections (one launch) -> pure fp16 Q,K,V
    gemm_qkv<<<dim3(DMODEL/128, MTOT/128, 3), 256, GSMEM>>>(qkvmaps, pbc, pqkv);

    // 3. attention (pure fp16 HMMA), writes split AO
    attn_mma<<<dim3(SEQ / QT, BHTOT), 256, ASMEM>>>(mQKV[0], mQKV[1], mQKV[2], pao);

    // 4. output projection (2-product on split AO)
    gemm_out<<<dim3(DMODEL/128, MTOT/128), 256, GSMEM>>>(mAao, mBo, bia[3], out);
}

// round 11
// speedup vs baseline: 6.4461x; 1.2455x over previous
#include <cuda_runtime.h>
#include <cuda.h>
#include <cuda_fp16.h>
#include <cstdint>

#define BATCH 2
#define SEQ   2048
#define DMODEL 1024
#define NHEAD 16
#define DHEAD 64
#define MTOT  (BATCH*SEQ)          // 4096
#define BHTOT (BATCH*NHEAD)        // 32
#define QKVPART ((size_t)BHTOT*SEQ*DHEAD)

// 0.125 * log2(e), folded into Wq/bq at preprocessing time.
#define QSCALE 0.1803368801111832f

// ---------------------------------------------------------------------------
// Device scratch
// ---------------------------------------------------------------------------
__device__ __half g_act[3u*MTOT*DMODEL];       // activations fp16 hi only
__device__ __half g_wt[4u*DMODEL*DMODEL];      // W^T fp16 hi only; segs q,k,v,o
__device__ __half g_ao[(size_t)MTOT*2*DMODEL]; // attention out split (hi|lo)
__device__ __half g_qkvs[3*QKVPART];           // Qh,Kh,Vh [BH][S][64]
__device__ float g_biasc[3*DMODEL];            // concat bq*QSCALE|bk|bv

// ---------------------------------------------------------------------------
// PTX helpers (legal at virtual arch compute_103)
// ---------------------------------------------------------------------------
__device__ __forceinline__ uint32_t smem_u32(const void* p) {
    uint32_t a;
    asm("{ .reg .u64 t; cvta.to.shared.u64 t, %1; cvt.u32.u64 %0, t; }" : "=r"(a) : "l"(p));
    return a;
}

#define MBARRIER_INIT(addr, cnt) \
    asm volatile("mbarrier.init.shared.b64 [%0], %1;" :: "r"((uint32_t)(addr)), "r"((uint32_t)(cnt)) : "memory")
#define MBARRIER_EXPECT_TX(addr, bytes) \
    asm volatile("mbarrier.arrive.expect_tx.shared.b64 _, [%0], %1;" :: "r"((uint32_t)(addr)), "r"((uint32_t)(bytes)) : "memory")
#define MBARRIER_ARRIVE(addr) \
    asm volatile("mbarrier.arrive.release.cta.shared::cta.b64 _, [%0];" :: "r"((uint32_t)(addr)) : "memory")

#define MBARRIER_WAIT_PARITY(mbar_smem_addr, phase_parity) do { \
    uint32_t _mbar = (uint32_t)(mbar_smem_addr); \
    uint32_t _parity = (uint32_t)(phase_parity); \
    uint32_t _done; \
    asm volatile( \
        "{\n\t.reg .pred p;\n\t" \
        "mbarrier.try_wait.parity.acquire.cta.shared::cta.b64 p, [%1], %2;\n\t" \
        "selp.b32 %0, 1, 0, p;\n\t}" \
        : "=r"(_done) : "r"(_mbar), "r"(_parity) : "memory"); \
    if (!_done) { \
        asm volatile( \
            "{\n\t.reg .pred P1;\n\t" \
            "WAIT_LOOP_%=:\n\t" \
            "mbarrier.try_wait.parity.acquire.cta.shared::cta.b64 P1, [%0], %1, 0x989680;\n\t" \
            "@P1 bra.uni WAIT_DONE_%=;\n\t" \
            "bra.uni WAIT_LOOP_%=;\n\t" \
            "WAIT_DONE_%=:\n\t}" \
            :: "r"(_mbar), "r"(_parity) : "memory"); \
    } \
} while(0)

__device__ __forceinline__ void tma2d(uint32_t dst, const CUtensorMap* m, int x, int y, uint32_t bar) {
    asm volatile(
        "cp.async.bulk.tensor.2d.shared::cta.global.tile.mbarrier::complete_tx::bytes "
        "[%0], [%1, {%2, %3}], [%4];"
        :: "r"(dst), "l"(m), "r"(x), "r"(y), "r"(bar) : "memory");
}

__device__ __forceinline__ void ldsm_x4(uint32_t& r0, uint32_t& r1, uint32_t& r2, uint32_t& r3,
                                        uint32_t addr) {
    asm volatile("ldmatrix.sync.aligned.m8n8.x4.shared.b16 {%0,%1,%2,%3}, [%4];"
                 : "=r"(r0), "=r"(r1), "=r"(r2), "=r"(r3) : "r"(addr));
}
__device__ __forceinline__ void ldsm_x4_t(uint32_t& r0, uint32_t& r1, uint32_t& r2, uint32_t& r3,
                                          uint32_t addr) {
    asm volatile("ldmatrix.sync.aligned.m8n8.x4.trans.shared.b16 {%0,%1,%2,%3}, [%4];"
                 : "=r"(r0), "=r"(r1), "=r"(r2), "=r"(r3) : "r"(addr));
}

// fp16 mma, fp32 accum
__device__ __forceinline__ void mma16816h(float* c, const uint32_t* a, uint32_t b0, uint32_t b1) {
    asm volatile(
        "mma.sync.aligned.m16n8k16.row.col.f32.f16.f16.f32 "
        "{%0,%1,%2,%3}, {%4,%5,%6,%7}, {%8,%9}, {%0,%1,%2,%3};"
        : "+f"(c[0]), "+f"(c[1]), "+f"(c[2]), "+f"(c[3])
        : "r"(a[0]), "r"(a[1]), "r"(a[2]), "r"(a[3]), "r"(b0), "r"(b1));
}

__device__ __forceinline__ uint32_t pack2_f16(float x0, float x1) {
    uint32_t u;
    asm("cvt.rn.f16x2.f32 %0, %1, %2;" : "=r"(u) : "f"(x1), "f"(x0));
    return u;
}
__device__ __forceinline__ void split_pack2_f16(float x0, float x1, uint32_t& hp, uint32_t& lp) {
    hp = pack2_f16(x0, x1);
    __half2 hh = *reinterpret_cast<__half2*>(&hp);
    lp = pack2_f16(x0 - __low2float(hh), x1 - __high2float(hh));
}
__device__ __forceinline__ float ex2(float x) {
    float y; asm("ex2.approx.f32 %0, %1;" : "=f"(y) : "f"(x)); return y;
}

// smem address for 16B unit `u` of row `r` in a SW128 tile (128B rows)
__device__ __forceinline__ uint32_t ldsm_addr(uint32_t base, int r, int u) {
    return base + (uint32_t)r * 128u + (uint32_t)((u ^ (r & 7)) << 4);
}

// ---------------------------------------------------------------------------
// Fused preprocessing
// ---------------------------------------------------------------------------
__global__ void __launch_bounds__(256)
split_rows_kernel(const float* __restrict__ q, const float* __restrict__ k,
                  const float* __restrict__ v, __half* __restrict__ dstbase)
{
    const float* x = (blockIdx.y == 0) ? q : (blockIdx.y == 1) ? k : v;
    __half* dst = dstbase + (size_t)blockIdx.y * MTOT * DMODEL;
    const int m = blockIdx.x;
    const int k4 = threadIdx.x * 4;
    float4 val = *(const float4*)&x[(size_t)m * DMODEL + k4];
    __half* hi = dst + (size_t)m * DMODEL + k4;
    *(uint32_t*)(hi)     = pack2_f16(val.x, val.y);
    *(uint32_t*)(hi + 2) = pack2_f16(val.z, val.w);
}

__global__ void __launch_bounds__(256)
wt_split_kernel(const float* __restrict__ Wq, const float* __restrict__ Wk,
                const float* __restrict__ Wv, const float* __restrict__ Wo,
                __half* __restrict__ Tbase)
{
    const float* W = (blockIdx.z == 0) ? Wq : (blockIdx.z == 1) ? Wk
                   : (blockIdx.z == 2) ? Wv : Wo;
    const float sc = (blockIdx.z == 0) ? QSCALE : 1.0f;
    __half* T = Tbase + (size_t)blockIdx.z * DMODEL * DMODEL;
    __shared__ float t[32][33];
    const int n0 = blockIdx.x * 32, k0 = blockIdx.y * 32;
    const int tx = threadIdx.x, ty = threadIdx.y;   // (32, 8)
#pragma unroll
    for (int i = 0; i < 4; i++)
        t[ty + 8*i][tx] = W[(size_t)(k0 + ty + 8*i) * DMODEL + n0 + tx];
    __syncthreads();
#pragma unroll
    for (int i = 0; i < 4; i++) {
        const int n = n0 + ty + 8*i;
        const int k = k0 + tx;
        T[(size_t)n * DMODEL + k] = __float2half(t[tx][ty + 8*i] * sc);
    }
}

__global__ void __launch_bounds__(256)
bias_concat_kernel(const float* __restrict__ bq, const float* __restrict__ bk,
                   const float* __restrict__ bv, float* __restrict__ dst)
{
    const int i = blockIdx.x * 256 + threadIdx.x;       // 0..3071
    const float* s = (i < 1024) ? bq : (i < 2048) ? bk : bv;
    const float sc = (i < 1024) ? QSCALE : 1.0f;
    dst[i] = s[i & 1023] * sc;
}

// ---------------------------------------------------------------------------
// fp16 HMMA GEMM core, K=1024.
// NPROD=1: C = Ah*Bh (3-stage pipeline, 2 tiles/stage).
// NPROD=2: C = Ah*Bh + Al*Bh (2-stage, 3 tiles/stage; A split hi|lo).
// MODE 0: row-major fp32 C.  MODE 1: fp16 hi scatter to [BH][S][64].
// ---------------------------------------------------------------------------
#define BK       64
#define NCHUNK   16
#define GTILE    16384              // 128 rows x 128B
#define GSMEM    (1024 + 6*GTILE)   // same footprint for both variants

template<int MODE, int NPROD>
__device__ __forceinline__ void gemm_core(
    const CUtensorMap* tmA, const CUtensorMap* tmB,
    const float* __restrict__ bias, float* __restrict__ C,
    __half* __restrict__ Ohi, int bm, int bn)
{
    constexpr int NSTG = (NPROD == 1) ? 3 : 2;
    constexpr int SSZ  = (NPROD == 1) ? 2*GTILE : 3*GTILE;
    constexpr int SBYTES = SSZ;

    extern __shared__ char sm_raw[];
    const uint32_t sb = smem_u32(sm_raw);
    const uint32_t tiles = (sb + 1024) & ~1023u;
    const int tid = threadIdx.x;
    const int lane = tid & 31, wid = tid >> 5;
    const int wm = wid & 3, wn = wid >> 2;

    const uint32_t FULL = sb;            // 3 x 8B
    const uint32_t EMPTY = sb + 24;      // 3 x 8B

    if (tid == 0) {
#pragma unroll
        for (int s = 0; s < NSTG; s++) {
            MBARRIER_INIT(FULL + 8*s, 1);
            MBARRIER_INIT(EMPTY + 8*s, 256);
        }
    }
    __syncthreads();

    if (tid == 0) {
#pragma unroll
        for (int s = 0; s < NSTG; s++) {
            MBARRIER_EXPECT_TX(FULL + 8*s, SBYTES);
            const uint32_t st = tiles + s*SSZ;
            if (NPROD == 1) {
                tma2d(st,         tmA, s*BK, bm, FULL + 8*s);
                tma2d(st + GTILE, tmB, s*BK, bn, FULL + 8*s);
            } else {
                tma2d(st,           tmA, s*BK,          bm, FULL + 8*s);
                tma2d(st + GTILE,   tmA, DMODEL + s*BK, bm, FULL + 8*s);
                tma2d(st + 2*GTILE, tmB, s*BK,          bn, FULL + 8*s);
            }
        }
    }

    float acc[2][8][4];
#pragma unroll
    for (int i = 0; i < 2; i++)
#pragma unroll
        for (int j = 0; j < 8; j++)
#pragma unroll
            for (int q = 0; q < 4; q++) acc[i][j][q] = 0.f;

    const int lrow = lane & 15;
    const int lcolhalf = lane >> 4;
    const int sw = lane & 7;

    for (int c = 0; c < NCHUNK; c++) {
        const int s = c % NSTG;
        const int ph = (c / NSTG) & 1;
        MBARRIER_WAIT_PARITY(FULL + 8*s, ph);

        const uint32_t Ah = tiles + s*SSZ;
        const uint32_t Al = Ah + GTILE;                       // NPROD==2 only
        const uint32_t Bs = Ah + (NPROD == 1 ? GTILE : 2*GTILE);

#pragma unroll
        for (int kk = 0; kk < 4; kk++) {
            const int cidx = 2*kk + lcolhalf;
            const uint32_t coff = (uint32_t)((cidx ^ sw) << 4);

            uint32_t ah[2][4], al[2][4];
#pragma unroll
            for (int mi = 0; mi < 2; mi++) {
                const int r = wm*32 + mi*16 + lrow;
                ldsm_x4(ah[mi][0], ah[mi][1], ah[mi][2], ah[mi][3],
                        Ah + (uint32_t)r*128 + coff);
                if (NPROD == 2)
                    ldsm_x4(al[mi][0], al[mi][1], al[mi][2], al[mi][3],
                            Al + (uint32_t)r*128 + coff);
            }
            uint32_t b[4][4];
#pragma unroll
            for (int ni = 0; ni < 4; ni++) {
                const int r = wn*64 + ni*16 + lrow;
                ldsm_x4(b[ni][0], b[ni][1], b[ni][2], b[ni][3],
                        Bs + (uint32_t)r*128 + coff);
            }
#pragma unroll
            for (int mi = 0; mi < 2; mi++)
#pragma unroll
                for (int ni = 0; ni < 4; ni++) {
                    mma16816h(acc[mi][2*ni+0], ah[mi], b[ni][0], b[ni][2]);
                    mma16816h(acc[mi][2*ni+1], ah[mi], b[ni][1], b[ni][3]);
                    if (NPROD == 2) {
                        mma16816h(acc[mi][2*ni+0], al[mi], b[ni][0], b[ni][2]);
                        mma16816h(acc[mi][2*ni+1], al[mi], b[ni][1], b[ni][3]);
                    }
                }
        }
        MBARRIER_ARRIVE(EMPTY + 8*s);
        if (tid == 0 && c + NSTG < NCHUNK) {
            MBARRIER_WAIT_PARITY(EMPTY + 8*s, ph);
            MBARRIER_EXPECT_TX(FULL + 8*s, SBYTES);
            const int kx = (c + NSTG) * BK;
            if (NPROD == 1) {
                tma2d(Ah, tmA, kx, bm, FULL + 8*s);
                tma2d(Bs, tmB, kx, bn, FULL + 8*s);
            } else {
                tma2d(Ah, tmA, kx,          bm, FULL + 8*s);
                tma2d(Al, tmA, DMODEL + kx, bm, FULL + 8*s);
                tma2d(Bs, tmB, kx,          bn, FULL + 8*s);
            }
        }
    }

    const int grp = lane >> 2;
    const int qd  = lane & 3;
#pragma unroll
    for (int mi = 0; mi < 2; mi++) {
#pragma unroll
        for (int nj = 0; nj < 8; nj++) {
            const int col = bn + wn*64 + nj*8 + qd*2;
            const float b0 = __ldg(&bias[col]);
            const float b1 = __ldg(&bias[col + 1]);
#pragma unroll
            for (int half = 0; half < 2; half++) {
                const int m = bm + wm*32 + mi*16 + grp + half*8;
                const float v0 = acc[mi][nj][2*half+0] + b0;
                const float v1 = acc[mi][nj][2*half+1] + b1;
                if (MODE == 0) {
                    *(float2*)&C[(size_t)m * DMODEL + col] = make_float2(v0, v1);
                } else {
                    const int b = m >> 11, srow = m & 2047;
                    const int h = col >> 6, d = col & 63;
                    const size_t off = (((size_t)b * NHEAD + h) * SEQ + srow) * DHEAD + d;
                    *(uint32_t*)&Ohi[off] = pack2_f16(v0, v1);
                }
            }
        }
    }
}

// Fused QKV: grid.z selects tensor; 1-product (outputs are fp16-rounded anyway).
struct QkvMaps { CUtensorMap a[3]; CUtensorMap b[3]; };

__global__ void __launch_bounds__(256, 2)
gemm_qkv(const __grid_constant__ QkvMaps maps,
         const float* __restrict__ biasc, __half* __restrict__ qkvbase)
{
    const int i = blockIdx.z;
    gemm_core<1, 1>(&maps.a[i], &maps.b[i], biasc + i * DMODEL, nullptr,
                    qkvbase + (size_t)i * QKVPART,
                    blockIdx.y * 128, blockIdx.x * 128);
}

// Output projection: 2-product on split AO (fp32 output precision anchor).
__global__ void __launch_bounds__(256, 2)
gemm_out(const __grid_constant__ CUtensorMap tmA,
         const __grid_constant__ CUtensorMap tmB,
         const float* __restrict__ bias, float* __restrict__ C)
{
    gemm_core<0, 2>(&tmA, &tmB, bias, C, nullptr, blockIdx.y * 128, blockIdx.x * 128);
}

// ---------------------------------------------------------------------------
// Flash attention, pure fp16 HMMA, exp2 softmax, EMPTY-mbarrier KV pipeline.
// Output written as split fp16 AO for the Wo 2-product GEMM.
// ---------------------------------------------------------------------------
#define QT 128
#define KT 64
#define AT_TILEQ  16384
#define AT_TILEKV 8192
#define AT_STAGE  (2*AT_TILEKV)      // Kh, Vh
#define ASMEM (1024 + AT_TILEQ + 2*AT_STAGE)

__global__ void __launch_bounds__(256)
attn_mma(const __grid_constant__ CUtensorMap tmQ,
         const __grid_constant__ CUtensorMap tmK,
         const __grid_constant__ CUtensorMap tmV,
         __half* __restrict__ AO)
{
    extern __shared__ char smraw[];
    const uint32_t sb = smem_u32(smraw);
    const uint32_t tiles = (sb + 1024) & ~1023u;
    const uint32_t Qs = tiles;
    const uint32_t STG = tiles + AT_TILEQ;
    const int tid = threadIdx.x, lane = tid & 31, wid = tid >> 5;
    const int bh = blockIdx.y;
    const int q0 = blockIdx.x * QT;
    const int gy = bh * SEQ;

    const uint32_t BQ = sb, BF = sb + 8, BE = sb + 24;
    if (tid == 0) {
        MBARRIER_INIT(BQ, 1);
        MBARRIER_INIT(BF + 0, 1);
        MBARRIER_INIT(BF + 8, 1);
        MBARRIER_INIT(BE + 0, 256);
        MBARRIER_INIT(BE + 8, 256);
    }
    __syncthreads();
    if (tid == 0) {
        MBARRIER_EXPECT_TX(BQ, AT_TILEQ);
        tma2d(Qs, &tmQ, 0, gy + q0, BQ);
#pragma unroll
        for (int s = 0; s < 2; s++) {
            const uint32_t st = STG + s*AT_STAGE;
            MBARRIER_EXPECT_TX(BF + 8*s, AT_STAGE);
            tma2d(st,              &tmK, 0, gy + s*KT, BF + 8*s);
            tma2d(st + AT_TILEKV,  &tmV, 0, gy + s*KT, BF + 8*s);
        }
    }

    float m_run[2] = { -1e30f, -1e30f };
    float l_run[2] = { 0.f, 0.f };
    float o_acc[8][4];
#pragma unroll
    for (int i = 0; i < 8; i++)
#pragma unroll
        for (int j = 0; j < 4; j++) o_acc[i][j] = 0.f;

    MBARRIER_WAIT_PARITY(BQ, 0);

    const int r0q = wid * 16;
    const int la7 = lane & 7;
    const int g01 = (lane >> 3) & 1;
    const int g23 = lane >> 4;

    uint32_t qf[4][4];
#pragma unroll
    for (int j = 0; j < 4; j++) {
        const int rr = r0q + la7 + g01*8;
        const int uu = 2*j + g23;
        ldsm_x4(qf[j][0], qf[j][1], qf[j][2], qf[j][3], ldsm_addr(Qs, rr, uu));
    }

    for (int kt = 0; kt < SEQ / KT; kt++) {
        const int s = kt & 1, ph = (kt >> 1) & 1;
        MBARRIER_WAIT_PARITY(BF + 8*s, ph);
        const uint32_t Kh = STG + s*AT_STAGE;
        const uint32_t Vh = Kh + AT_TILEKV;

        float sf[8][4];
#pragma unroll
        for (int i = 0; i < 8; i++)
#pragma unroll
            for (int j = 0; j < 4; j++) sf[i][j] = 0.f;

#pragma unroll
        for (int j = 0; j < 4; j++) {
#pragma unroll
            for (int np = 0; np < 4; np++) {
                const int rr = np*16 + la7 + g23*8;
                const int uu = 2*j + g01;
                uint32_t k0,k1,k2,k3;
                ldsm_x4(k0,k1,k2,k3, ldsm_addr(Kh, rr, uu));
                mma16816h(sf[2*np+0], qf[j], k0, k1);
                mma16816h(sf[2*np+1], qf[j], k2, k3);
            }
        }

#pragma unroll
        for (int hf = 0; hf < 2; hf++) {
            float mx = -1e30f;
#pragma unroll
            for (int nt = 0; nt < 8; nt++)
                mx = fmaxf(mx, fmaxf(sf[nt][2*hf], sf[nt][2*hf+1]));
            mx = fmaxf(mx, __shfl_xor_sync(0xffffffffu, mx, 1));
            mx = fmaxf(mx, __shfl_xor_sync(0xffffffffu, mx, 2));
            const float mnew = fmaxf(m_run[hf], mx);
            const float corr = ex2(m_run[hf] - mnew);
            float sum = 0.f;
#pragma unroll
            for (int nt = 0; nt < 8; nt++) {
                const float p0 = ex2(sf[nt][2*hf]   - mnew);
                const float p1 = ex2(sf[nt][2*hf+1] - mnew);
                sf[nt][2*hf] = p0; sf[nt][2*hf+1] = p1;
                sum += p0 + p1;
            }
            sum += __shfl_xor_sync(0xffffffffu, sum, 1);
            sum += __shfl_xor_sync(0xffffffffu, sum, 2);
            l_run[hf] = l_run[hf] * corr + sum;
            m_run[hf] = mnew;
#pragma unroll
            for (int nt = 0; nt < 8; nt++) {
                o_acc[nt][2*hf]   *= corr;
                o_acc[nt][2*hf+1] *= corr;
            }
        }

#pragma unroll
        for (int j = 0; j < 4; j++) {
            uint32_t ph16[4];
#pragma unroll
            for (int t = 0; t < 4; t++) {
                const int nt = 2*j + (t >> 1);
                const int vv = (t & 1) * 2;
                ph16[t] = pack2_f16(sf[nt][vv+0], sf[nt][vv+1]);
            }
#pragma unroll
            for (int np = 0; np < 4; np++) {
                const int rr = 16*j + la7 + g01*8;
                const int uu = 2*np + g23;
                uint32_t v0,v1,v2,v3;
                ldsm_x4_t(v0,v1,v2,v3, ldsm_addr(Vh, rr, uu));
                mma16816h(o_acc[2*np+0], ph16, v0, v1);
                mma16816h(o_acc[2*np+1], ph16, v2, v3);
            }
        }

        MBARRIER_ARRIVE(BE + 8*s);
        if (tid == 0 && kt + 2 < SEQ / KT) {
            MBARRIER_WAIT_PARITY(BE + 8*s, ph);
            const uint32_t st = STG + s*AT_STAGE;
            MBARRIER_EXPECT_TX(BF + 8*s, AT_STAGE);
            tma2d(st,             &tmK, 0, gy + (kt+2)*KT, BF + 8*s);
            tma2d(st + AT_TILEKV, &tmV, 0, gy + (kt+2)*KT, BF + 8*s);
        }
    }

    const int b = bh >> 4, h = bh & 15;
#pragma unroll
    for (int hf = 0; hf < 2; hf++) {
        const float inv = 1.f / l_run[hf];
        const int srow = q0 + r0q + (lane >> 2) + hf*8;
#pragma unroll
        for (int nt = 0; nt < 8; nt++) {
            const int d = nt*8 + (lane & 3)*2;
            const float f0 = o_acc[nt][2*hf]   * inv;
            const float f1 = o_acc[nt][2*hf+1] * inv;
            uint32_t hp, lp;
            split_pack2_f16(f0, f1, hp, lp);
            const size_t base = ((size_t)b * SEQ + srow) * 2 * DMODEL + h * DHEAD + d;
            *(uint32_t*)&AO[base]          = hp;
            *(uint32_t*)&AO[base + DMODEL] = lp;
        }
    }
}

// ---------------------------------------------------------------------------
// Host
// ---------------------------------------------------------------------------
typedef CUresult (*PFN_tmEncode)(CUtensorMap*, CUtensorMapDataType, cuuint32_t, void*,
                                 const cuuint64_t*, const cuuint64_t*, const cuuint32_t*,
                                 const cuuint32_t*, CUtensorMapInterleave, CUtensorMapSwizzle,
                                 CUtensorMapL2promotion, CUtensorMapFloatOOBfill);

static void make_map(PFN_tmEncode enc, CUtensorMap* m, void* p, uint64_t rows,
                     uint64_t width, uint32_t b0, uint32_t b1)
{
    cuuint64_t dims[2]    = { width, rows };
    cuuint64_t strides[1] = { width * 2 };
    cuuint32_t box[2]     = { b0, b1 };
    cuuint32_t es[2]      = { 1, 1 };
    enc(m, CU_TENSOR_MAP_DATA_TYPE_FLOAT16, 2, p, dims, strides, box, es,
        CU_TENSOR_MAP_INTERLEAVE_NONE, CU_TENSOR_MAP_SWIZZLE_128B,
        CU_TENSOR_MAP_L2_PROMOTION_L2_128B, CU_TENSOR_MAP_FLOAT_OOB_FILL_NONE);
}

extern "C" void kernel_launch(void* const* d_in, const int* in_sizes, int n_in,
                              void* d_out, int out_size)
{
    const float* act[3] = { (const float*)d_in[0], (const float*)d_in[1], (const float*)d_in[2] };
    const float* W[4]   = { (const float*)d_in[3], (const float*)d_in[5], (const float*)d_in[7], (const float*)d_in[9] };
    const float* bia[4] = { (const float*)d_in[4], (const float*)d_in[6], (const float*)d_in[8], (const float*)d_in[10] };
    float* out = (float*)d_out;

    __half *pact, *pwt, *pao, *pqkv;
    float* pbc;
    cudaGetSymbolAddress((void**)&pact, g_act);
    cudaGetSymbolAddress((void**)&pwt,  g_wt);
    cudaGetSymbolAddress((void**)&pao,  g_ao);
    cudaGetSymbolAddress((void**)&pqkv, g_qkvs);
    cudaGetSymbolAddress((void**)&pbc,  g_biasc);

    PFN_tmEncode enc = nullptr;
    cudaDriverEntryPointQueryResult qr;
    cudaGetDriverEntryPointByVersion("cuTensorMapEncodeTiled", (void**)&enc, 12000,
                                     cudaEnableDefault, &qr);

    const size_t WM = (size_t)DMODEL * DMODEL;

    static QkvMaps qkvmaps;
    static CUtensorMap mAao, mBo, mQKV[3];
    for (int i = 0; i < 3; i++) {
        make_map(enc, &qkvmaps.a[i], pact + (size_t)i * MTOT * DMODEL, MTOT, DMODEL, BK, 128);
        make_map(enc, &qkvmaps.b[i], pwt + (size_t)i * WM, DMODEL, DMODEL, BK, 128);
    }
    make_map(enc, &mAao, pao, MTOT, 2*DMODEL, BK, 128);
    make_map(enc, &mBo, pwt + 3*WM, DMODEL, DMODEL, BK, 128);
    for (int i = 0; i < 3; i++)
        make_map(enc, &mQKV[i], pqkv + i * QKVPART, (uint64_t)BHTOT * SEQ, DHEAD,
                 DHEAD, (i == 0) ? QT : KT);

    cudaFuncSetAttribute(gemm_qkv, cudaFuncAttributeMaxDynamicSharedMemorySize, GSMEM);
    cudaFuncSetAttribute(gemm_out, cudaFuncAttributeMaxDynamicSharedMemorySize, GSMEM);
    cudaFuncSetAttribute(attn_mma, cudaFuncAttributeMaxDynamicSharedMemorySize, ASMEM);

    // 1. fused preprocessing
    split_rows_kernel<<<dim3(MTOT, 3), 256>>>(act[0], act[1], act[2], pact);
    wt_split_kernel<<<dim3(32, 32, 4), dim3(32, 8)>>>(W[0], W[1], W[2], W[3], pwt);
    bias_concat_kernel<<<12, 256>>>(bia[0], bia[1], bia[2], pbc);

    // 2. fused QKV projections (1-product, one launch) -> fp16 Q,K,V
    gemm_qkv<<<dim3(DMODEL/128, MTOT/128, 3), 256, GSMEM>>>(qkvmaps, pbc, pqkv);

    // 3. attention (pure fp16 HMMA), writes split AO
    attn_mma<<<dim3(SEQ / QT, BHTOT), 256, ASMEM>>>(mQKV[0], mQKV[1], mQKV[2], pao);

    // 4. output projection (2-product on split AO)
    gemm_out<<<dim3(DMODEL/128, MTOT/128), 256, GSMEM>>>(mAao, mBo, bia[3], out);
}